// round 1
// baseline (speedup 1.0000x reference)
#include <cuda_runtime.h>
#include <cuda_bf16.h>
#include <math.h>

// ---------------- problem constants ----------------
#define NN   8192
#define EE   65536
#define GG   64
#define DNODE 64
#define DEDGE 32
#define CC   256
#define H1C  8
#define H2C  4
#define ET   (EE + NN)          // 73728 edges incl. self loops
#define HC1  (H1C * CC)         // 2048
#define HC2  (H2C * CC)         // 1024
#define NEG_SLOPE 0.2f

// ---------------- device scratch (static allocation, allowed) ----------------
__device__ int   g_is64;
__device__ int   g_src[EE];
__device__ int   g_dst[EE];
__device__ int   g_batch[NN];
__device__ int   g_deg[NN];
__device__ int   g_cur[NN];
__device__ int   g_off[NN + 1];
__device__ int   g_csr[ET];
__device__ float g_easum[NN * DEDGE];
__device__ float g_ea2[ET * DEDGE];
__device__ float g_xl[NN * HC1];
__device__ float g_xr[NN * HC1];
__device__ float g_ee[(size_t)ET * HC1];     // 603 MB scratch, reused by layer 2
__device__ float g_logits[ET * H1C];
__device__ float g_h1[NN * HC1];
__device__ float g_h2[NN * HC2];
__device__ float g_pool[GG * HC2];
__device__ float g_cnt[GG];
__device__ float g_m1[GG * 512];
__device__ float g_m2[GG * 256];

// ---------------- helpers ----------------
__device__ __forceinline__ float warp_sum(float v) {
    #pragma unroll
    for (int o = 16; o; o >>= 1) v += __shfl_xor_sync(0xffffffffu, v, o);
    return v;
}
__device__ __forceinline__ float warp_max(float v) {
    #pragma unroll
    for (int o = 16; o; o >>= 1) v = fmaxf(v, __shfl_xor_sync(0xffffffffu, v, o));
    return v;
}

// ---------------- index dtype detection + normalization ----------------
// JAX may hand us int32 (x64 disabled) or int64 (x64 enabled). src values are
// random in [0, 8192): if int64, words 2i+1 (high words) are all zero; if
// int32, the probability that 16 consecutive src values are zero is ~0.
__global__ void k_detect(const int* __restrict__ ei) {
    int is64 = 1;
    for (int i = 0; i < 16; i++)
        if (ei[2 * i + 1] != 0) is64 = 0;
    g_is64 = is64;
}

__global__ void k_norm_idx(const int* __restrict__ ei, const int* __restrict__ batch) {
    int t = blockIdx.x * blockDim.x + threadIdx.x;
    int is64 = g_is64;
    if (t < EE) {
        g_src[t] = is64 ? ei[2 * t]        : ei[t];
        g_dst[t] = is64 ? ei[2 * (EE + t)] : ei[EE + t];
    }
    if (t < NN) g_batch[t] = is64 ? batch[2 * t] : batch[t];
}

// ---------------- zero accumulators (must run every call; graph replays) ----
__global__ void k_zero() {
    int t = blockIdx.x * blockDim.x + threadIdx.x;
    if (t < NN) { g_deg[t] = 0; g_cur[t] = 0; }
    if (t < NN * DEDGE) g_easum[t] = 0.f;
    if (t < GG * HC2) g_pool[t] = 0.f;
    if (t < GG) g_cnt[t] = 0.f;
}

// ---------------- degree + edge-attr sums per destination -------------------
__global__ void k_deg_easum(const float* __restrict__ ea) {
    int t = blockIdx.x * blockDim.x + threadIdx.x;
    if (t >= EE * DEDGE) return;
    int e = t >> 5, d = t & 31;
    int dst = g_dst[e];
    atomicAdd(&g_easum[dst * DEDGE + d], ea[t]);
    if (d == 0) atomicAdd(&g_deg[dst], 1);
}

// ---------------- build ea2 = concat(edge_attr, loop_ea) --------------------
__global__ void k_ea2(const float* __restrict__ ea) {
    int t = blockIdx.x * blockDim.x + threadIdx.x;
    if (t >= ET * DEDGE) return;
    if (t < EE * DEDGE) {
        g_ea2[t] = ea[t];
    } else {
        int u = t - EE * DEDGE;
        int n = u >> 5;
        g_ea2[t] = g_easum[u] / fmaxf((float)g_deg[n], 1.f);
    }
}

// ---------------- exclusive scan of (deg+1) -> CSR offsets -------------------
__global__ void k_scan() {
    __shared__ int part[256];
    int t = threadIdx.x;
    int base = t * 32;
    int loc[32];
    int s = 0;
    #pragma unroll
    for (int i = 0; i < 32; i++) { loc[i] = s; s += g_deg[base + i] + 1; }
    part[t] = s;
    __syncthreads();
    if (t == 0) {
        int acc = 0;
        for (int i = 0; i < 256; i++) { int v = part[i]; part[i] = acc; acc += v; }
        g_off[NN] = acc;  // == ET
    }
    __syncthreads();
    int p = part[t];
    #pragma unroll
    for (int i = 0; i < 32; i++) g_off[base + i] = p + loc[i];
}

// ---------------- CSR fill (counting sort by dst) ----------------------------
__global__ void k_csr() {
    int e = blockIdx.x * blockDim.x + threadIdx.x;
    if (e >= ET) return;
    int node = (e < EE) ? g_dst[e] : (e - EE);
    int pos = g_off[node] + atomicAdd(&g_cur[node], 1);
    g_csr[pos] = e;
}

// ---------------- generic SGEMM: C[M,Nc] = A[M,K] @ B[Nc,K]^T (+bias)(+relu) -
__global__ __launch_bounds__(256) void k_sgemm(
    const float* __restrict__ A, const float* __restrict__ Bm,
    const float* __restrict__ bias, float* __restrict__ Cm,
    int M, int Nc, int K, int act)
{
    constexpr int BM = 128, BN = 128, BK = 16, TM = 8, TN = 8;
    __shared__ float As[BK][BM];
    __shared__ float Bs[BK][BN];
    int tid = threadIdx.x;
    int tx = tid % 16, ty = tid / 16;
    int rowBase = blockIdx.y * BM;
    int colBase = blockIdx.x * BN;
    float acc[TM][TN];
    #pragma unroll
    for (int i = 0; i < TM; i++)
        #pragma unroll
        for (int j = 0; j < TN; j++) acc[i][j] = 0.f;

    for (int k0 = 0; k0 < K; k0 += BK) {
        #pragma unroll
        for (int i = 0; i < 2; i++) {
            int f4 = tid + i * 256;         // 0..511
            int r  = f4 >> 2;               // 0..127
            int kk = (f4 & 3) * 4;          // 0,4,8,12
            int gr = rowBase + r;
            float4 v = make_float4(0.f, 0.f, 0.f, 0.f);
            if (gr < M) v = *reinterpret_cast<const float4*>(A + (size_t)gr * K + k0 + kk);
            As[kk + 0][r] = v.x; As[kk + 1][r] = v.y; As[kk + 2][r] = v.z; As[kk + 3][r] = v.w;
            int gc = colBase + r;
            float4 w = make_float4(0.f, 0.f, 0.f, 0.f);
            if (gc < Nc) w = *reinterpret_cast<const float4*>(Bm + (size_t)gc * K + k0 + kk);
            Bs[kk + 0][r] = w.x; Bs[kk + 1][r] = w.y; Bs[kk + 2][r] = w.z; Bs[kk + 3][r] = w.w;
        }
        __syncthreads();
        #pragma unroll
        for (int k = 0; k < BK; k++) {
            float a[TM], b[TN];
            #pragma unroll
            for (int i = 0; i < TM; i++) a[i] = As[k][ty * TM + i];
            #pragma unroll
            for (int j = 0; j < TN; j++) b[j] = Bs[k][tx * TN + j];
            #pragma unroll
            for (int i = 0; i < TM; i++)
                #pragma unroll
                for (int j = 0; j < TN; j++) acc[i][j] = fmaf(a[i], b[j], acc[i][j]);
        }
        __syncthreads();
    }
    #pragma unroll
    for (int i = 0; i < TM; i++) {
        int gr = rowBase + ty * TM + i;
        if (gr >= M) continue;
        #pragma unroll
        for (int j = 0; j < TN; j++) {
            int gc = colBase + tx * TN + j;
            if (gc >= Nc) continue;
            float v = acc[i][j];
            if (bias) v += bias[gc];
            if (act) v = fmaxf(v, 0.f);
            Cm[(size_t)gr * Nc + gc] = v;
        }
    }
}

// ---------------- per-edge attention logits ---------------------------------
// logit[e,h] = sum_c lrelu(xl[src,h,c] + xr[dst,h,c] + ee[e,h,c]) * att[h,c]
template <int H>
__global__ void k_logits(const float* __restrict__ att) {
    int e = blockIdx.x;
    int h = threadIdx.x >> 5, lane = threadIdx.x & 31;
    int s, d;
    if (e < EE) { s = g_src[e]; d = g_dst[e]; } else { s = d = e - EE; }
    const int HC = H * CC;
    size_t eb = (size_t)e * HC + h * CC + lane;
    size_t sb = (size_t)s * HC + h * CC + lane;
    size_t db = (size_t)d * HC + h * CC + lane;
    float acc = 0.f;
    #pragma unroll
    for (int j = 0; j < 8; j++) {
        float v = g_xl[sb + 32 * j] + g_xr[db + 32 * j] + g_ee[eb + 32 * j];
        v = (v > 0.f) ? v : NEG_SLOPE * v;
        acc += v * att[h * CC + lane + 32 * j];
    }
    acc = warp_sum(acc);
    if (lane == 0) g_logits[e * H + h] = acc;
}

// ---------------- segment softmax + weighted gather (CSR, no atomics) -------
template <int H, int RELU>
__global__ void k_aggregate(const float* __restrict__ bias, float* __restrict__ out) {
    int n = blockIdx.x;
    int h = threadIdx.x >> 5, lane = threadIdx.x & 31;
    int s0 = g_off[n], s1 = g_off[n + 1];
    float mx = -1e30f;
    for (int i = s0 + lane; i < s1; i += 32) mx = fmaxf(mx, g_logits[g_csr[i] * H + h]);
    mx = warp_max(mx);
    float den = 0.f;
    for (int i = s0 + lane; i < s1; i += 32) den += __expf(g_logits[g_csr[i] * H + h] - mx);
    den = warp_sum(den);
    float inv = 1.f / den;
    const int HC = H * CC;
    float acc[8];
    #pragma unroll
    for (int j = 0; j < 8; j++) acc[j] = 0.f;
    for (int i = s0; i < s1; i++) {
        int e = g_csr[i];
        float w = __expf(g_logits[e * H + h] - mx) * inv;
        int s = (e < EE) ? g_src[e] : (e - EE);
        const float* row = g_xl + (size_t)s * HC + h * CC + lane;
        #pragma unroll
        for (int j = 0; j < 8; j++) acc[j] = fmaf(w, row[32 * j], acc[j]);
    }
    size_t ob = (size_t)n * HC + h * CC + lane;
    #pragma unroll
    for (int j = 0; j < 8; j++) {
        float v = acc[j] + bias[h * CC + lane + 32 * j];
        if (RELU) v = fmaxf(v, 0.f);
        out[ob + 32 * j] = v;
    }
}

// ---------------- global mean pool -------------------------------------------
__global__ void k_pool() {
    int t = blockIdx.x * blockDim.x + threadIdx.x;
    if (t >= NN * HC2) return;
    int n = t >> 10, c = t & 1023;
    int b = g_batch[n];
    atomicAdd(&g_pool[b * HC2 + c], g_h2[t]);
    if (c == 0) atomicAdd(&g_cnt[b], 1.f);
}
__global__ void k_pool_div() {
    int t = blockIdx.x * blockDim.x + threadIdx.x;
    if (t >= GG * HC2) return;
    g_pool[t] /= fmaxf(g_cnt[t >> 10], 1.f);
}

// ---------------- final 256 -> 1 + sigmoid -----------------------------------
__global__ void k_final(const float* __restrict__ W3, const float* __restrict__ b3,
                        float* __restrict__ out) {
    int g = blockIdx.x, lane = threadIdx.x;
    float acc = 0.f;
    #pragma unroll
    for (int j = 0; j < 8; j++) acc += g_m2[g * 256 + lane + 32 * j] * W3[lane + 32 * j];
    acc = warp_sum(acc);
    if (lane == 0) out[g] = 1.f / (1.f + expf(-(acc + b3[0])));
}

// ---------------- host launch --------------------------------------------------
static inline void launch_sgemm(const float* A, const float* B, const float* bias,
                                float* C, int M, int Nc, int K, int act) {
    dim3 grid((Nc + 127) / 128, (M + 127) / 128);
    k_sgemm<<<grid, 256>>>(A, B, bias, C, M, Nc, K, act);
}

extern "C" void kernel_launch(void* const* d_in, const int* in_sizes, int n_in,
                              void* d_out, int out_size) {
    const float* x     = (const float*)d_in[0];
    const int*   ei    = (const int*)  d_in[1];
    const float* ea    = (const float*)d_in[2];
    const int*   batch = (const int*)  d_in[3];
    const float* Wl1 = (const float*)d_in[4],  *bl1 = (const float*)d_in[5];
    const float* Wr1 = (const float*)d_in[6],  *br1 = (const float*)d_in[7];
    const float* We1 = (const float*)d_in[8],  *att1 = (const float*)d_in[9];
    const float* bias1 = (const float*)d_in[10];
    const float* Wl2 = (const float*)d_in[11], *bl2 = (const float*)d_in[12];
    const float* Wr2 = (const float*)d_in[13], *br2 = (const float*)d_in[14];
    const float* We2 = (const float*)d_in[15], *att2 = (const float*)d_in[16];
    const float* bias2 = (const float*)d_in[17];
    const float* W1 = (const float*)d_in[18], *b1 = (const float*)d_in[19];
    const float* W2 = (const float*)d_in[20], *b2 = (const float*)d_in[21];
    const float* W3 = (const float*)d_in[22], *b3 = (const float*)d_in[23];
    float* out = (float*)d_out;

    // scratch pointers for SGEMM args
    float *p_xl, *p_xr, *p_ee, *p_ea2, *p_h1, *p_h2, *p_pool, *p_m1, *p_m2;
    cudaGetSymbolAddress((void**)&p_xl,   g_xl);
    cudaGetSymbolAddress((void**)&p_xr,   g_xr);
    cudaGetSymbolAddress((void**)&p_ee,   g_ee);
    cudaGetSymbolAddress((void**)&p_ea2,  g_ea2);
    cudaGetSymbolAddress((void**)&p_h1,   g_h1);
    cudaGetSymbolAddress((void**)&p_h2,   g_h2);
    cudaGetSymbolAddress((void**)&p_pool, g_pool);
    cudaGetSymbolAddress((void**)&p_m1,   g_m1);
    cudaGetSymbolAddress((void**)&p_m2,   g_m2);

    // --- graph preprocessing ---
    k_detect<<<1, 1>>>(ei);
    k_norm_idx<<<(EE + 255) / 256, 256>>>(ei, batch);
    k_zero<<<(NN * DEDGE + 255) / 256, 256>>>();
    k_deg_easum<<<(EE * DEDGE + 255) / 256, 256>>>(ea);
    k_ea2<<<(ET * DEDGE + 255) / 256, 256>>>(ea);
    k_scan<<<1, 256>>>();
    k_csr<<<(ET + 255) / 256, 256>>>();

    // --- GATv2 layer 1 ---
    launch_sgemm(x, Wl1, bl1, p_xl, NN, HC1, DNODE, 0);
    launch_sgemm(x, Wr1, br1, p_xr, NN, HC1, DNODE, 0);
    launch_sgemm(p_ea2, We1, nullptr, p_ee, ET, HC1, DEDGE, 0);
    k_logits<H1C><<<ET, H1C * 32>>>(att1);
    k_aggregate<H1C, 1><<<NN, H1C * 32>>>(bias1, p_h1);

    // --- GATv2 layer 2 ---
    launch_sgemm(p_h1, Wl2, bl2, p_xl, NN, HC2, HC1, 0);
    launch_sgemm(p_h1, Wr2, br2, p_xr, NN, HC2, HC1, 0);
    launch_sgemm(p_ea2, We2, nullptr, p_ee, ET, HC2, DEDGE, 0);
    k_logits<H2C><<<ET, H2C * 32>>>(att2);
    k_aggregate<H2C, 0><<<NN, H2C * 32>>>(bias2, p_h2);

    // --- pool + MLP ---
    k_pool<<<(NN * HC2 + 255) / 256, 256>>>();
    k_pool_div<<<(GG * HC2 + 255) / 256, 256>>>();
    launch_sgemm(p_pool, W1, b1, p_m1, GG, 512, HC2, 1);
    launch_sgemm(p_m1,  W2, b2, p_m2, GG, 256, 512, 1);
    k_final<<<GG, 32>>>(W3, b3, out);
}

// round 3
// speedup vs baseline: 1.8665x; 1.8665x over previous
#include <cuda_runtime.h>
#include <cuda_bf16.h>
#include <math.h>
#include <stdint.h>

// ---------------- problem constants ----------------
#define NN   8192
#define EE   65536
#define GG   64
#define DNODE 64
#define DEDGE 32
#define CC   256
#define H1C  8
#define H2C  4
#define ET   (EE + NN)          // 73728 edges incl. self loops (576 * 128)
#define HC1  (H1C * CC)         // 2048
#define HC2  (H2C * CC)         // 1024
#define NEG_SLOPE 0.2f

// ---------------- device scratch ----------------
__device__ int   g_is64;
__device__ int   g_src[EE];
__device__ int   g_dst[EE];
__device__ int   g_batch[NN];
__device__ int   g_deg[NN];
__device__ int   g_cur[NN];
__device__ int   g_off[NN + 1];
__device__ int   g_csr[ET];
__device__ float g_easum[NN * DEDGE];
__device__ float g_ea2[ET * DEDGE];
__device__ float g_xl[NN * HC1];
__device__ float g_xr[NN * HC1];
__device__ __nv_bfloat16 g_eeb[(size_t)ET * HC1];   // bf16 edge-feature GEMM output
__device__ float g_logits[ET * H1C];
__device__ float g_h1[NN * HC1];
__device__ float g_h2[NN * HC2];
__device__ float g_pool[GG * HC2];
__device__ float g_cnt[GG];
__device__ float g_m1[GG * 512];
__device__ float g_m2[GG * 256];

// ---------------- warp helpers ----------------
__device__ __forceinline__ float warp_sum(float v) {
    #pragma unroll
    for (int o = 16; o; o >>= 1) v += __shfl_xor_sync(0xffffffffu, v, o);
    return v;
}
__device__ __forceinline__ float warp_max(float v) {
    #pragma unroll
    for (int o = 16; o; o >>= 1) v = fmaxf(v, __shfl_xor_sync(0xffffffffu, v, o));
    return v;
}
__device__ __forceinline__ uint32_t f2tf(float f) {
    uint32_t r;
    asm("cvt.rna.tf32.f32 %0, %1;" : "=r"(r) : "f"(f));
    return r;
}
__device__ __forceinline__ void mma_tf32(float* c, uint4 a, uint2 b) {
    asm volatile(
        "mma.sync.aligned.m16n8k8.row.col.f32.tf32.tf32.f32 "
        "{%0,%1,%2,%3},{%4,%5,%6,%7},{%8,%9},{%0,%1,%2,%3};"
        : "+f"(c[0]), "+f"(c[1]), "+f"(c[2]), "+f"(c[3])
        : "r"(a.x), "r"(a.y), "r"(a.z), "r"(a.w), "r"(b.x), "r"(b.y));
}

// =================================================================
// tf32 mma.sync GEMM: C[M,N] = A[M,K] @ B[N,K]^T (+bias)(+relu)
// Requires: M % 128 == 0, N % 128 == 0, K % 32 == 0.
// CTA tile 128x128x32, 8 warps (4 in M x 2 in N), warp tile 32x64.
// Smem holds tiles in mma-fragment-native order:
//   A subtile (kstep, mtile): 128 u32, laid out lane*4 + reg  (LDS.128/lane)
//   B subtile (kstep, ntile): 64 u32,  laid out lane*2 + reg  (LDS.64/lane)
// Double buffered: stage stride 8192 u32 (32 KB), total 64 KB dynamic.
// =================================================================
#define MMA_SMEM_BYTES 65536

__device__ __forceinline__ void ldg_tile(
    const float* __restrict__ A, const float* __restrict__ B, int K,
    int rowBase, int colBase, int kc, int tid, float4* va, float4* vb)
{
    #pragma unroll
    for (int i = 0; i < 4; i++) {
        int id = i * 256 + tid;
        int r = id >> 3, c4 = id & 7;
        va[i] = *reinterpret_cast<const float4*>(A + (size_t)(rowBase + r) * K + kc + c4 * 4);
        vb[i] = *reinterpret_cast<const float4*>(B + (size_t)(colBase + r) * K + kc + c4 * 4);
    }
}

__device__ __forceinline__ void sts_tile(
    uint32_t* __restrict__ sA, uint32_t* __restrict__ sB,
    int tid, const float4* va, const float4* vb)
{
    #pragma unroll
    for (int i = 0; i < 4; i++) {
        int id = i * 256 + tid;
        int r = id >> 3, c4 = id & 7;
        int kstep = c4 >> 1, half = c4 & 1;
        // ---- A: element (r, k= c4*4+j) -> subtile (kstep, r/16),
        //      lane = (r%8)*4 + j, reg = half*2 + ((r%16)/8)
        int mtile = r >> 4, ri = r & 15;
        int regA = half * 2 + (ri >> 3);
        int baseA = (kstep * 8 + mtile) * 128 + (ri & 7) * 16 + regA;
        sA[baseA +  0] = f2tf(va[i].x);
        sA[baseA +  4] = f2tf(va[i].y);
        sA[baseA +  8] = f2tf(va[i].z);
        sA[baseA + 12] = f2tf(va[i].w);
        // ---- B: element (n=r, k) -> subtile (kstep, r/8),
        //      lane = (r%8)*4 + j, reg = half
        int ntile = r >> 3, ni = r & 7;
        int baseB = (kstep * 16 + ntile) * 64 + ni * 8 + half;
        sB[baseB + 0] = f2tf(vb[i].x);
        sB[baseB + 2] = f2tf(vb[i].y);
        sB[baseB + 4] = f2tf(vb[i].z);
        sB[baseB + 6] = f2tf(vb[i].w);
    }
}

template <int OUTBF16>
__global__ __launch_bounds__(256) void k_mma_gemm(
    const float* __restrict__ A, const float* __restrict__ B,
    const float* __restrict__ bias, void* __restrict__ Cout,
    int M, int N, int K, int act)
{
    extern __shared__ uint32_t sm[];
    int tid = threadIdx.x;
    int wid = tid >> 5, lane = tid & 31;
    int mw = wid & 3, nw = wid >> 2;          // warp grid 4 (M) x 2 (N)
    int gid = lane >> 2, tig = lane & 3;
    int rowBase = blockIdx.y * 128, colBase = blockIdx.x * 128;

    float acc[2][8][4];
    #pragma unroll
    for (int mt = 0; mt < 2; mt++)
        #pragma unroll
        for (int nt = 0; nt < 8; nt++)
            #pragma unroll
            for (int q = 0; q < 4; q++) acc[mt][nt][q] = 0.f;

    const int NCH = K >> 5;
    float4 va[4], vb[4];

    ldg_tile(A, B, K, rowBase, colBase, 0, tid, va, vb);
    sts_tile(sm, sm + 4096, tid, va, vb);
    __syncthreads();

    for (int c = 0; c < NCH; c++) {
        if (c + 1 < NCH)
            ldg_tile(A, B, K, rowBase, colBase, (c + 1) << 5, tid, va, vb);

        const uint32_t* As = sm + (c & 1) * 8192;
        const uint32_t* Bs = As + 4096;
        #pragma unroll
        for (int kstep = 0; kstep < 4; kstep++) {
            uint4 afr[2];
            #pragma unroll
            for (int mt = 0; mt < 2; mt++)
                afr[mt] = *reinterpret_cast<const uint4*>(
                    As + (kstep * 8 + mw * 2 + mt) * 128 + lane * 4);
            uint2 bfr[8];
            #pragma unroll
            for (int nt = 0; nt < 8; nt++)
                bfr[nt] = *reinterpret_cast<const uint2*>(
                    Bs + (kstep * 16 + nw * 8 + nt) * 64 + lane * 2);
            #pragma unroll
            for (int mt = 0; mt < 2; mt++)
                #pragma unroll
                for (int nt = 0; nt < 8; nt++)
                    mma_tf32(acc[mt][nt], afr[mt], bfr[nt]);
        }

        if (c + 1 < NCH) {
            uint32_t* sA = sm + ((c + 1) & 1) * 8192;
            sts_tile(sA, sA + 4096, tid, va, vb);
        }
        __syncthreads();
    }

    // ---- epilogue ----
    #pragma unroll
    for (int mt = 0; mt < 2; mt++) {
        int row0 = rowBase + mw * 32 + mt * 16 + gid;
        #pragma unroll
        for (int nt = 0; nt < 8; nt++) {
            int col = colBase + nw * 64 + nt * 8 + tig * 2;
            float c0 = acc[mt][nt][0], c1 = acc[mt][nt][1];
            float c2 = acc[mt][nt][2], c3 = acc[mt][nt][3];
            if (!OUTBF16) {
                if (bias) {
                    float b0 = bias[col], b1 = bias[col + 1];
                    c0 += b0; c1 += b1; c2 += b0; c3 += b1;
                }
                if (act) {
                    c0 = fmaxf(c0, 0.f); c1 = fmaxf(c1, 0.f);
                    c2 = fmaxf(c2, 0.f); c3 = fmaxf(c3, 0.f);
                }
                float* Cf = (float*)Cout;
                *reinterpret_cast<float2*>(Cf + (size_t)row0 * N + col)       = make_float2(c0, c1);
                *reinterpret_cast<float2*>(Cf + (size_t)(row0 + 8) * N + col) = make_float2(c2, c3);
            } else {
                __nv_bfloat16* Cb = (__nv_bfloat16*)Cout;
                __nv_bfloat162 p0 = __floats2bfloat162_rn(c0, c1);
                __nv_bfloat162 p1 = __floats2bfloat162_rn(c2, c3);
                *reinterpret_cast<__nv_bfloat162*>(Cb + (size_t)row0 * N + col)       = p0;
                *reinterpret_cast<__nv_bfloat162*>(Cb + (size_t)(row0 + 8) * N + col) = p1;
            }
        }
    }
}

// ---------------- index detection / normalization ----------------
__global__ void k_detect(const int* __restrict__ ei) {
    int is64 = 1;
    for (int i = 0; i < 16; i++)
        if (ei[2 * i + 1] != 0) is64 = 0;
    g_is64 = is64;
}
__global__ void k_norm_idx(const int* __restrict__ ei, const int* __restrict__ batch) {
    int t = blockIdx.x * blockDim.x + threadIdx.x;
    int is64 = g_is64;
    if (t < EE) {
        g_src[t] = is64 ? ei[2 * t]        : ei[t];
        g_dst[t] = is64 ? ei[2 * (EE + t)] : ei[EE + t];
    }
    if (t < NN) g_batch[t] = is64 ? batch[2 * t] : batch[t];
}
__global__ void k_zero() {
    int t = blockIdx.x * blockDim.x + threadIdx.x;
    if (t < NN) { g_deg[t] = 0; g_cur[t] = 0; }
    if (t < NN * DEDGE) g_easum[t] = 0.f;
    if (t < GG * HC2) g_pool[t] = 0.f;
    if (t < GG) g_cnt[t] = 0.f;
}
__global__ void k_deg_easum(const float* __restrict__ ea) {
    int t = blockIdx.x * blockDim.x + threadIdx.x;
    if (t >= EE * DEDGE) return;
    int e = t >> 5, d = t & 31;
    int dst = g_dst[e];
    atomicAdd(&g_easum[dst * DEDGE + d], ea[t]);
    if (d == 0) atomicAdd(&g_deg[dst], 1);
}
__global__ void k_ea2(const float* __restrict__ ea) {
    int t = blockIdx.x * blockDim.x + threadIdx.x;
    if (t >= ET * DEDGE) return;
    if (t < EE * DEDGE) {
        g_ea2[t] = ea[t];
    } else {
        int u = t - EE * DEDGE;
        int n = u >> 5;
        g_ea2[t] = g_easum[u] / fmaxf((float)g_deg[n], 1.f);
    }
}
__global__ void k_scan() {
    __shared__ int part[256];
    int t = threadIdx.x;
    int base = t * 32;
    int loc[32];
    int s = 0;
    #pragma unroll
    for (int i = 0; i < 32; i++) { loc[i] = s; s += g_deg[base + i] + 1; }
    part[t] = s;
    __syncthreads();
    if (t == 0) {
        int acc = 0;
        for (int i = 0; i < 256; i++) { int v = part[i]; part[i] = acc; acc += v; }
        g_off[NN] = acc;
    }
    __syncthreads();
    int p = part[t];
    #pragma unroll
    for (int i = 0; i < 32; i++) g_off[base + i] = p + loc[i];
}
__global__ void k_csr() {
    int e = blockIdx.x * blockDim.x + threadIdx.x;
    if (e >= ET) return;
    int node = (e < EE) ? g_dst[e] : (e - EE);
    int pos = g_off[node] + atomicAdd(&g_cur[node], 1);
    g_csr[pos] = e;
}

// ---------------- fp32 SGEMM kept for the tiny MLP ----------------
__global__ __launch_bounds__(256) void k_sgemm(
    const float* __restrict__ A, const float* __restrict__ Bm,
    const float* __restrict__ bias, float* __restrict__ Cm,
    int M, int Nc, int K, int act)
{
    constexpr int BM = 128, BN = 128, BK = 16, TM = 8, TN = 8;
    __shared__ float As[BK][BM];
    __shared__ float Bs[BK][BN];
    int tid = threadIdx.x;
    int tx = tid % 16, ty = tid / 16;
    int rowBase = blockIdx.y * BM;
    int colBase = blockIdx.x * BN;
    float acc[TM][TN];
    #pragma unroll
    for (int i = 0; i < TM; i++)
        #pragma unroll
        for (int j = 0; j < TN; j++) acc[i][j] = 0.f;
    for (int k0 = 0; k0 < K; k0 += BK) {
        #pragma unroll
        for (int i = 0; i < 2; i++) {
            int f4 = tid + i * 256;
            int r = f4 >> 2;
            int kk = (f4 & 3) * 4;
            int gr = rowBase + r;
            float4 v = make_float4(0.f, 0.f, 0.f, 0.f);
            if (gr < M) v = *reinterpret_cast<const float4*>(A + (size_t)gr * K + k0 + kk);
            As[kk + 0][r] = v.x; As[kk + 1][r] = v.y; As[kk + 2][r] = v.z; As[kk + 3][r] = v.w;
            int gc = colBase + r;
            float4 w = make_float4(0.f, 0.f, 0.f, 0.f);
            if (gc < Nc) w = *reinterpret_cast<const float4*>(Bm + (size_t)gc * K + k0 + kk);
            Bs[kk + 0][r] = w.x; Bs[kk + 1][r] = w.y; Bs[kk + 2][r] = w.z; Bs[kk + 3][r] = w.w;
        }
        __syncthreads();
        #pragma unroll
        for (int k = 0; k < BK; k++) {
            float a[TM], b[TN];
            #pragma unroll
            for (int i = 0; i < TM; i++) a[i] = As[k][ty * TM + i];
            #pragma unroll
            for (int j = 0; j < TN; j++) b[j] = Bs[k][tx * TN + j];
            #pragma unroll
            for (int i = 0; i < TM; i++)
                #pragma unroll
                for (int j = 0; j < TN; j++) acc[i][j] = fmaf(a[i], b[j], acc[i][j]);
        }
        __syncthreads();
    }
    #pragma unroll
    for (int i = 0; i < TM; i++) {
        int gr = rowBase + ty * TM + i;
        if (gr >= M) continue;
        #pragma unroll
        for (int j = 0; j < TN; j++) {
            int gc = colBase + tx * TN + j;
            if (gc >= Nc) continue;
            float v = acc[i][j];
            if (bias) v += bias[gc];
            if (act) v = fmaxf(v, 0.f);
            Cm[(size_t)gr * Nc + gc] = v;
        }
    }
}

// ---------------- per-edge attention logits ----------------
template <int H>
__global__ void k_logits(const float* __restrict__ att) {
    int e = blockIdx.x;
    int h = threadIdx.x >> 5, lane = threadIdx.x & 31;
    int s, d;
    if (e < EE) { s = g_src[e]; d = g_dst[e]; } else { s = d = e - EE; }
    const int HC = H * CC;
    size_t eb = (size_t)e * HC + h * CC + lane;
    size_t sbb = (size_t)s * HC + h * CC + lane;
    size_t db = (size_t)d * HC + h * CC + lane;
    float acc = 0.f;
    #pragma unroll
    for (int j = 0; j < 8; j++) {
        float v = g_xl[sbb + 32 * j] + g_xr[db + 32 * j] + __bfloat162float(g_eeb[eb + 32 * j]);
        v = (v > 0.f) ? v : NEG_SLOPE * v;
        acc += v * att[h * CC + lane + 32 * j];
    }
    acc = warp_sum(acc);
    if (lane == 0) g_logits[e * H + h] = acc;
}

// ---------------- segment softmax + weighted gather ----------------
template <int H, int RELU>
__global__ void k_aggregate(const float* __restrict__ bias, float* __restrict__ out) {
    int n = blockIdx.x;
    int h = threadIdx.x >> 5, lane = threadIdx.x & 31;
    int s0 = g_off[n], s1 = g_off[n + 1];
    float mx = -1e30f;
    for (int i = s0 + lane; i < s1; i += 32) mx = fmaxf(mx, g_logits[g_csr[i] * H + h]);
    mx = warp_max(mx);
    float den = 0.f;
    for (int i = s0 + lane; i < s1; i += 32) den += __expf(g_logits[g_csr[i] * H + h] - mx);
    den = warp_sum(den);
    float inv = 1.f / den;
    const int HC = H * CC;
    float acc[8];
    #pragma unroll
    for (int j = 0; j < 8; j++) acc[j] = 0.f;
    for (int i = s0; i < s1; i++) {
        int e = g_csr[i];
        float w = __expf(g_logits[e * H + h] - mx) * inv;
        int s = (e < EE) ? g_src[e] : (e - EE);
        const float* row = g_xl + (size_t)s * HC + h * CC + lane;
        #pragma unroll
        for (int j = 0; j < 8; j++) acc[j] = fmaf(w, row[32 * j], acc[j]);
    }
    size_t ob = (size_t)n * HC + h * CC + lane;
    #pragma unroll
    for (int j = 0; j < 8; j++) {
        float v = acc[j] + bias[h * CC + lane + 32 * j];
        if (RELU) v = fmaxf(v, 0.f);
        out[ob + 32 * j] = v;
    }
}

// ---------------- pooling + final ----------------
__global__ void k_pool() {
    int t = blockIdx.x * blockDim.x + threadIdx.x;
    if (t >= NN * HC2) return;
    int n = t >> 10, c = t & 1023;
    int b = g_batch[n];
    atomicAdd(&g_pool[b * HC2 + c], g_h2[t]);
    if (c == 0) atomicAdd(&g_cnt[b], 1.f);
}
__global__ void k_pool_div() {
    int t = blockIdx.x * blockDim.x + threadIdx.x;
    if (t >= GG * HC2) return;
    g_pool[t] /= fmaxf(g_cnt[t >> 10], 1.f);
}
__global__ void k_final(const float* __restrict__ W3, const float* __restrict__ b3,
                        float* __restrict__ out) {
    int g = blockIdx.x, lane = threadIdx.x;
    float acc = 0.f;
    #pragma unroll
    for (int j = 0; j < 8; j++) acc += g_m2[g * 256 + lane + 32 * j] * W3[lane + 32 * j];
    acc = warp_sum(acc);
    if (lane == 0) out[g] = 1.f / (1.f + expf(-(acc + b3[0])));
}

// ---------------- host launch ----------------
static inline void launch_tc(const float* A, const float* B, const float* bias,
                             void* C, int M, int N, int K, int act, int outbf16) {
    dim3 grid(N / 128, M / 128);
    if (outbf16)
        k_mma_gemm<1><<<grid, 256, MMA_SMEM_BYTES>>>(A, B, bias, C, M, N, K, act);
    else
        k_mma_gemm<0><<<grid, 256, MMA_SMEM_BYTES>>>(A, B, bias, C, M, N, K, act);
}
static inline void launch_sgemm(const float* A, const float* B, const float* bias,
                                float* C, int M, int Nc, int K, int act) {
    dim3 grid((Nc + 127) / 128, (M + 127) / 128);
    k_sgemm<<<grid, 256>>>(A, B, bias, C, M, Nc, K, act);
}

extern "C" void kernel_launch(void* const* d_in, const int* in_sizes, int n_in,
                              void* d_out, int out_size) {
    const float* x     = (const float*)d_in[0];
    const int*   ei    = (const int*)  d_in[1];
    const float* ea    = (const float*)d_in[2];
    const int*   batch = (const int*)  d_in[3];
    const float* Wl1 = (const float*)d_in[4],  *bl1 = (const float*)d_in[5];
    const float* Wr1 = (const float*)d_in[6],  *br1 = (const float*)d_in[7];
    const float* We1 = (const float*)d_in[8],  *att1 = (const float*)d_in[9];
    const float* bias1 = (const float*)d_in[10];
    const float* Wl2 = (const float*)d_in[11], *bl2 = (const float*)d_in[12];
    const float* Wr2 = (const float*)d_in[13], *br2 = (const float*)d_in[14];
    const float* We2 = (const float*)d_in[15], *att2 = (const float*)d_in[16];
    const float* bias2 = (const float*)d_in[17];
    const float* W1 = (const float*)d_in[18], *b1 = (const float*)d_in[19];
    const float* W2 = (const float*)d_in[20], *b2 = (const float*)d_in[21];
    const float* W3 = (const float*)d_in[22], *b3 = (const float*)d_in[23];
    float* out = (float*)d_out;

    static int attr_done = 0;
    if (!attr_done) {
        cudaFuncSetAttribute(k_mma_gemm<0>, cudaFuncAttributeMaxDynamicSharedMemorySize, MMA_SMEM_BYTES);
        cudaFuncSetAttribute(k_mma_gemm<1>, cudaFuncAttributeMaxDynamicSharedMemorySize, MMA_SMEM_BYTES);
        attr_done = 1;
    }

    float *p_xl, *p_xr, *p_ea2, *p_h1, *p_h2, *p_pool, *p_m1, *p_m2;
    __nv_bfloat16* p_eeb;
    cudaGetSymbolAddress((void**)&p_xl,   g_xl);
    cudaGetSymbolAddress((void**)&p_xr,   g_xr);
    cudaGetSymbolAddress((void**)&p_eeb,  g_eeb);
    cudaGetSymbolAddress((void**)&p_ea2,  g_ea2);
    cudaGetSymbolAddress((void**)&p_h1,   g_h1);
    cudaGetSymbolAddress((void**)&p_h2,   g_h2);
    cudaGetSymbolAddress((void**)&p_pool, g_pool);
    cudaGetSymbolAddress((void**)&p_m1,   g_m1);
    cudaGetSymbolAddress((void**)&p_m2,   g_m2);

    // --- graph preprocessing ---
    k_detect<<<1, 1>>>(ei);
    k_norm_idx<<<(EE + 255) / 256, 256>>>(ei, batch);
    k_zero<<<(NN * DEDGE + 255) / 256, 256>>>();
    k_deg_easum<<<(EE * DEDGE + 255) / 256, 256>>>(ea);
    k_ea2<<<(ET * DEDGE + 255) / 256, 256>>>(ea);
    k_scan<<<1, 256>>>();
    k_csr<<<(ET + 255) / 256, 256>>>();

    // --- GATv2 layer 1 (tf32 mma.sync) ---
    launch_tc(x, Wl1, bl1, p_xl, NN, HC1, DNODE, 0, 0);
    launch_tc(x, Wr1, br1, p_xr, NN, HC1, DNODE, 0, 0);
    launch_tc(p_ea2, We1, nullptr, p_eeb, ET, HC1, DEDGE, 0, 1);
    k_logits<H1C><<<ET, H1C * 32>>>(att1);
    k_aggregate<H1C, 1><<<NN, H1C * 32>>>(bias1, p_h1);

    // --- GATv2 layer 2 ---
    launch_tc(p_h1, Wl2, bl2, p_xl, NN, HC2, HC1, 0, 0);
    launch_tc(p_h1, Wr2, br2, p_xr, NN, HC2, HC1, 0, 0);
    launch_tc(p_ea2, We2, nullptr, p_eeb, ET, HC2, DEDGE, 0, 1);
    k_logits<H2C><<<ET, H2C * 32>>>(att2);
    k_aggregate<H2C, 0><<<NN, H2C * 32>>>(bias2, p_h2);

    // --- pool + MLP (fp32 for accuracy; tiny) ---
    k_pool<<<(NN * HC2 + 255) / 256, 256>>>();
    k_pool_div<<<(GG * HC2 + 255) / 256, 256>>>();
    launch_sgemm(p_pool, W1, b1, p_m1, GG, 512, HC2, 1);
    launch_sgemm(p_m1,  W2, b2, p_m2, GG, 256, 512, 1);
    k_final<<<GG, 32>>>(W3, b3, out);
}

// round 4
// speedup vs baseline: 3.0966x; 1.6590x over previous
#include <cuda_runtime.h>
#include <cuda_fp16.h>
#include <math.h>
#include <stdint.h>

// ---------------- problem constants ----------------
#define NN   8192
#define EE   65536
#define GG   64
#define DNODE 64
#define DEDGE 32
#define CC   256
#define H1C  8
#define H2C  4
#define ET   (EE + NN)          // 73728 edges incl. self loops
#define HC1  (H1C * CC)         // 2048
#define HC2  (H2C * CC)         // 1024
#define NEG_SLOPE 0.2f

// ---------------- device scratch ----------------
__device__ int   g_is64;
__device__ int   g_src[EE];
__device__ int   g_dst[EE];
__device__ int   g_batch[NN];
__device__ int   g_deg[NN];
__device__ int   g_cur[NN];
__device__ int   g_off[NN + 1];
__device__ int   g_csr[ET];
__device__ float g_easum[NN * DEDGE];
__device__ float g_ea2[ET * DEDGE];
__device__ __half g_xl[NN * HC1];                 // fp16 lin_l output
__device__ __half g_xr[NN * HC1];                 // fp16 lin_r output
__device__ __half g_eeh[(size_t)ET * HC1];        // fp16 edge-feature GEMM output
__device__ float g_logits[ET * H1C];
__device__ float g_h1[NN * HC1];
__device__ float g_h2[NN * HC2];
__device__ float g_pool[GG * HC2];
__device__ float g_cnt[GG];
__device__ float g_m1[GG * 512];
__device__ float g_m2[GG * 256];

// ---------------- warp helpers ----------------
__device__ __forceinline__ float warp_sum(float v) {
    #pragma unroll
    for (int o = 16; o; o >>= 1) v += __shfl_xor_sync(0xffffffffu, v, o);
    return v;
}
__device__ __forceinline__ float warp_max(float v) {
    #pragma unroll
    for (int o = 16; o; o >>= 1) v = fmaxf(v, __shfl_xor_sync(0xffffffffu, v, o));
    return v;
}
__device__ __forceinline__ uint32_t pack_h2(float x, float y) {
    __half2 h = __floats2half2_rn(x, y);
    return *reinterpret_cast<uint32_t*>(&h);
}
__device__ __forceinline__ void mma_f16(float* c, uint4 a, uint2 b) {
    asm volatile(
        "mma.sync.aligned.m16n8k16.row.col.f32.f16.f16.f32 "
        "{%0,%1,%2,%3},{%4,%5,%6,%7},{%8,%9},{%0,%1,%2,%3};"
        : "+f"(c[0]), "+f"(c[1]), "+f"(c[2]), "+f"(c[3])
        : "r"(a.x), "r"(a.y), "r"(a.z), "r"(a.w), "r"(b.x), "r"(b.y));
}

// =================================================================
// fp16 mma.sync GEMM: C[M,N] = A[M,K] @ B[N,K]^T (+bias)
// Requires: M % 128 == 0, N % 128 == 0, K % 32 == 0. A,B fp32 in GMEM,
// converted to fp16 at smem staging. Accumulation fp32.
// CTA tile 128x128x32, 8 warps (4 M x 2 N), warp tile 32x64.
// Smem fragment-native layout:
//   A subtile (kstep, mtile): 128 u32 (=256 f16), lane*4+reg -> LDS.128
//   B subtile (kstep, ntile): 64 u32, lane*2+reg -> LDS.64
// kstep = 16 K-elements; 2 ksteps per 32-K chunk.
// Stage = (2*8*128 + 2*16*64) u32 = 4096 u32 = 16 KB; double buffered = 32 KB.
// =================================================================
#define MMA_SMEM_BYTES 32768

__device__ __forceinline__ void ldg_tile(
    const float* __restrict__ A, const float* __restrict__ B, int K,
    int rowBase, int colBase, int kc, int tid, float4* va, float4* vb)
{
    #pragma unroll
    for (int i = 0; i < 4; i++) {
        int id = i * 256 + tid;
        int r = id >> 3, c4 = id & 7;
        va[i] = *reinterpret_cast<const float4*>(A + (size_t)(rowBase + r) * K + kc + c4 * 4);
        vb[i] = *reinterpret_cast<const float4*>(B + (size_t)(colBase + r) * K + kc + c4 * 4);
    }
}

__device__ __forceinline__ void sts_tile(
    uint32_t* __restrict__ sA, uint32_t* __restrict__ sB,
    int tid, const float4* va, const float4* vb)
{
    #pragma unroll
    for (int i = 0; i < 4; i++) {
        int id = i * 256 + tid;
        int r = id >> 3, c4 = id & 7;
        int kstep = c4 >> 2;            // 16-K step within the 32-K chunk
        int pl = (c4 & 3) * 2;          // pair index 0,2,4,6 within kstep
        // ---- A: pair p -> lane (ri%8)*4 + (p&3), reg (p>=4)*2 + (ri>=8)
        int mtile = r >> 4, ri = r & 15;
        int regA = ((pl & 4) ? 2 : 0) + (ri >> 3);
        int laneA = (ri & 7) * 4 + (pl & 3);
        int baseA = (kstep * 8 + mtile) * 128;
        sA[baseA + laneA * 4 + regA]       = pack_h2(va[i].x, va[i].y);
        sA[baseA + (laneA + 1) * 4 + regA] = pack_h2(va[i].z, va[i].w);
        // ---- B: pair p -> lane ni*4 + (p&3), reg (p>=4)
        int ntile = r >> 3, ni = r & 7;
        int regB = (pl & 4) ? 1 : 0;
        int laneB = ni * 4 + (pl & 3);
        int baseB = (kstep * 16 + ntile) * 64;
        sB[baseB + laneB * 2 + regB]       = pack_h2(vb[i].x, vb[i].y);
        sB[baseB + (laneB + 1) * 2 + regB] = pack_h2(vb[i].z, vb[i].w);
    }
}

template <int OUTHALF>
__global__ __launch_bounds__(256) void k_mma_gemm(
    const float* __restrict__ A, const float* __restrict__ B,
    const float* __restrict__ bias, void* __restrict__ Cout,
    int M, int N, int K, int act)
{
    extern __shared__ uint32_t sm[];
    int tid = threadIdx.x;
    int wid = tid >> 5, lane = tid & 31;
    int mw = wid & 3, nw = wid >> 2;
    int gid = lane >> 2, tig = lane & 3;
    int rowBase = blockIdx.y * 128, colBase = blockIdx.x * 128;

    float acc[2][8][4];
    #pragma unroll
    for (int mt = 0; mt < 2; mt++)
        #pragma unroll
        for (int nt = 0; nt < 8; nt++)
            #pragma unroll
            for (int q = 0; q < 4; q++) acc[mt][nt][q] = 0.f;

    const int NCH = K >> 5;
    float4 va[4], vb[4];

    ldg_tile(A, B, K, rowBase, colBase, 0, tid, va, vb);
    sts_tile(sm, sm + 2048, tid, va, vb);
    __syncthreads();

    for (int c = 0; c < NCH; c++) {
        if (c + 1 < NCH)
            ldg_tile(A, B, K, rowBase, colBase, (c + 1) << 5, tid, va, vb);

        const uint32_t* As = sm + (c & 1) * 4096;
        const uint32_t* Bs = As + 2048;
        #pragma unroll
        for (int kstep = 0; kstep < 2; kstep++) {
            uint4 afr[2];
            #pragma unroll
            for (int mt = 0; mt < 2; mt++)
                afr[mt] = *reinterpret_cast<const uint4*>(
                    As + (kstep * 8 + mw * 2 + mt) * 128 + lane * 4);
            uint2 bfr[8];
            #pragma unroll
            for (int nt = 0; nt < 8; nt++)
                bfr[nt] = *reinterpret_cast<const uint2*>(
                    Bs + (kstep * 16 + nw * 8 + nt) * 64 + lane * 2);
            #pragma unroll
            for (int mt = 0; mt < 2; mt++)
                #pragma unroll
                for (int nt = 0; nt < 8; nt++)
                    mma_f16(acc[mt][nt], afr[mt], bfr[nt]);
        }

        if (c + 1 < NCH) {
            uint32_t* sA = sm + ((c + 1) & 1) * 4096;
            sts_tile(sA, sA + 2048, tid, va, vb);
        }
        __syncthreads();
    }

    // ---- epilogue ----
    #pragma unroll
    for (int mt = 0; mt < 2; mt++) {
        int row0 = rowBase + mw * 32 + mt * 16 + gid;
        #pragma unroll
        for (int nt = 0; nt < 8; nt++) {
            int col = colBase + nw * 64 + nt * 8 + tig * 2;
            float c0 = acc[mt][nt][0], c1 = acc[mt][nt][1];
            float c2 = acc[mt][nt][2], c3 = acc[mt][nt][3];
            if (bias) {
                float b0 = bias[col], b1 = bias[col + 1];
                c0 += b0; c1 += b1; c2 += b0; c3 += b1;
            }
            if (act) {
                c0 = fmaxf(c0, 0.f); c1 = fmaxf(c1, 0.f);
                c2 = fmaxf(c2, 0.f); c3 = fmaxf(c3, 0.f);
            }
            if (OUTHALF) {
                __half* Ch = (__half*)Cout;
                __half2 p0 = __floats2half2_rn(c0, c1);
                __half2 p1 = __floats2half2_rn(c2, c3);
                *reinterpret_cast<__half2*>(Ch + (size_t)row0 * N + col)       = p0;
                *reinterpret_cast<__half2*>(Ch + (size_t)(row0 + 8) * N + col) = p1;
            } else {
                float* Cf = (float*)Cout;
                *reinterpret_cast<float2*>(Cf + (size_t)row0 * N + col)       = make_float2(c0, c1);
                *reinterpret_cast<float2*>(Cf + (size_t)(row0 + 8) * N + col) = make_float2(c2, c3);
            }
        }
    }
}

// ---------------- index detection / normalization ----------------
__global__ void k_detect(const int* __restrict__ ei) {
    int is64 = 1;
    for (int i = 0; i < 16; i++)
        if (ei[2 * i + 1] != 0) is64 = 0;
    g_is64 = is64;
}
__global__ void k_norm_idx(const int* __restrict__ ei, const int* __restrict__ batch) {
    int t = blockIdx.x * blockDim.x + threadIdx.x;
    int is64 = g_is64;
    if (t < EE) {
        g_src[t] = is64 ? ei[2 * t]        : ei[t];
        g_dst[t] = is64 ? ei[2 * (EE + t)] : ei[EE + t];
    }
    if (t < NN) g_batch[t] = is64 ? batch[2 * t] : batch[t];
}
__global__ void k_zero() {
    int t = blockIdx.x * blockDim.x + threadIdx.x;
    if (t < NN) { g_deg[t] = 0; g_cur[t] = 0; }
    if (t < NN * DEDGE) g_easum[t] = 0.f;
    if (t < GG * HC2) g_pool[t] = 0.f;
    if (t < GG) g_cnt[t] = 0.f;
}
__global__ void k_deg_easum(const float* __restrict__ ea) {
    int t = blockIdx.x * blockDim.x + threadIdx.x;
    if (t >= EE * DEDGE) return;
    int e = t >> 5, d = t & 31;
    int dst = g_dst[e];
    atomicAdd(&g_easum[dst * DEDGE + d], ea[t]);
    if (d == 0) atomicAdd(&g_deg[dst], 1);
}
__global__ void k_ea2(const float* __restrict__ ea) {
    int t = blockIdx.x * blockDim.x + threadIdx.x;
    if (t >= ET * DEDGE) return;
    if (t < EE * DEDGE) {
        g_ea2[t] = ea[t];
    } else {
        int u = t - EE * DEDGE;
        int n = u >> 5;
        g_ea2[t] = g_easum[u] / fmaxf((float)g_deg[n], 1.f);
    }
}
__global__ void k_scan() {
    __shared__ int part[256];
    int t = threadIdx.x;
    int base = t * 32;
    int loc[32];
    int s = 0;
    #pragma unroll
    for (int i = 0; i < 32; i++) { loc[i] = s; s += g_deg[base + i] + 1; }
    part[t] = s;
    __syncthreads();
    if (t == 0) {
        int acc = 0;
        for (int i = 0; i < 256; i++) { int v = part[i]; part[i] = acc; acc += v; }
        g_off[NN] = acc;
    }
    __syncthreads();
    int p = part[t];
    #pragma unroll
    for (int i = 0; i < 32; i++) g_off[base + i] = p + loc[i];
}
__global__ void k_csr() {
    int e = blockIdx.x * blockDim.x + threadIdx.x;
    if (e >= ET) return;
    int node = (e < EE) ? g_dst[e] : (e - EE);
    int pos = g_off[node] + atomicAdd(&g_cur[node], 1);
    g_csr[pos] = e;
}

// ---------------- fp32 SGEMM for the tiny MLP (M=64) ----------------
__global__ __launch_bounds__(256) void k_sgemm(
    const float* __restrict__ A, const float* __restrict__ Bm,
    const float* __restrict__ bias, float* __restrict__ Cm,
    int M, int Nc, int K, int act)
{
    constexpr int BM = 128, BN = 128, BK = 16, TM = 8, TN = 8;
    __shared__ float As[BK][BM];
    __shared__ float Bs[BK][BN];
    int tid = threadIdx.x;
    int tx = tid % 16, ty = tid / 16;
    int rowBase = blockIdx.y * BM;
    int colBase = blockIdx.x * BN;
    float acc[TM][TN];
    #pragma unroll
    for (int i = 0; i < TM; i++)
        #pragma unroll
        for (int j = 0; j < TN; j++) acc[i][j] = 0.f;
    for (int k0 = 0; k0 < K; k0 += BK) {
        #pragma unroll
        for (int i = 0; i < 2; i++) {
            int f4 = tid + i * 256;
            int r = f4 >> 2;
            int kk = (f4 & 3) * 4;
            int gr = rowBase + r;
            float4 v = make_float4(0.f, 0.f, 0.f, 0.f);
            if (gr < M) v = *reinterpret_cast<const float4*>(A + (size_t)gr * K + k0 + kk);
            As[kk + 0][r] = v.x; As[kk + 1][r] = v.y; As[kk + 2][r] = v.z; As[kk + 3][r] = v.w;
            int gc = colBase + r;
            float4 w = make_float4(0.f, 0.f, 0.f, 0.f);
            if (gc < Nc) w = *reinterpret_cast<const float4*>(Bm + (size_t)gc * K + k0 + kk);
            Bs[kk + 0][r] = w.x; Bs[kk + 1][r] = w.y; Bs[kk + 2][r] = w.z; Bs[kk + 3][r] = w.w;
        }
        __syncthreads();
        #pragma unroll
        for (int k = 0; k < BK; k++) {
            float a[TM], b[TN];
            #pragma unroll
            for (int i = 0; i < TM; i++) a[i] = As[k][ty * TM + i];
            #pragma unroll
            for (int j = 0; j < TN; j++) b[j] = Bs[k][tx * TN + j];
            #pragma unroll
            for (int i = 0; i < TM; i++)
                #pragma unroll
                for (int j = 0; j < TN; j++) acc[i][j] = fmaf(a[i], b[j], acc[i][j]);
        }
        __syncthreads();
    }
    #pragma unroll
    for (int i = 0; i < TM; i++) {
        int gr = rowBase + ty * TM + i;
        if (gr >= M) continue;
        #pragma unroll
        for (int j = 0; j < TN; j++) {
            int gc = colBase + tx * TN + j;
            if (gc >= Nc) continue;
            float v = acc[i][j];
            if (bias) v += bias[gc];
            if (act) v = fmaxf(v, 0.f);
            Cm[(size_t)gr * Nc + gc] = v;
        }
    }
}

// ---------------- per-edge attention logits (half2 reads) ----------------
// logit[e,h] = sum_c lrelu(xl[src,h,c] + xr[dst,h,c] + ee[e,h,c]) * att[h,c]
template <int H>
__global__ void k_logits(const float* __restrict__ att) {
    int e = blockIdx.x;
    int h = threadIdx.x >> 5, lane = threadIdx.x & 31;
    int s, d;
    if (e < EE) { s = g_src[e]; d = g_dst[e]; } else { s = d = e - EE; }
    const int HCH = H * (CC / 2);       // half2 units per node row
    const __half2* xl = reinterpret_cast<const __half2*>(g_xl);
    const __half2* xr = reinterpret_cast<const __half2*>(g_xr);
    const __half2* ee = reinterpret_cast<const __half2*>(g_eeh);
    size_t sb = (size_t)s * HCH + h * 128 + lane;
    size_t db = (size_t)d * HCH + h * 128 + lane;
    size_t eb = (size_t)e * HCH + h * 128 + lane;
    float acc = 0.f;
    #pragma unroll
    for (int j = 0; j < 4; j++) {
        float2 a = __half22float2(xl[sb + 32 * j]);
        float2 b = __half22float2(xr[db + 32 * j]);
        float2 c = __half22float2(ee[eb + 32 * j]);
        float2 at = *reinterpret_cast<const float2*>(att + h * CC + 2 * (lane + 32 * j));
        float v0 = a.x + b.x + c.x, v1 = a.y + b.y + c.y;
        v0 = (v0 > 0.f) ? v0 : NEG_SLOPE * v0;
        v1 = (v1 > 0.f) ? v1 : NEG_SLOPE * v1;
        acc += v0 * at.x + v1 * at.y;
    }
    acc = warp_sum(acc);
    if (lane == 0) g_logits[e * H + h] = acc;
}

// ---------------- segment softmax + weighted gather (CSR) ----------------
template <int H, int RELU>
__global__ void k_aggregate(const float* __restrict__ bias, float* __restrict__ out) {
    int n = blockIdx.x;
    int h = threadIdx.x >> 5, lane = threadIdx.x & 31;
    int s0 = g_off[n], s1 = g_off[n + 1];
    float mx = -1e30f;
    for (int i = s0 + lane; i < s1; i += 32) mx = fmaxf(mx, g_logits[g_csr[i] * H + h]);
    mx = warp_max(mx);
    float den = 0.f;
    for (int i = s0 + lane; i < s1; i += 32) den += __expf(g_logits[g_csr[i] * H + h] - mx);
    den = warp_sum(den);
    float inv = 1.f / den;
    const int HCH = H * (CC / 2);
    const __half2* xl = reinterpret_cast<const __half2*>(g_xl);
    float2 acc[4];
    #pragma unroll
    for (int j = 0; j < 4; j++) acc[j] = make_float2(0.f, 0.f);
    for (int i = s0; i < s1; i++) {
        int e = g_csr[i];
        float w = __expf(g_logits[e * H + h] - mx) * inv;
        int s = (e < EE) ? g_src[e] : (e - EE);
        const __half2* row = xl + (size_t)s * HCH + h * 128 + lane;
        #pragma unroll
        for (int j = 0; j < 4; j++) {
            float2 f = __half22float2(row[32 * j]);
            acc[j].x = fmaf(w, f.x, acc[j].x);
            acc[j].y = fmaf(w, f.y, acc[j].y);
        }
    }
    #pragma unroll
    for (int j = 0; j < 4; j++) {
        int col = h * CC + 2 * (lane + 32 * j);
        float2 b = *reinterpret_cast<const float2*>(bias + col);
        float v0 = acc[j].x + b.x, v1 = acc[j].y + b.y;
        if (RELU) { v0 = fmaxf(v0, 0.f); v1 = fmaxf(v1, 0.f); }
        *reinterpret_cast<float2*>(out + (size_t)n * (H * CC) + col) = make_float2(v0, v1);
    }
}

// ---------------- pooling + final ----------------
__global__ void k_pool() {
    int t = blockIdx.x * blockDim.x + threadIdx.x;
    if (t >= NN * HC2) return;
    int n = t >> 10, c = t & 1023;
    int b = g_batch[n];
    atomicAdd(&g_pool[b * HC2 + c], g_h2[t]);
    if (c == 0) atomicAdd(&g_cnt[b], 1.f);
}
__global__ void k_pool_div() {
    int t = blockIdx.x * blockDim.x + threadIdx.x;
    if (t >= GG * HC2) return;
    g_pool[t] /= fmaxf(g_cnt[t >> 10], 1.f);
}
__global__ void k_final(const float* __restrict__ W3, const float* __restrict__ b3,
                        float* __restrict__ out) {
    int g = blockIdx.x, lane = threadIdx.x;
    float acc = 0.f;
    #pragma unroll
    for (int j = 0; j < 8; j++) acc += g_m2[g * 256 + lane + 32 * j] * W3[lane + 32 * j];
    acc = warp_sum(acc);
    if (lane == 0) out[g] = 1.f / (1.f + expf(-(acc + b3[0])));
}

// ---------------- host launch ----------------
static inline void launch_tc(const float* A, const float* B, const float* bias,
                             void* C, int M, int N, int K, int act) {
    dim3 grid(N / 128, M / 128);
    k_mma_gemm<1><<<grid, 256, MMA_SMEM_BYTES>>>(A, B, bias, C, M, N, K, act);
}
static inline void launch_sgemm(const float* A, const float* B, const float* bias,
                                float* C, int M, int Nc, int K, int act) {
    dim3 grid((Nc + 127) / 128, (M + 127) / 128);
    k_sgemm<<<grid, 256>>>(A, B, bias, C, M, Nc, K, act);
}

extern "C" void kernel_launch(void* const* d_in, const int* in_sizes, int n_in,
                              void* d_out, int out_size) {
    const float* x     = (const float*)d_in[0];
    const int*   ei    = (const int*)  d_in[1];
    const float* ea    = (const float*)d_in[2];
    const int*   batch = (const int*)  d_in[3];
    const float* Wl1 = (const float*)d_in[4],  *bl1 = (const float*)d_in[5];
    const float* Wr1 = (const float*)d_in[6],  *br1 = (const float*)d_in[7];
    const float* We1 = (const float*)d_in[8],  *att1 = (const float*)d_in[9];
    const float* bias1 = (const float*)d_in[10];
    const float* Wl2 = (const float*)d_in[11], *bl2 = (const float*)d_in[12];
    const float* Wr2 = (const float*)d_in[13], *br2 = (const float*)d_in[14];
    const float* We2 = (const float*)d_in[15], *att2 = (const float*)d_in[16];
    const float* bias2 = (const float*)d_in[17];
    const float* W1 = (const float*)d_in[18], *b1 = (const float*)d_in[19];
    const float* W2 = (const float*)d_in[20], *b2 = (const float*)d_in[21];
    const float* W3 = (const float*)d_in[22], *b3 = (const float*)d_in[23];
    float* out = (float*)d_out;

    float *p_ea2, *p_h1, *p_h2, *p_pool, *p_m1, *p_m2;
    __half *p_xl, *p_xr, *p_eeh;
    cudaGetSymbolAddress((void**)&p_xl,   g_xl);
    cudaGetSymbolAddress((void**)&p_xr,   g_xr);
    cudaGetSymbolAddress((void**)&p_eeh,  g_eeh);
    cudaGetSymbolAddress((void**)&p_ea2,  g_ea2);
    cudaGetSymbolAddress((void**)&p_h1,   g_h1);
    cudaGetSymbolAddress((void**)&p_h2,   g_h2);
    cudaGetSymbolAddress((void**)&p_pool, g_pool);
    cudaGetSymbolAddress((void**)&p_m1,   g_m1);
    cudaGetSymbolAddress((void**)&p_m2,   g_m2);

    // --- graph preprocessing ---
    k_detect<<<1, 1>>>(ei);
    k_norm_idx<<<(EE + 255) / 256, 256>>>(ei, batch);
    k_zero<<<(NN * DEDGE + 255) / 256, 256>>>();
    k_deg_easum<<<(EE * DEDGE + 255) / 256, 256>>>(ea);
    k_ea2<<<(ET * DEDGE + 255) / 256, 256>>>(ea);
    k_scan<<<1, 256>>>();
    k_csr<<<(ET + 255) / 256, 256>>>();

    // --- GATv2 layer 1 (fp16 mma.sync) ---
    launch_tc(x, Wl1, bl1, p_xl, NN, HC1, DNODE, 0);
    launch_tc(x, Wr1, br1, p_xr, NN, HC1, DNODE, 0);
    launch_tc(p_ea2, We1, nullptr, p_eeh, ET, HC1, DEDGE, 0);
    k_logits<H1C><<<ET, H1C * 32>>>(att1);
    k_aggregate<H1C, 1><<<NN, H1C * 32>>>(bias1, p_h1);

    // --- GATv2 layer 2 ---
    launch_tc(p_h1, Wl2, bl2, p_xl, NN, HC2, HC1, 0);
    launch_tc(p_h1, Wr2, br2, p_xr, NN, HC2, HC1, 0);
    launch_tc(p_ea2, We2, nullptr, p_eeh, ET, HC2, DEDGE, 0);
    k_logits<H2C><<<ET, H2C * 32>>>(att2);
    k_aggregate<H2C, 0><<<NN, H2C * 32>>>(bias2, p_h2);

    // --- pool + MLP (fp32; tiny) ---
    k_pool<<<(NN * HC2 + 255) / 256, 256>>>();
    k_pool_div<<<(GG * HC2 + 255) / 256, 256>>>();
    launch_sgemm(p_pool, W1, b1, p_m1, GG, 512, HC2, 1);
    launch_sgemm(p_m1,  W2, b2, p_m2, GG, 256, 512, 1);
    k_final<<<GG, 32>>>(W3, b3, out);
}

// round 5
// speedup vs baseline: 3.2334x; 1.0442x over previous
#include <cuda_runtime.h>
#include <cuda_fp16.h>
#include <math.h>
#include <stdint.h>

// ---------------- problem constants ----------------
#define NN   8192
#define EE   65536
#define GG   64
#define DNODE 64
#define DEDGE 32
#define CC   256
#define H1C  8
#define H2C  4
#define ET   (EE + NN)          // 73728 = 576*128
#define HC1  (H1C * CC)         // 2048
#define HC2  (H2C * CC)         // 1024
#define NEG_SLOPE 0.2f

// ---------------- device scratch ----------------
__device__ int    g_is64;
__device__ int    g_src[EE];
__device__ int    g_dst[EE];
__device__ int    g_batch[NN];
__device__ int    g_deg[NN];
__device__ int    g_cur[NN];
__device__ int    g_off[NN + 1];
__device__ int    g_csr[ET];
__device__ float  g_easum[NN * DEDGE];
__device__ __half g_ea2h[ET * DEDGE];
__device__ __half g_xl[NN * HC1];
__device__ __half g_xr[NN * HC1];
__device__ __half g_h1h[NN * HC1];
__device__ float  g_logits[ET * H1C];
__device__ float  g_h2[NN * HC2];
__device__ float  g_pool[GG * HC2];
__device__ float  g_cnt[GG];
__device__ float  g_m1[GG * 512];
__device__ float  g_m2[GG * 256];

// ---------------- warp helpers ----------------
__device__ __forceinline__ float warp_sum(float v) {
    #pragma unroll
    for (int o = 16; o; o >>= 1) v += __shfl_xor_sync(0xffffffffu, v, o);
    return v;
}
__device__ __forceinline__ float warp_max(float v) {
    #pragma unroll
    for (int o = 16; o; o >>= 1) v = fmaxf(v, __shfl_xor_sync(0xffffffffu, v, o));
    return v;
}
__device__ __forceinline__ uint32_t pack_h2(float x, float y) {
    __half2 h = __floats2half2_rn(x, y);
    return *reinterpret_cast<uint32_t*>(&h);
}
__device__ __forceinline__ void mma_f16(float* c, uint4 a, uint2 b) {
    asm volatile(
        "mma.sync.aligned.m16n8k16.row.col.f32.f16.f16.f32 "
        "{%0,%1,%2,%3},{%4,%5,%6,%7},{%8,%9},{%0,%1,%2,%3};"
        : "+f"(c[0]), "+f"(c[1]), "+f"(c[2]), "+f"(c[3])
        : "r"(a.x), "r"(a.y), "r"(a.z), "r"(a.w), "r"(b.x), "r"(b.y));
}

// =================================================================
// fp16 mma GEMM pieces. Fragment-native smem layout (validated R4):
//   A subtile (kstep, mtile): 128 u32, lane*4+reg  -> LDS.128
//   B subtile (kstep, ntile): 64  u32, lane*2+reg  -> LDS.64
// Stage = 4096 u32 (16 KB); double buffered = 32 KB.
// =================================================================
#define MMA_SMEM_BYTES 32768

template <int AH>
__device__ __forceinline__ void ldg_tile(
    const void* __restrict__ A, const float* __restrict__ B, int K,
    int rowBase, int colBase, int kc, int tid, uint2* pa, uint2* pb)
{
    #pragma unroll
    for (int i = 0; i < 4; i++) {
        int id = i * 256 + tid;
        int r = id >> 3, c4 = id & 7;
        if (AH) {
            pa[i] = *reinterpret_cast<const uint2*>(
                (const __half*)A + (size_t)(rowBase + r) * K + kc + c4 * 4);
        } else {
            float4 v = *reinterpret_cast<const float4*>(
                (const float*)A + (size_t)(rowBase + r) * K + kc + c4 * 4);
            pa[i].x = pack_h2(v.x, v.y); pa[i].y = pack_h2(v.z, v.w);
        }
        float4 w = *reinterpret_cast<const float4*>(B + (size_t)(colBase + r) * K + kc + c4 * 4);
        pb[i].x = pack_h2(w.x, w.y); pb[i].y = pack_h2(w.z, w.w);
    }
}

__device__ __forceinline__ void sts_tile(
    uint32_t* __restrict__ sA, uint32_t* __restrict__ sB,
    int tid, const uint2* pa, const uint2* pb)
{
    #pragma unroll
    for (int i = 0; i < 4; i++) {
        int id = i * 256 + tid;
        int r = id >> 3, c4 = id & 7;
        int kstep = c4 >> 2;
        int pl = (c4 & 3) * 2;
        int mtile = r >> 4, ri = r & 15;
        int regA = ((pl & 4) ? 2 : 0) + (ri >> 3);
        int laneA = (ri & 7) * 4 + (pl & 3);
        int baseA = (kstep * 8 + mtile) * 128;
        sA[baseA + laneA * 4 + regA]       = pa[i].x;
        sA[baseA + (laneA + 1) * 4 + regA] = pa[i].y;
        int ntile = r >> 3, ni = r & 7;
        int regB = (pl & 4) ? 1 : 0;
        int laneB = ni * 4 + (pl & 3);
        int baseB = (kstep * 16 + ntile) * 64;
        sB[baseB + laneB * 2 + regB]       = pb[i].x;
        sB[baseB + (laneB + 1) * 2 + regB] = pb[i].y;
    }
}

template <int AH, int OUTHALF>
__global__ __launch_bounds__(256) void k_mma_gemm(
    const void* __restrict__ A, const float* __restrict__ B,
    const float* __restrict__ bias, void* __restrict__ Cout,
    int M, int N, int K, int act)
{
    extern __shared__ uint32_t sm[];
    int tid = threadIdx.x;
    int wid = tid >> 5, lane = tid & 31;
    int mw = wid & 3, nw = wid >> 2;
    int gid = lane >> 2, tig = lane & 3;
    int rowBase = blockIdx.y * 128, colBase = blockIdx.x * 128;

    float acc[2][8][4];
    #pragma unroll
    for (int mt = 0; mt < 2; mt++)
        #pragma unroll
        for (int nt = 0; nt < 8; nt++)
            #pragma unroll
            for (int q = 0; q < 4; q++) acc[mt][nt][q] = 0.f;

    const int NCH = K >> 5;
    uint2 pa[4], pb[4];

    ldg_tile<AH>(A, B, K, rowBase, colBase, 0, tid, pa, pb);
    sts_tile(sm, sm + 2048, tid, pa, pb);
    __syncthreads();

    for (int c = 0; c < NCH; c++) {
        if (c + 1 < NCH)
            ldg_tile<AH>(A, B, K, rowBase, colBase, (c + 1) << 5, tid, pa, pb);

        const uint32_t* As = sm + (c & 1) * 4096;
        const uint32_t* Bs = As + 2048;
        #pragma unroll
        for (int kstep = 0; kstep < 2; kstep++) {
            uint4 afr[2];
            #pragma unroll
            for (int mt = 0; mt < 2; mt++)
                afr[mt] = *reinterpret_cast<const uint4*>(
                    As + (kstep * 8 + mw * 2 + mt) * 128 + lane * 4);
            uint2 bfr[8];
            #pragma unroll
            for (int nt = 0; nt < 8; nt++)
                bfr[nt] = *reinterpret_cast<const uint2*>(
                    Bs + (kstep * 16 + nw * 8 + nt) * 64 + lane * 2);
            #pragma unroll
            for (int mt = 0; mt < 2; mt++)
                #pragma unroll
                for (int nt = 0; nt < 8; nt++)
                    mma_f16(acc[mt][nt], afr[mt], bfr[nt]);
        }

        if (c + 1 < NCH) {
            uint32_t* sA = sm + ((c + 1) & 1) * 4096;
            sts_tile(sA, sA + 2048, tid, pa, pb);
        }
        __syncthreads();
    }

    #pragma unroll
    for (int mt = 0; mt < 2; mt++) {
        int row0 = rowBase + mw * 32 + mt * 16 + gid;
        #pragma unroll
        for (int nt = 0; nt < 8; nt++) {
            int col = colBase + nw * 64 + nt * 8 + tig * 2;
            float c0 = acc[mt][nt][0], c1 = acc[mt][nt][1];
            float c2 = acc[mt][nt][2], c3 = acc[mt][nt][3];
            if (bias) {
                float b0 = bias[col], b1 = bias[col + 1];
                c0 += b0; c1 += b1; c2 += b0; c3 += b1;
            }
            if (act) {
                c0 = fmaxf(c0, 0.f); c1 = fmaxf(c1, 0.f);
                c2 = fmaxf(c2, 0.f); c3 = fmaxf(c3, 0.f);
            }
            if (OUTHALF) {
                __half* Ch = (__half*)Cout;
                *reinterpret_cast<__half2*>(Ch + (size_t)row0 * N + col)       = __floats2half2_rn(c0, c1);
                *reinterpret_cast<__half2*>(Ch + (size_t)(row0 + 8) * N + col) = __floats2half2_rn(c2, c3);
            } else {
                float* Cf = (float*)Cout;
                *reinterpret_cast<float2*>(Cf + (size_t)row0 * N + col)       = make_float2(c0, c1);
                *reinterpret_cast<float2*>(Cf + (size_t)(row0 + 8) * N + col) = make_float2(c2, c3);
            }
        }
    }
}

// =================================================================
// Fused edge-feature GEMM + attention logits.
// ee = ea2h @ We^T (K=32, single chunk). Epilogue: per element
// v = lrelu(ee + xl[src,col] + xr[dst,col]) * att[col], reduced to
// logits[e, h] via quad-shuffle + atomicAdd. One head per CTA tile.
// =================================================================
template <int H>
__global__ __launch_bounds__(256) void k_ee_logits(
    const __half* __restrict__ A, const float* __restrict__ B,
    const float* __restrict__ att)
{
    __shared__ uint32_t sm[4096];
    int tid = threadIdx.x;
    int wid = tid >> 5, lane = tid & 31;
    int mw = wid & 3, nw = wid >> 2;
    int gid = lane >> 2, tig = lane & 3;
    int rowBase = blockIdx.y * 128, colBase = blockIdx.x * 128;

    float acc[2][8][4];
    #pragma unroll
    for (int mt = 0; mt < 2; mt++)
        #pragma unroll
        for (int nt = 0; nt < 8; nt++)
            #pragma unroll
            for (int q = 0; q < 4; q++) acc[mt][nt][q] = 0.f;

    uint2 pa[4], pb[4];
    ldg_tile<1>(A, B, DEDGE, rowBase, colBase, 0, tid, pa, pb);
    sts_tile(sm, sm + 2048, tid, pa, pb);
    __syncthreads();

    #pragma unroll
    for (int kstep = 0; kstep < 2; kstep++) {
        uint4 afr[2];
        #pragma unroll
        for (int mt = 0; mt < 2; mt++)
            afr[mt] = *reinterpret_cast<const uint4*>(
                sm + (kstep * 8 + mw * 2 + mt) * 128 + lane * 4);
        uint2 bfr[8];
        #pragma unroll
        for (int nt = 0; nt < 8; nt++)
            bfr[nt] = *reinterpret_cast<const uint2*>(
                sm + 2048 + (kstep * 16 + nw * 8 + nt) * 64 + lane * 2);
        #pragma unroll
        for (int mt = 0; mt < 2; mt++)
            #pragma unroll
            for (int nt = 0; nt < 8; nt++)
                mma_f16(acc[mt][nt], afr[mt], bfr[nt]);
    }

    // ---- fused logits epilogue ----
    int h = colBase >> 8;                       // CC = 256
    const int HCH = H * (CC / 2);               // half2 per node row
    const __half2* xl = reinterpret_cast<const __half2*>(g_xl);
    const __half2* xr = reinterpret_cast<const __half2*>(g_xr);

    #pragma unroll
    for (int mt = 0; mt < 2; mt++) {
        int e0 = rowBase + mw * 32 + mt * 16 + gid;
        int e1 = e0 + 8;
        int s0, d0, s1, d1;
        if (e0 < EE) { s0 = g_src[e0]; d0 = g_dst[e0]; } else { s0 = d0 = e0 - EE; }
        if (e1 < EE) { s1 = g_src[e1]; d1 = g_dst[e1]; } else { s1 = d1 = e1 - EE; }
        float p0 = 0.f, p1 = 0.f;
        #pragma unroll
        for (int nt = 0; nt < 8; nt++) {
            int col = colBase + nw * 64 + nt * 8 + tig * 2;
            int c2i = col >> 1;
            float2 at = *reinterpret_cast<const float2*>(att + h * CC + (col & (CC - 1)));
            float2 a0 = __half22float2(xl[(size_t)s0 * HCH + c2i]);
            float2 b0 = __half22float2(xr[(size_t)d0 * HCH + c2i]);
            float2 a1 = __half22float2(xl[(size_t)s1 * HCH + c2i]);
            float2 b1 = __half22float2(xr[(size_t)d1 * HCH + c2i]);
            float v0 = acc[mt][nt][0] + a0.x + b0.x;
            float v1 = acc[mt][nt][1] + a0.y + b0.y;
            float v2 = acc[mt][nt][2] + a1.x + b1.x;
            float v3 = acc[mt][nt][3] + a1.y + b1.y;
            v0 = (v0 > 0.f) ? v0 : NEG_SLOPE * v0;
            v1 = (v1 > 0.f) ? v1 : NEG_SLOPE * v1;
            v2 = (v2 > 0.f) ? v2 : NEG_SLOPE * v2;
            v3 = (v3 > 0.f) ? v3 : NEG_SLOPE * v3;
            p0 += v0 * at.x + v1 * at.y;
            p1 += v2 * at.x + v3 * at.y;
        }
        // reduce over the quad (tig lanes)
        p0 += __shfl_xor_sync(0xffffffffu, p0, 1);
        p0 += __shfl_xor_sync(0xffffffffu, p0, 2);
        p1 += __shfl_xor_sync(0xffffffffu, p1, 1);
        p1 += __shfl_xor_sync(0xffffffffu, p1, 2);
        if (tig == 0) {
            atomicAdd(&g_logits[e0 * H + h], p0);
            atomicAdd(&g_logits[e1 * H + h], p1);
        }
    }
}

__global__ void k_zlog(int count) {
    int t = blockIdx.x * blockDim.x + threadIdx.x;
    if (t < count) g_logits[t] = 0.f;
}

// ---------------- index detection / normalization ----------------
__global__ void k_detect(const int* __restrict__ ei) {
    int is64 = 1;
    for (int i = 0; i < 16; i++)
        if (ei[2 * i + 1] != 0) is64 = 0;
    g_is64 = is64;
}
__global__ void k_norm_idx(const int* __restrict__ ei, const int* __restrict__ batch) {
    int t = blockIdx.x * blockDim.x + threadIdx.x;
    int is64 = g_is64;
    if (t < EE) {
        g_src[t] = is64 ? ei[2 * t]        : ei[t];
        g_dst[t] = is64 ? ei[2 * (EE + t)] : ei[EE + t];
    }
    if (t < NN) g_batch[t] = is64 ? batch[2 * t] : batch[t];
}
__global__ void k_zero() {
    int t = blockIdx.x * blockDim.x + threadIdx.x;
    if (t < NN) { g_deg[t] = 0; g_cur[t] = 0; }
    if (t < NN * DEDGE) g_easum[t] = 0.f;
    if (t < GG * HC2) g_pool[t] = 0.f;
    if (t < GG) g_cnt[t] = 0.f;
}
__global__ void k_deg_easum(const float* __restrict__ ea) {
    int t = blockIdx.x * blockDim.x + threadIdx.x;
    if (t >= EE * DEDGE) return;
    int e = t >> 5, d = t & 31;
    int dst = g_dst[e];
    atomicAdd(&g_easum[dst * DEDGE + d], ea[t]);
    if (d == 0) atomicAdd(&g_deg[dst], 1);
}
__global__ void k_ea2(const float* __restrict__ ea) {
    int t = blockIdx.x * blockDim.x + threadIdx.x;
    if (t >= ET * DEDGE) return;
    if (t < EE * DEDGE) {
        g_ea2h[t] = __float2half_rn(ea[t]);
    } else {
        int u = t - EE * DEDGE;
        int n = u >> 5;
        g_ea2h[t] = __float2half_rn(g_easum[u] / fmaxf((float)g_deg[n], 1.f));
    }
}
__global__ void k_scan() {
    __shared__ int part[256];
    int t = threadIdx.x;
    int base = t * 32;
    int loc[32];
    int s = 0;
    #pragma unroll
    for (int i = 0; i < 32; i++) { loc[i] = s; s += g_deg[base + i] + 1; }
    part[t] = s;
    __syncthreads();
    if (t == 0) {
        int acc = 0;
        for (int i = 0; i < 256; i++) { int v = part[i]; part[i] = acc; acc += v; }
        g_off[NN] = acc;
    }
    __syncthreads();
    int p = part[t];
    #pragma unroll
    for (int i = 0; i < 32; i++) g_off[base + i] = p + loc[i];
}
__global__ void k_csr() {
    int e = blockIdx.x * blockDim.x + threadIdx.x;
    if (e >= ET) return;
    int node = (e < EE) ? g_dst[e] : (e - EE);
    int pos = g_off[node] + atomicAdd(&g_cur[node], 1);
    g_csr[pos] = e;
}

// ---------------- fp32 SGEMM for the tiny MLP (M=64) ----------------
__global__ __launch_bounds__(256) void k_sgemm(
    const float* __restrict__ A, const float* __restrict__ Bm,
    const float* __restrict__ bias, float* __restrict__ Cm,
    int M, int Nc, int K, int act)
{
    constexpr int BM = 128, BN = 128, BK = 16, TM = 8, TN = 8;
    __shared__ float As[BK][BM];
    __shared__ float Bs[BK][BN];
    int tid = threadIdx.x;
    int tx = tid % 16, ty = tid / 16;
    int rowBase = blockIdx.y * BM;
    int colBase = blockIdx.x * BN;
    float acc[TM][TN];
    #pragma unroll
    for (int i = 0; i < TM; i++)
        #pragma unroll
        for (int j = 0; j < TN; j++) acc[i][j] = 0.f;
    for (int k0 = 0; k0 < K; k0 += BK) {
        #pragma unroll
        for (int i = 0; i < 2; i++) {
            int f4 = tid + i * 256;
            int r = f4 >> 2;
            int kk = (f4 & 3) * 4;
            int gr = rowBase + r;
            float4 v = make_float4(0.f, 0.f, 0.f, 0.f);
            if (gr < M) v = *reinterpret_cast<const float4*>(A + (size_t)gr * K + k0 + kk);
            As[kk + 0][r] = v.x; As[kk + 1][r] = v.y; As[kk + 2][r] = v.z; As[kk + 3][r] = v.w;
            int gc = colBase + r;
            float4 w = make_float4(0.f, 0.f, 0.f, 0.f);
            if (gc < Nc) w = *reinterpret_cast<const float4*>(Bm + (size_t)gc * K + k0 + kk);
            Bs[kk + 0][r] = w.x; Bs[kk + 1][r] = w.y; Bs[kk + 2][r] = w.z; Bs[kk + 3][r] = w.w;
        }
        __syncthreads();
        #pragma unroll
        for (int k = 0; k < BK; k++) {
            float a[TM], b[TN];
            #pragma unroll
            for (int i = 0; i < TM; i++) a[i] = As[k][ty * TM + i];
            #pragma unroll
            for (int j = 0; j < TN; j++) b[j] = Bs[k][tx * TN + j];
            #pragma unroll
            for (int i = 0; i < TM; i++)
                #pragma unroll
                for (int j = 0; j < TN; j++) acc[i][j] = fmaf(a[i], b[j], acc[i][j]);
        }
        __syncthreads();
    }
    #pragma unroll
    for (int i = 0; i < TM; i++) {
        int gr = rowBase + ty * TM + i;
        if (gr >= M) continue;
        #pragma unroll
        for (int j = 0; j < TN; j++) {
            int gc = colBase + tx * TN + j;
            if (gc >= Nc) continue;
            float v = acc[i][j];
            if (bias) v += bias[gc];
            if (act) v = fmaxf(v, 0.f);
            Cm[(size_t)gr * Nc + gc] = v;
        }
    }
}

// ---------------- segment softmax + weighted gather (CSR) ----------------
template <int H, int RELU, int OUTH>
__global__ void k_aggregate(const float* __restrict__ bias, void* __restrict__ out) {
    int n = blockIdx.x;
    int h = threadIdx.x >> 5, lane = threadIdx.x & 31;
    int s0 = g_off[n], s1 = g_off[n + 1];
    float mx = -1e30f;
    for (int i = s0 + lane; i < s1; i += 32) mx = fmaxf(mx, g_logits[g_csr[i] * H + h]);
    mx = warp_max(mx);
    float den = 0.f;
    for (int i = s0 + lane; i < s1; i += 32) den += __expf(g_logits[g_csr[i] * H + h] - mx);
    den = warp_sum(den);
    float inv = 1.f / den;
    const int HCH = H * (CC / 2);
    const __half2* xl = reinterpret_cast<const __half2*>(g_xl);
    float2 acc[4];
    #pragma unroll
    for (int j = 0; j < 4; j++) acc[j] = make_float2(0.f, 0.f);
    for (int i = s0; i < s1; i++) {
        int e = g_csr[i];
        float w = __expf(g_logits[e * H + h] - mx) * inv;
        int s = (e < EE) ? g_src[e] : (e - EE);
        const __half2* row = xl + (size_t)s * HCH + h * 128 + lane;
        #pragma unroll
        for (int j = 0; j < 4; j++) {
            float2 f = __half22float2(row[32 * j]);
            acc[j].x = fmaf(w, f.x, acc[j].x);
            acc[j].y = fmaf(w, f.y, acc[j].y);
        }
    }
    #pragma unroll
    for (int j = 0; j < 4; j++) {
        int col = h * CC + 2 * (lane + 32 * j);
        float2 b = *reinterpret_cast<const float2*>(bias + col);
        float v0 = acc[j].x + b.x, v1 = acc[j].y + b.y;
        if (RELU) { v0 = fmaxf(v0, 0.f); v1 = fmaxf(v1, 0.f); }
        if (OUTH) {
            __half* oh = (__half*)out;
            *reinterpret_cast<__half2*>(oh + (size_t)n * (H * CC) + col) = __floats2half2_rn(v0, v1);
        } else {
            float* of = (float*)out;
            *reinterpret_cast<float2*>(of + (size_t)n * (H * CC) + col) = make_float2(v0, v1);
        }
    }
}

// ---------------- pooling + final ----------------
__global__ void k_pool() {
    int t = blockIdx.x * blockDim.x + threadIdx.x;
    if (t >= NN * HC2) return;
    int n = t >> 10, c = t & 1023;
    int b = g_batch[n];
    atomicAdd(&g_pool[b * HC2 + c], g_h2[t]);
    if (c == 0) atomicAdd(&g_cnt[b], 1.f);
}
__global__ void k_pool_div() {
    int t = blockIdx.x * blockDim.x + threadIdx.x;
    if (t >= GG * HC2) return;
    g_pool[t] /= fmaxf(g_cnt[t >> 10], 1.f);
}
__global__ void k_final(const float* __restrict__ W3, const float* __restrict__ b3,
                        float* __restrict__ out) {
    int g = blockIdx.x, lane = threadIdx.x;
    float acc = 0.f;
    #pragma unroll
    for (int j = 0; j < 8; j++) acc += g_m2[g * 256 + lane + 32 * j] * W3[lane + 32 * j];
    acc = warp_sum(acc);
    if (lane == 0) out[g] = 1.f / (1.f + expf(-(acc + b3[0])));
}

// ---------------- host launch ----------------
template <int AH>
static inline void launch_tc(const void* A, const float* B, const float* bias,
                             void* C, int M, int N, int K) {
    dim3 grid(N / 128, M / 128);
    k_mma_gemm<AH, 1><<<grid, 256, MMA_SMEM_BYTES>>>(A, B, bias, C, M, N, K, 0);
}
static inline void launch_sgemm(const float* A, const float* B, const float* bias,
                                float* C, int M, int Nc, int K, int act) {
    dim3 grid((Nc + 127) / 128, (M + 127) / 128);
    k_sgemm<<<grid, 256>>>(A, B, bias, C, M, Nc, K, act);
}

extern "C" void kernel_launch(void* const* d_in, const int* in_sizes, int n_in,
                              void* d_out, int out_size) {
    const float* x     = (const float*)d_in[0];
    const int*   ei    = (const int*)  d_in[1];
    const float* ea    = (const float*)d_in[2];
    const int*   batch = (const int*)  d_in[3];
    const float* Wl1 = (const float*)d_in[4],  *bl1 = (const float*)d_in[5];
    const float* Wr1 = (const float*)d_in[6],  *br1 = (const float*)d_in[7];
    const float* We1 = (const float*)d_in[8],  *att1 = (const float*)d_in[9];
    const float* bias1 = (const float*)d_in[10];
    const float* Wl2 = (const float*)d_in[11], *bl2 = (const float*)d_in[12];
    const float* Wr2 = (const float*)d_in[13], *br2 = (const float*)d_in[14];
    const float* We2 = (const float*)d_in[15], *att2 = (const float*)d_in[16];
    const float* bias2 = (const float*)d_in[17];
    const float* W1 = (const float*)d_in[18], *b1 = (const float*)d_in[19];
    const float* W2 = (const float*)d_in[20], *b2 = (const float*)d_in[21];
    const float* W3 = (const float*)d_in[22], *b3 = (const float*)d_in[23];
    float* out = (float*)d_out;

    float *p_h2, *p_pool, *p_m1, *p_m2;
    __half *p_xl, *p_xr, *p_h1h, *p_ea2h;
    cudaGetSymbolAddress((void**)&p_xl,    g_xl);
    cudaGetSymbolAddress((void**)&p_xr,    g_xr);
    cudaGetSymbolAddress((void**)&p_h1h,   g_h1h);
    cudaGetSymbolAddress((void**)&p_ea2h,  g_ea2h);
    cudaGetSymbolAddress((void**)&p_h2,    g_h2);
    cudaGetSymbolAddress((void**)&p_pool,  g_pool);
    cudaGetSymbolAddress((void**)&p_m1,    g_m1);
    cudaGetSymbolAddress((void**)&p_m2,    g_m2);

    // --- graph preprocessing ---
    k_detect<<<1, 1>>>(ei);
    k_norm_idx<<<(EE + 255) / 256, 256>>>(ei, batch);
    k_zero<<<(NN * DEDGE + 255) / 256, 256>>>();
    k_deg_easum<<<(EE * DEDGE + 255) / 256, 256>>>(ea);
    k_ea2<<<(ET * DEDGE + 255) / 256, 256>>>(ea);
    k_scan<<<1, 256>>>();
    k_csr<<<(ET + 255) / 256, 256>>>();

    // --- GATv2 layer 1 ---
    k_zlog<<<(ET * H1C + 255) / 256, 256>>>(ET * H1C);
    launch_tc<0>(x, Wl1, bl1, p_xl, NN, HC1, DNODE);
    launch_tc<0>(x, Wr1, br1, p_xr, NN, HC1, DNODE);
    k_ee_logits<H1C><<<dim3(HC1 / 128, ET / 128), 256>>>(p_ea2h, We1, att1);
    k_aggregate<H1C, 1, 1><<<NN, H1C * 32>>>(bias1, p_h1h);

    // --- GATv2 layer 2 ---
    k_zlog<<<(ET * H2C + 255) / 256, 256>>>(ET * H2C);
    launch_tc<1>(p_h1h, Wl2, bl2, p_xl, NN, HC2, HC1);
    launch_tc<1>(p_h1h, Wr2, br2, p_xr, NN, HC2, HC1);
    k_ee_logits<H2C><<<dim3(HC2 / 128, ET / 128), 256>>>(p_ea2h, We2, att2);
    k_aggregate<H2C, 0, 0><<<NN, H2C * 32>>>(bias2, p_h2);

    // --- pool + MLP ---
    k_pool<<<(NN * HC2 + 255) / 256, 256>>>();
    k_pool_div<<<(GG * HC2 + 255) / 256, 256>>>();
    launch_sgemm(p_pool, W1, b1, p_m1, GG, 512, HC2, 1);
    launch_sgemm(p_m1,  W2, b2, p_m2, GG, 256, 512, 1);
    k_final<<<GG, 32>>>(W3, b3, out);
}

// round 6
// speedup vs baseline: 3.5190x; 1.0883x over previous
#include <cuda_runtime.h>
#include <cuda_fp16.h>
#include <math.h>
#include <stdint.h>

// ---------------- problem constants ----------------
#define NN   8192
#define EE   65536
#define GG   64
#define DNODE 64
#define DEDGE 32
#define CC   256
#define H1C  8
#define H2C  4
#define ET   (EE + NN)          // 73728 = 576*128
#define HC1  (H1C * CC)         // 2048
#define HC2  (H2C * CC)         // 1024
#define NEG_SLOPE 0.2f

// ---------------- device scratch ----------------
__device__ int    g_is64;
__device__ int    g_src[EE];
__device__ int    g_dst[EE];
__device__ int    g_batch[NN];
__device__ int    g_deg[NN];
__device__ int    g_cur[NN];
__device__ int    g_off[NN + 1];
__device__ int    g_csr[ET];
__device__ float  g_easum[NN * DEDGE];
__device__ __half g_ea2h[ET * DEDGE];
__device__ __half g_xl[NN * HC1];
__device__ __half g_xr[NN * HC1];
__device__ __half g_h1h[NN * HC1];
__device__ float  g_logits[ET * H1C];
__device__ float  g_h2[NN * HC2];
__device__ float  g_pool[GG * HC2];
__device__ float  g_cnt[GG];
__device__ float  g_m1[GG * 512];
__device__ float  g_m2[GG * 256];
// fp16 weights (converted once per call)
__device__ __half g_w1h[2 * HC1 * DNODE];    // [Wl1; Wr1]  (4096 x 64)
__device__ __half g_w2h[2 * HC2 * HC1];      // [Wl2; Wr2]  (2048 x 2048)
__device__ __half g_we1h[HC1 * DEDGE];
__device__ __half g_we2h[HC2 * DEDGE];

// ---------------- warp helpers ----------------
__device__ __forceinline__ float warp_sum(float v) {
    #pragma unroll
    for (int o = 16; o; o >>= 1) v += __shfl_xor_sync(0xffffffffu, v, o);
    return v;
}
__device__ __forceinline__ float warp_max(float v) {
    #pragma unroll
    for (int o = 16; o; o >>= 1) v = fmaxf(v, __shfl_xor_sync(0xffffffffu, v, o));
    return v;
}
__device__ __forceinline__ uint32_t pack_h2(float x, float y) {
    __half2 h = __floats2half2_rn(x, y);
    return *reinterpret_cast<uint32_t*>(&h);
}
__device__ __forceinline__ void mma_f16(float* c, uint4 a, uint2 b) {
    asm volatile(
        "mma.sync.aligned.m16n8k16.row.col.f32.f16.f16.f32 "
        "{%0,%1,%2,%3},{%4,%5,%6,%7},{%8,%9},{%0,%1,%2,%3};"
        : "+f"(c[0]), "+f"(c[1]), "+f"(c[2]), "+f"(c[3])
        : "r"(a.x), "r"(a.y), "r"(a.z), "r"(a.w), "r"(b.x), "r"(b.y));
}

// =================================================================
// fp16 mma GEMM pieces (fragment-native smem layout, validated R4/R5)
// =================================================================
#define MMA_SMEM_BYTES 32768

template <int AH, int BH>
__device__ __forceinline__ void ldg_tile(
    const void* __restrict__ A, const void* __restrict__ B, int K,
    int rowBase, int colBase, int kc, int tid, uint2* pa, uint2* pb)
{
    #pragma unroll
    for (int i = 0; i < 4; i++) {
        int id = i * 256 + tid;
        int r = id >> 3, c4 = id & 7;
        if (AH) {
            pa[i] = *reinterpret_cast<const uint2*>(
                (const __half*)A + (size_t)(rowBase + r) * K + kc + c4 * 4);
        } else {
            float4 v = *reinterpret_cast<const float4*>(
                (const float*)A + (size_t)(rowBase + r) * K + kc + c4 * 4);
            pa[i].x = pack_h2(v.x, v.y); pa[i].y = pack_h2(v.z, v.w);
        }
        if (BH) {
            pb[i] = *reinterpret_cast<const uint2*>(
                (const __half*)B + (size_t)(colBase + r) * K + kc + c4 * 4);
        } else {
            float4 w = *reinterpret_cast<const float4*>(
                (const float*)B + (size_t)(colBase + r) * K + kc + c4 * 4);
            pb[i].x = pack_h2(w.x, w.y); pb[i].y = pack_h2(w.z, w.w);
        }
    }
}

__device__ __forceinline__ void sts_tile(
    uint32_t* __restrict__ sA, uint32_t* __restrict__ sB,
    int tid, const uint2* pa, const uint2* pb)
{
    #pragma unroll
    for (int i = 0; i < 4; i++) {
        int id = i * 256 + tid;
        int r = id >> 3, c4 = id & 7;
        int kstep = c4 >> 2;
        int pl = (c4 & 3) * 2;
        int mtile = r >> 4, ri = r & 15;
        int regA = ((pl & 4) ? 2 : 0) + (ri >> 3);
        int laneA = (ri & 7) * 4 + (pl & 3);
        int baseA = (kstep * 8 + mtile) * 128;
        sA[baseA + laneA * 4 + regA]       = pa[i].x;
        sA[baseA + (laneA + 1) * 4 + regA] = pa[i].y;
        int ntile = r >> 3, ni = r & 7;
        int regB = (pl & 4) ? 1 : 0;
        int laneB = ni * 4 + (pl & 3);
        int baseB = (kstep * 16 + ntile) * 64;
        sB[baseB + laneB * 2 + regB]       = pb[i].x;
        sB[baseB + (laneB + 1) * 2 + regB] = pb[i].y;
    }
}

// ---- dual-output GEMM: C = A @ [BL;BR]^T, columns [0,N/2) -> outL (+biasL),
//      [N/2,N) -> outR (+biasR). Outputs fp16, row stride N/2. ----
template <int AH>
__global__ __launch_bounds__(256) void k_mma_dual(
    const void* __restrict__ A, const __half* __restrict__ B,
    const float* __restrict__ biasL, const float* __restrict__ biasR,
    __half* __restrict__ outL, __half* __restrict__ outR,
    int M, int N, int K)
{
    extern __shared__ uint32_t sm[];
    int tid = threadIdx.x;
    int wid = tid >> 5, lane = tid & 31;
    int mw = wid & 3, nw = wid >> 2;
    int gid = lane >> 2, tig = lane & 3;
    int rowBase = blockIdx.y * 128, colBase = blockIdx.x * 128;

    float acc[2][8][4];
    #pragma unroll
    for (int mt = 0; mt < 2; mt++)
        #pragma unroll
        for (int nt = 0; nt < 8; nt++)
            #pragma unroll
            for (int q = 0; q < 4; q++) acc[mt][nt][q] = 0.f;

    const int NCH = K >> 5;
    uint2 pa[4], pb[4];

    ldg_tile<AH, 1>(A, B, K, rowBase, colBase, 0, tid, pa, pb);
    sts_tile(sm, sm + 2048, tid, pa, pb);
    __syncthreads();

    for (int c = 0; c < NCH; c++) {
        if (c + 1 < NCH)
            ldg_tile<AH, 1>(A, B, K, rowBase, colBase, (c + 1) << 5, tid, pa, pb);

        const uint32_t* As = sm + (c & 1) * 4096;
        const uint32_t* Bs = As + 2048;
        #pragma unroll
        for (int kstep = 0; kstep < 2; kstep++) {
            uint4 afr[2];
            #pragma unroll
            for (int mt = 0; mt < 2; mt++)
                afr[mt] = *reinterpret_cast<const uint4*>(
                    As + (kstep * 8 + mw * 2 + mt) * 128 + lane * 4);
            uint2 bfr[8];
            #pragma unroll
            for (int nt = 0; nt < 8; nt++)
                bfr[nt] = *reinterpret_cast<const uint2*>(
                    Bs + (kstep * 16 + nw * 8 + nt) * 64 + lane * 2);
            #pragma unroll
            for (int mt = 0; mt < 2; mt++)
                #pragma unroll
                for (int nt = 0; nt < 8; nt++)
                    mma_f16(acc[mt][nt], afr[mt], bfr[nt]);
        }

        if (c + 1 < NCH) {
            uint32_t* sA = sm + ((c + 1) & 1) * 4096;
            sts_tile(sA, sA + 2048, tid, pa, pb);
        }
        __syncthreads();
    }

    // ---- epilogue: select side ----
    int halfN = N >> 1;
    bool isR = (colBase >= halfN);
    const float* bias = isR ? biasR : biasL;
    __half* outp = isR ? outR : outL;
    int cb = colBase - (isR ? halfN : 0);

    #pragma unroll
    for (int mt = 0; mt < 2; mt++) {
        int row0 = rowBase + mw * 32 + mt * 16 + gid;
        #pragma unroll
        for (int nt = 0; nt < 8; nt++) {
            int col = cb + nw * 64 + nt * 8 + tig * 2;
            float b0 = bias[col], b1 = bias[col + 1];
            float c0 = acc[mt][nt][0] + b0, c1 = acc[mt][nt][1] + b1;
            float c2 = acc[mt][nt][2] + b0, c3 = acc[mt][nt][3] + b1;
            *reinterpret_cast<__half2*>(outp + (size_t)row0 * halfN + col)       = __floats2half2_rn(c0, c1);
            *reinterpret_cast<__half2*>(outp + (size_t)(row0 + 8) * halfN + col) = __floats2half2_rn(c2, c3);
        }
    }
}

// =================================================================
// Fused edge-feature GEMM + attention logits (K=32, one chunk).
// =================================================================
template <int H>
__global__ __launch_bounds__(256) void k_ee_logits(
    const __half* __restrict__ A, const __half* __restrict__ B,
    const float* __restrict__ att)
{
    __shared__ uint32_t sm[4096];
    int tid = threadIdx.x;
    int wid = tid >> 5, lane = tid & 31;
    int mw = wid & 3, nw = wid >> 2;
    int gid = lane >> 2, tig = lane & 3;
    int rowBase = blockIdx.y * 128, colBase = blockIdx.x * 128;

    float acc[2][8][4];
    #pragma unroll
    for (int mt = 0; mt < 2; mt++)
        #pragma unroll
        for (int nt = 0; nt < 8; nt++)
            #pragma unroll
            for (int q = 0; q < 4; q++) acc[mt][nt][q] = 0.f;

    uint2 pa[4], pb[4];
    ldg_tile<1, 1>(A, B, DEDGE, rowBase, colBase, 0, tid, pa, pb);
    sts_tile(sm, sm + 2048, tid, pa, pb);
    __syncthreads();

    #pragma unroll
    for (int kstep = 0; kstep < 2; kstep++) {
        uint4 afr[2];
        #pragma unroll
        for (int mt = 0; mt < 2; mt++)
            afr[mt] = *reinterpret_cast<const uint4*>(
                sm + (kstep * 8 + mw * 2 + mt) * 128 + lane * 4);
        uint2 bfr[8];
        #pragma unroll
        for (int nt = 0; nt < 8; nt++)
            bfr[nt] = *reinterpret_cast<const uint2*>(
                sm + 2048 + (kstep * 16 + nw * 8 + nt) * 64 + lane * 2);
        #pragma unroll
        for (int mt = 0; mt < 2; mt++)
            #pragma unroll
            for (int nt = 0; nt < 8; nt++)
                mma_f16(acc[mt][nt], afr[mt], bfr[nt]);
    }

    int h = colBase >> 8;
    const int HCH = H * (CC / 2);
    const __half2* xl = reinterpret_cast<const __half2*>(g_xl);
    const __half2* xr = reinterpret_cast<const __half2*>(g_xr);

    #pragma unroll
    for (int mt = 0; mt < 2; mt++) {
        int e0 = rowBase + mw * 32 + mt * 16 + gid;
        int e1 = e0 + 8;
        int s0, d0, s1, d1;
        if (e0 < EE) { s0 = g_src[e0]; d0 = g_dst[e0]; } else { s0 = d0 = e0 - EE; }
        if (e1 < EE) { s1 = g_src[e1]; d1 = g_dst[e1]; } else { s1 = d1 = e1 - EE; }
        float p0 = 0.f, p1 = 0.f;
        #pragma unroll
        for (int nt = 0; nt < 8; nt++) {
            int col = colBase + nw * 64 + nt * 8 + tig * 2;
            int c2i = col >> 1;
            float2 at = *reinterpret_cast<const float2*>(att + h * CC + (col & (CC - 1)));
            float2 a0 = __half22float2(xl[(size_t)s0 * HCH + c2i]);
            float2 b0 = __half22float2(xr[(size_t)d0 * HCH + c2i]);
            float2 a1 = __half22float2(xl[(size_t)s1 * HCH + c2i]);
            float2 b1 = __half22float2(xr[(size_t)d1 * HCH + c2i]);
            float v0 = acc[mt][nt][0] + a0.x + b0.x;
            float v1 = acc[mt][nt][1] + a0.y + b0.y;
            float v2 = acc[mt][nt][2] + a1.x + b1.x;
            float v3 = acc[mt][nt][3] + a1.y + b1.y;
            v0 = (v0 > 0.f) ? v0 : NEG_SLOPE * v0;
            v1 = (v1 > 0.f) ? v1 : NEG_SLOPE * v1;
            v2 = (v2 > 0.f) ? v2 : NEG_SLOPE * v2;
            v3 = (v3 > 0.f) ? v3 : NEG_SLOPE * v3;
            p0 += v0 * at.x + v1 * at.y;
            p1 += v2 * at.x + v3 * at.y;
        }
        p0 += __shfl_xor_sync(0xffffffffu, p0, 1);
        p0 += __shfl_xor_sync(0xffffffffu, p0, 2);
        p1 += __shfl_xor_sync(0xffffffffu, p1, 1);
        p1 += __shfl_xor_sync(0xffffffffu, p1, 2);
        if (tig == 0) {
            atomicAdd(&g_logits[e0 * H + h], p0);
            atomicAdd(&g_logits[e1 * H + h], p1);
        }
    }
}

__global__ void k_zlog(int count) {
    int t = blockIdx.x * blockDim.x + threadIdx.x;
    if (t < count) g_logits[t] = 0.f;
}

// ---------------- weight conversion to fp16 (once per call) ----------------
__global__ void k_wconv(const float* __restrict__ Wl1, const float* __restrict__ Wr1,
                        const float* __restrict__ Wl2, const float* __restrict__ Wr2,
                        const float* __restrict__ We1, const float* __restrict__ We2)
{
    int t = blockIdx.x * blockDim.x + threadIdx.x;
    const int s1 = HC1 * DNODE;     // 131072
    const int s2 = HC2 * HC1;       // 2097152
    const int s3 = HC1 * DEDGE;     // 65536
    const int s4 = HC2 * DEDGE;     // 32768
    if (t < s1) { g_w1h[t] = __float2half_rn(Wl1[t]); g_w1h[s1 + t] = __float2half_rn(Wr1[t]); }
    if (t < s2) { g_w2h[t] = __float2half_rn(Wl2[t]); g_w2h[s2 + t] = __float2half_rn(Wr2[t]); }
    if (t < s3) g_we1h[t] = __float2half_rn(We1[t]);
    if (t < s4) g_we2h[t] = __float2half_rn(We2[t]);
}

// ---------------- index detection / normalization ----------------
__global__ void k_detect(const int* __restrict__ ei) {
    int is64 = 1;
    for (int i = 0; i < 16; i++)
        if (ei[2 * i + 1] != 0) is64 = 0;
    g_is64 = is64;
}
__global__ void k_norm_idx(const int* __restrict__ ei, const int* __restrict__ batch) {
    int t = blockIdx.x * blockDim.x + threadIdx.x;
    int is64 = g_is64;
    if (t < EE) {
        g_src[t] = is64 ? ei[2 * t]        : ei[t];
        g_dst[t] = is64 ? ei[2 * (EE + t)] : ei[EE + t];
    }
    if (t < NN) g_batch[t] = is64 ? batch[2 * t] : batch[t];
}
__global__ void k_zero() {
    int t = blockIdx.x * blockDim.x + threadIdx.x;
    if (t < NN) { g_deg[t] = 0; g_cur[t] = 0; }
    if (t < NN * DEDGE) g_easum[t] = 0.f;
    if (t < GG * HC2) g_pool[t] = 0.f;
    if (t < GG) g_cnt[t] = 0.f;
}
__global__ void k_deg_easum(const float* __restrict__ ea) {
    int t = blockIdx.x * blockDim.x + threadIdx.x;
    if (t >= EE * DEDGE) return;
    int e = t >> 5, d = t & 31;
    int dst = g_dst[e];
    atomicAdd(&g_easum[dst * DEDGE + d], ea[t]);
    if (d == 0) atomicAdd(&g_deg[dst], 1);
}
__global__ void k_ea2(const float* __restrict__ ea) {
    int t = blockIdx.x * blockDim.x + threadIdx.x;
    if (t >= ET * DEDGE) return;
    if (t < EE * DEDGE) {
        g_ea2h[t] = __float2half_rn(ea[t]);
    } else {
        int u = t - EE * DEDGE;
        int n = u >> 5;
        g_ea2h[t] = __float2half_rn(g_easum[u] / fmaxf((float)g_deg[n], 1.f));
    }
}
__global__ void k_scan() {
    __shared__ int part[256];
    int t = threadIdx.x;
    int base = t * 32;
    int loc[32];
    int s = 0;
    #pragma unroll
    for (int i = 0; i < 32; i++) { loc[i] = s; s += g_deg[base + i] + 1; }
    part[t] = s;
    __syncthreads();
    if (t == 0) {
        int acc = 0;
        for (int i = 0; i < 256; i++) { int v = part[i]; part[i] = acc; acc += v; }
        g_off[NN] = acc;
    }
    __syncthreads();
    int p = part[t];
    #pragma unroll
    for (int i = 0; i < 32; i++) g_off[base + i] = p + loc[i];
}
__global__ void k_csr() {
    int e = blockIdx.x * blockDim.x + threadIdx.x;
    if (e >= ET) return;
    int node = (e < EE) ? g_dst[e] : (e - EE);
    int pos = g_off[node] + atomicAdd(&g_cur[node], 1);
    g_csr[pos] = e;
}

// ---------------- fp32 SGEMM for the tiny MLP (M=64) ----------------
__global__ __launch_bounds__(256) void k_sgemm(
    const float* __restrict__ A, const float* __restrict__ Bm,
    const float* __restrict__ bias, float* __restrict__ Cm,
    int M, int Nc, int K, int act)
{
    constexpr int BM = 128, BN = 128, BK = 16, TM = 8, TN = 8;
    __shared__ float As[BK][BM];
    __shared__ float Bs[BK][BN];
    int tid = threadIdx.x;
    int tx = tid % 16, ty = tid / 16;
    int rowBase = blockIdx.y * BM;
    int colBase = blockIdx.x * BN;
    float acc[TM][TN];
    #pragma unroll
    for (int i = 0; i < TM; i++)
        #pragma unroll
        for (int j = 0; j < TN; j++) acc[i][j] = 0.f;
    for (int k0 = 0; k0 < K; k0 += BK) {
        #pragma unroll
        for (int i = 0; i < 2; i++) {
            int f4 = tid + i * 256;
            int r = f4 >> 2;
            int kk = (f4 & 3) * 4;
            int gr = rowBase + r;
            float4 v = make_float4(0.f, 0.f, 0.f, 0.f);
            if (gr < M) v = *reinterpret_cast<const float4*>(A + (size_t)gr * K + k0 + kk);
            As[kk + 0][r] = v.x; As[kk + 1][r] = v.y; As[kk + 2][r] = v.z; As[kk + 3][r] = v.w;
            int gc = colBase + r;
            float4 w = make_float4(0.f, 0.f, 0.f, 0.f);
            if (gc < Nc) w = *reinterpret_cast<const float4*>(Bm + (size_t)gc * K + k0 + kk);
            Bs[kk + 0][r] = w.x; Bs[kk + 1][r] = w.y; Bs[kk + 2][r] = w.z; Bs[kk + 3][r] = w.w;
        }
        __syncthreads();
        #pragma unroll
        for (int k = 0; k < BK; k++) {
            float a[TM], b[TN];
            #pragma unroll
            for (int i = 0; i < TM; i++) a[i] = As[k][ty * TM + i];
            #pragma unroll
            for (int j = 0; j < TN; j++) b[j] = Bs[k][tx * TN + j];
            #pragma unroll
            for (int i = 0; i < TM; i++)
                #pragma unroll
                for (int j = 0; j < TN; j++) acc[i][j] = fmaf(a[i], b[j], acc[i][j]);
        }
        __syncthreads();
    }
    #pragma unroll
    for (int i = 0; i < TM; i++) {
        int gr = rowBase + ty * TM + i;
        if (gr >= M) continue;
        #pragma unroll
        for (int j = 0; j < TN; j++) {
            int gc = colBase + tx * TN + j;
            if (gc >= Nc) continue;
            float v = acc[i][j];
            if (bias) v += bias[gc];
            if (act) v = fmaxf(v, 0.f);
            Cm[(size_t)gr * Nc + gc] = v;
        }
    }
}

// ---------------- segment softmax + weighted gather (CSR) ----------------
template <int H, int RELU, int OUTH>
__global__ void k_aggregate(const float* __restrict__ bias, void* __restrict__ out) {
    int n = blockIdx.x;
    int h = threadIdx.x >> 5, lane = threadIdx.x & 31;
    int s0 = g_off[n], s1 = g_off[n + 1];
    float mx = -1e30f;
    for (int i = s0 + lane; i < s1; i += 32) mx = fmaxf(mx, g_logits[g_csr[i] * H + h]);
    mx = warp_max(mx);
    float den = 0.f;
    for (int i = s0 + lane; i < s1; i += 32) den += __expf(g_logits[g_csr[i] * H + h] - mx);
    den = warp_sum(den);
    float inv = 1.f / den;
    const int HCH = H * (CC / 2);
    const __half2* xl = reinterpret_cast<const __half2*>(g_xl);
    float2 acc[4];
    #pragma unroll
    for (int j = 0; j < 4; j++) acc[j] = make_float2(0.f, 0.f);
    for (int i = s0; i < s1; i++) {
        int e = g_csr[i];
        float w = __expf(g_logits[e * H + h] - mx) * inv;
        int s = (e < EE) ? g_src[e] : (e - EE);
        const __half2* row = xl + (size_t)s * HCH + h * 128 + lane;
        #pragma unroll
        for (int j = 0; j < 4; j++) {
            float2 f = __half22float2(row[32 * j]);
            acc[j].x = fmaf(w, f.x, acc[j].x);
            acc[j].y = fmaf(w, f.y, acc[j].y);
        }
    }
    #pragma unroll
    for (int j = 0; j < 4; j++) {
        int col = h * CC + 2 * (lane + 32 * j);
        float2 b = *reinterpret_cast<const float2*>(bias + col);
        float v0 = acc[j].x + b.x, v1 = acc[j].y + b.y;
        if (RELU) { v0 = fmaxf(v0, 0.f); v1 = fmaxf(v1, 0.f); }
        if (OUTH) {
            __half* oh = (__half*)out;
            *reinterpret_cast<__half2*>(oh + (size_t)n * (H * CC) + col) = __floats2half2_rn(v0, v1);
        } else {
            float* of = (float*)out;
            *reinterpret_cast<float2*>(of + (size_t)n * (H * CC) + col) = make_float2(v0, v1);
        }
    }
}

// ---------------- pooling + final ----------------
__global__ void k_pool() {
    int t = blockIdx.x * blockDim.x + threadIdx.x;
    if (t >= NN * HC2) return;
    int n = t >> 10, c = t & 1023;
    int b = g_batch[n];
    atomicAdd(&g_pool[b * HC2 + c], g_h2[t]);
    if (c == 0) atomicAdd(&g_cnt[b], 1.f);
}
__global__ void k_pool_div() {
    int t = blockIdx.x * blockDim.x + threadIdx.x;
    if (t >= GG * HC2) return;
    g_pool[t] /= fmaxf(g_cnt[t >> 10], 1.f);
}
__global__ void k_final(const float* __restrict__ W3, const float* __restrict__ b3,
                        float* __restrict__ out) {
    int g = blockIdx.x, lane = threadIdx.x;
    float acc = 0.f;
    #pragma unroll
    for (int j = 0; j < 8; j++) acc += g_m2[g * 256 + lane + 32 * j] * W3[lane + 32 * j];
    acc = warp_sum(acc);
    if (lane == 0) out[g] = 1.f / (1.f + expf(-(acc + b3[0])));
}

// ---------------- host launch ----------------
static inline void launch_sgemm(const float* A, const float* B, const float* bias,
                                float* C, int M, int Nc, int K, int act) {
    dim3 grid((Nc + 127) / 128, (M + 127) / 128);
    k_sgemm<<<grid, 256>>>(A, B, bias, C, M, Nc, K, act);
}

extern "C" void kernel_launch(void* const* d_in, const int* in_sizes, int n_in,
                              void* d_out, int out_size) {
    const float* x     = (const float*)d_in[0];
    const int*   ei    = (const int*)  d_in[1];
    const float* ea    = (const float*)d_in[2];
    const int*   batch = (const int*)  d_in[3];
    const float* Wl1 = (const float*)d_in[4],  *bl1 = (const float*)d_in[5];
    const float* Wr1 = (const float*)d_in[6],  *br1 = (const float*)d_in[7];
    const float* We1 = (const float*)d_in[8],  *att1 = (const float*)d_in[9];
    const float* bias1 = (const float*)d_in[10];
    const float* Wl2 = (const float*)d_in[11], *bl2 = (const float*)d_in[12];
    const float* Wr2 = (const float*)d_in[13], *br2 = (const float*)d_in[14];
    const float* We2 = (const float*)d_in[15], *att2 = (const float*)d_in[16];
    const float* bias2 = (const float*)d_in[17];
    const float* W1 = (const float*)d_in[18], *b1 = (const float*)d_in[19];
    const float* W2 = (const float*)d_in[20], *b2 = (const float*)d_in[21];
    const float* W3 = (const float*)d_in[22], *b3 = (const float*)d_in[23];
    float* out = (float*)d_out;

    float *p_h2, *p_pool, *p_m1, *p_m2;
    __half *p_xl, *p_xr, *p_h1h, *p_ea2h, *p_w1h, *p_w2h, *p_we1h, *p_we2h;
    cudaGetSymbolAddress((void**)&p_xl,    g_xl);
    cudaGetSymbolAddress((void**)&p_xr,    g_xr);
    cudaGetSymbolAddress((void**)&p_h1h,   g_h1h);
    cudaGetSymbolAddress((void**)&p_ea2h,  g_ea2h);
    cudaGetSymbolAddress((void**)&p_w1h,   g_w1h);
    cudaGetSymbolAddress((void**)&p_w2h,   g_w2h);
    cudaGetSymbolAddress((void**)&p_we1h,  g_we1h);
    cudaGetSymbolAddress((void**)&p_we2h,  g_we2h);
    cudaGetSymbolAddress((void**)&p_h2,    g_h2);
    cudaGetSymbolAddress((void**)&p_pool,  g_pool);
    cudaGetSymbolAddress((void**)&p_m1,    g_m1);
    cudaGetSymbolAddress((void**)&p_m2,    g_m2);

    // --- graph preprocessing + weight conversion ---
    k_detect<<<1, 1>>>(ei);
    k_norm_idx<<<(EE + 255) / 256, 256>>>(ei, batch);
    k_zero<<<(NN * DEDGE + 255) / 256, 256>>>();
    k_wconv<<<(HC2 * HC1 + 255) / 256, 256>>>(Wl1, Wr1, Wl2, Wr2, We1, We2);
    k_deg_easum<<<(EE * DEDGE + 255) / 256, 256>>>(ea);
    k_ea2<<<(ET * DEDGE + 255) / 256, 256>>>(ea);
    k_scan<<<1, 256>>>();
    k_csr<<<(ET + 255) / 256, 256>>>();

    // --- GATv2 layer 1: fused xl|xr GEMM (N = 2*HC1 = 4096) ---
    k_zlog<<<(ET * H1C + 255) / 256, 256>>>(ET * H1C);
    k_mma_dual<0><<<dim3(2 * HC1 / 128, NN / 128), 256, MMA_SMEM_BYTES>>>(
        x, p_w1h, bl1, br1, p_xl, p_xr, NN, 2 * HC1, DNODE);
    k_ee_logits<H1C><<<dim3(HC1 / 128, ET / 128), 256>>>(p_ea2h, p_we1h, att1);
    k_aggregate<H1C, 1, 1><<<NN, H1C * 32>>>(bias1, p_h1h);

    // --- GATv2 layer 2: fused xl|xr GEMM (N = 2*HC2 = 2048) ---
    k_zlog<<<(ET * H2C + 255) / 256, 256>>>(ET * H2C);
    k_mma_dual<1><<<dim3(2 * HC2 / 128, NN / 128), 256, MMA_SMEM_BYTES>>>(
        p_h1h, p_w2h, bl2, br2, p_xl, p_xr, NN, 2 * HC2, HC1);
    k_ee_logits<H2C><<<dim3(HC2 / 128, ET / 128), 256>>>(p_ea2h, p_we2h, att2);
    k_aggregate<H2C, 0, 0><<<NN, H2C * 32>>>(bias2, p_h2);

    // --- pool + MLP ---
    k_pool<<<(NN * HC2 + 255) / 256, 256>>>();
    k_pool_div<<<(GG * HC2 + 255) / 256, 256>>>();
    launch_sgemm(p_pool, W1, b1, p_m1, GG, 512, HC2, 1);
    launch_sgemm(p_m1,  W2, b2, p_m2, GG, 256, 512, 1);
    k_final<<<GG, 32>>>(W3, b3, out);
}

// round 7
// speedup vs baseline: 3.9926x; 1.1346x over previous
#include <cuda_runtime.h>
#include <cuda_fp16.h>
#include <math.h>
#include <stdint.h>

// ---------------- problem constants ----------------
#define NN   8192
#define EE   65536
#define GG   64
#define DNODE 64
#define DEDGE 32
#define CC   256
#define H1C  8
#define H2C  4
#define ET   (EE + NN)          // 73728 = 576*128
#define HC1  (H1C * CC)         // 2048
#define HC2  (H2C * CC)         // 1024
#define NEG_SLOPE 0.2f

// ---------------- device scratch ----------------
__device__ int    g_is64;
__device__ int    g_src[EE];
__device__ int    g_dst[EE];
__device__ int    g_batch[NN];
__device__ int    g_deg[NN];
__device__ int    g_cur[NN];
__device__ int    g_off[NN + 1];
__device__ int    g_csr[ET];
__device__ float  g_easum[NN * DEDGE];
__device__ __half g_ea2h[ET * DEDGE];
__device__ __half g_xh[NN * DNODE];          // fp16 copy of x
__device__ __half g_xl[NN * HC1];
__device__ __half g_xr[NN * HC1];
__device__ __half g_h1h[NN * HC1];
__device__ float  g_logits[ET * H1C];
__device__ float  g_h2[NN * HC2];
__device__ float  g_pool[GG * HC2];
__device__ float  g_cnt[GG];
__device__ float  g_m1[GG * 512];
__device__ float  g_m2[GG * 256];
// fp16 weights (converted once per call)
__device__ __half g_w1h[2 * HC1 * DNODE];    // [Wl1; Wr1]  (4096 x 64)
__device__ __half g_w2h[2 * HC2 * HC1];      // [Wl2; Wr2]  (2048 x 2048)
__device__ __half g_we1h[HC1 * DEDGE];
__device__ __half g_we2h[HC2 * DEDGE];

// ---------------- helpers ----------------
__device__ __forceinline__ float warp_sum(float v) {
    #pragma unroll
    for (int o = 16; o; o >>= 1) v += __shfl_xor_sync(0xffffffffu, v, o);
    return v;
}
__device__ __forceinline__ float warp_max(float v) {
    #pragma unroll
    for (int o = 16; o; o >>= 1) v = fmaxf(v, __shfl_xor_sync(0xffffffffu, v, o));
    return v;
}
__device__ __forceinline__ uint32_t pack_h2(float x, float y) {
    __half2 h = __floats2half2_rn(x, y);
    return *reinterpret_cast<uint32_t*>(&h);
}
__device__ __forceinline__ uint32_t smem_u32(const void* p) {
    uint32_t a;
    asm("{ .reg .u64 t; cvta.to.shared.u64 t, %1; cvt.u32.u64 %0, t; }" : "=r"(a) : "l"(p));
    return a;
}
__device__ __forceinline__ void mma_f16(float* c, uint4 a, uint2 b) {
    asm volatile(
        "mma.sync.aligned.m16n8k16.row.col.f32.f16.f16.f32 "
        "{%0,%1,%2,%3},{%4,%5,%6,%7},{%8,%9},{%0,%1,%2,%3};"
        : "+f"(c[0]), "+f"(c[1]), "+f"(c[2]), "+f"(c[3])
        : "r"(a.x), "r"(a.y), "r"(a.z), "r"(a.w), "r"(b.x), "r"(b.y));
}
__device__ __forceinline__ uint4 ldsm4(uint32_t addr) {
    uint4 r;
    asm volatile("ldmatrix.sync.aligned.m8n8.x4.shared.b16 {%0,%1,%2,%3}, [%4];"
        : "=r"(r.x), "=r"(r.y), "=r"(r.z), "=r"(r.w) : "r"(addr));
    return r;
}
__device__ __forceinline__ void cp16(uint32_t dst, const void* src) {
    asm volatile("cp.async.cg.shared.global [%0], [%1], 16;" :: "r"(dst), "l"(src));
}

// =================================================================
// cp.async + ldmatrix fp16 GEMM.
// CTA tile 128x128, BK=64 (128B rows), XOR-swizzled smem, 3 stages.
// 8 warps (4 M x 2 N), warp tile 32x64.
// Stage: A 16KB + B 16KB = 32KB; total dynamic smem 96KB.
// =================================================================
#define GEMM_STAGE_BYTES 32768
#define GEMM_SMEM_BYTES  (3 * GEMM_STAGE_BYTES)

__device__ __forceinline__ void issue_stage(
    const __half* __restrict__ A, const __half* __restrict__ B, int K,
    int rowBase, int colBase, int k0, uint32_t abase, int tid)
{
    #pragma unroll
    for (int i = 0; i < 4; i++) {
        int id = i * 256 + tid;           // 0..1023
        int r = id >> 3, c = id & 7;
        uint32_t off = (uint32_t)(r * 128 + ((c ^ (r & 7)) << 4));
        cp16(abase + off,         A + (size_t)(rowBase + r) * K + k0 + c * 8);
        cp16(abase + 16384 + off, B + (size_t)(colBase + r) * K + k0 + c * 8);
    }
    asm volatile("cp.async.commit_group;" ::: "memory");
}

// dual-output GEMM: C = A @ [BL;BR]^T ; columns [0,N/2)->outL, [N/2,N)->outR
__global__ __launch_bounds__(256, 2) void k_mma_dual(
    const __half* __restrict__ A, const __half* __restrict__ B,
    const float* __restrict__ biasL, const float* __restrict__ biasR,
    __half* __restrict__ outL, __half* __restrict__ outR,
    int M, int N, int K)
{
    extern __shared__ char smem[];
    uint32_t sb = smem_u32(smem);
    int tid = threadIdx.x;
    int wid = tid >> 5, lane = tid & 31;
    int mw = wid & 3, nw = wid >> 2;
    int gid = lane >> 2, tig = lane & 3;
    int rowBase = blockIdx.y * 128, colBase = blockIdx.x * 128;

    float acc[2][8][4];
    #pragma unroll
    for (int mt = 0; mt < 2; mt++)
        #pragma unroll
        for (int nt = 0; nt < 8; nt++)
            #pragma unroll
            for (int q = 0; q < 4; q++) acc[mt][nt][q] = 0.f;

    const int NCH = K >> 6;               // 64-K chunks
    issue_stage(A, B, K, rowBase, colBase, 0, sb, tid);
    if (NCH > 1) issue_stage(A, B, K, rowBase, colBase, 64, sb + GEMM_STAGE_BYTES, tid);

    // per-lane ldmatrix row/chunk components (stage-independent)
    int arow = mw * 32 + (lane & 15);            // + mt*16
    int achoff = lane >> 4;                      // 0/1
    int brow = nw * 64 + ((lane >> 4) << 3) + (lane & 7);   // + ntp*16
    int bchoff = (lane >> 3) & 1;

    for (int c = 0; c < NCH; c++) {
        if (c + 2 <= NCH) asm volatile("cp.async.wait_group 1;" ::: "memory");
        else              asm volatile("cp.async.wait_group 0;" ::: "memory");
        __syncthreads();
        if (c + 2 < NCH)
            issue_stage(A, B, K, rowBase, colBase, (c + 2) << 6,
                        sb + ((c + 2) % 3) * GEMM_STAGE_BYTES, tid);

        uint32_t Ab = sb + (c % 3) * GEMM_STAGE_BYTES;
        uint32_t Bb = Ab + 16384;
        #pragma unroll
        for (int kstep = 0; kstep < 4; kstep++) {
            uint4 afr[2];
            #pragma unroll
            for (int mt = 0; mt < 2; mt++) {
                int row = arow + mt * 16;
                int ch = kstep * 2 + achoff;
                afr[mt] = ldsm4(Ab + row * 128 + ((ch ^ (row & 7)) << 4));
            }
            uint2 bfr[8];
            #pragma unroll
            for (int ntp = 0; ntp < 4; ntp++) {
                int row = brow + ntp * 16;
                int ch = kstep * 2 + bchoff;
                uint4 t = ldsm4(Bb + row * 128 + ((ch ^ (row & 7)) << 4));
                bfr[2 * ntp]     = make_uint2(t.x, t.y);
                bfr[2 * ntp + 1] = make_uint2(t.z, t.w);
            }
            #pragma unroll
            for (int mt = 0; mt < 2; mt++)
                #pragma unroll
                for (int nt = 0; nt < 8; nt++)
                    mma_f16(acc[mt][nt], afr[mt], bfr[nt]);
        }
    }

    // ---- epilogue: select side ----
    int halfN = N >> 1;
    bool isR = (colBase >= halfN);
    const float* bias = isR ? biasR : biasL;
    __half* outp = isR ? outR : outL;
    int cb = colBase - (isR ? halfN : 0);

    #pragma unroll
    for (int mt = 0; mt < 2; mt++) {
        int row0 = rowBase + mw * 32 + mt * 16 + gid;
        #pragma unroll
        for (int nt = 0; nt < 8; nt++) {
            int col = cb + nw * 64 + nt * 8 + tig * 2;
            float b0 = bias[col], b1 = bias[col + 1];
            float c0 = acc[mt][nt][0] + b0, c1 = acc[mt][nt][1] + b1;
            float c2 = acc[mt][nt][2] + b0, c3 = acc[mt][nt][3] + b1;
            *reinterpret_cast<__half2*>(outp + (size_t)row0 * halfN + col)       = __floats2half2_rn(c0, c1);
            *reinterpret_cast<__half2*>(outp + (size_t)(row0 + 8) * halfN + col) = __floats2half2_rn(c2, c3);
        }
    }
}

// =================================================================
// Fused edge-feature GEMM + attention logits (K=32) — proven R5 path.
// =================================================================
__device__ __forceinline__ void ldg_tile_h(
    const __half* __restrict__ A, const __half* __restrict__ B, int K,
    int rowBase, int colBase, int kc, int tid, uint2* pa, uint2* pb)
{
    #pragma unroll
    for (int i = 0; i < 4; i++) {
        int id = i * 256 + tid;
        int r = id >> 3, c4 = id & 7;
        pa[i] = *reinterpret_cast<const uint2*>(A + (size_t)(rowBase + r) * K + kc + c4 * 4);
        pb[i] = *reinterpret_cast<const uint2*>(B + (size_t)(colBase + r) * K + kc + c4 * 4);
    }
}
__device__ __forceinline__ void sts_tile(
    uint32_t* __restrict__ sA, uint32_t* __restrict__ sB,
    int tid, const uint2* pa, const uint2* pb)
{
    #pragma unroll
    for (int i = 0; i < 4; i++) {
        int id = i * 256 + tid;
        int r = id >> 3, c4 = id & 7;
        int kstep = c4 >> 2;
        int pl = (c4 & 3) * 2;
        int mtile = r >> 4, ri = r & 15;
        int regA = ((pl & 4) ? 2 : 0) + (ri >> 3);
        int laneA = (ri & 7) * 4 + (pl & 3);
        int baseA = (kstep * 8 + mtile) * 128;
        sA[baseA + laneA * 4 + regA]       = pa[i].x;
        sA[baseA + (laneA + 1) * 4 + regA] = pa[i].y;
        int ntile = r >> 3, ni = r & 7;
        int regB = (pl & 4) ? 1 : 0;
        int laneB = ni * 4 + (pl & 3);
        int baseB = (kstep * 16 + ntile) * 64;
        sB[baseB + laneB * 2 + regB]       = pb[i].x;
        sB[baseB + (laneB + 1) * 2 + regB] = pb[i].y;
    }
}

template <int H>
__global__ __launch_bounds__(256) void k_ee_logits(
    const __half* __restrict__ A, const __half* __restrict__ B,
    const float* __restrict__ att)
{
    __shared__ uint32_t sm[4096];
    int tid = threadIdx.x;
    int wid = tid >> 5, lane = tid & 31;
    int mw = wid & 3, nw = wid >> 2;
    int gid = lane >> 2, tig = lane & 3;
    int rowBase = blockIdx.y * 128, colBase = blockIdx.x * 128;

    float acc[2][8][4];
    #pragma unroll
    for (int mt = 0; mt < 2; mt++)
        #pragma unroll
        for (int nt = 0; nt < 8; nt++)
            #pragma unroll
            for (int q = 0; q < 4; q++) acc[mt][nt][q] = 0.f;

    uint2 pa[4], pb[4];
    ldg_tile_h(A, B, DEDGE, rowBase, colBase, 0, tid, pa, pb);
    sts_tile(sm, sm + 2048, tid, pa, pb);
    __syncthreads();

    #pragma unroll
    for (int kstep = 0; kstep < 2; kstep++) {
        uint4 afr[2];
        #pragma unroll
        for (int mt = 0; mt < 2; mt++)
            afr[mt] = *reinterpret_cast<const uint4*>(
                sm + (kstep * 8 + mw * 2 + mt) * 128 + lane * 4);
        uint2 bfr[8];
        #pragma unroll
        for (int nt = 0; nt < 8; nt++)
            bfr[nt] = *reinterpret_cast<const uint2*>(
                sm + 2048 + (kstep * 16 + nw * 8 + nt) * 64 + lane * 2);
        #pragma unroll
        for (int mt = 0; mt < 2; mt++)
            #pragma unroll
            for (int nt = 0; nt < 8; nt++)
                mma_f16(acc[mt][nt], afr[mt], bfr[nt]);
    }

    int h = colBase >> 8;
    const int HCH = H * (CC / 2);
    const __half2* xl = reinterpret_cast<const __half2*>(g_xl);
    const __half2* xr = reinterpret_cast<const __half2*>(g_xr);

    #pragma unroll
    for (int mt = 0; mt < 2; mt++) {
        int e0 = rowBase + mw * 32 + mt * 16 + gid;
        int e1 = e0 + 8;
        int s0, d0, s1, d1;
        if (e0 < EE) { s0 = g_src[e0]; d0 = g_dst[e0]; } else { s0 = d0 = e0 - EE; }
        if (e1 < EE) { s1 = g_src[e1]; d1 = g_dst[e1]; } else { s1 = d1 = e1 - EE; }
        float p0 = 0.f, p1 = 0.f;
        #pragma unroll
        for (int nt = 0; nt < 8; nt++) {
            int col = colBase + nw * 64 + nt * 8 + tig * 2;
            int c2i = col >> 1;
            float2 at = *reinterpret_cast<const float2*>(att + h * CC + (col & (CC - 1)));
            float2 a0 = __half22float2(xl[(size_t)s0 * HCH + c2i]);
            float2 b0 = __half22float2(xr[(size_t)d0 * HCH + c2i]);
            float2 a1 = __half22float2(xl[(size_t)s1 * HCH + c2i]);
            float2 b1 = __half22float2(xr[(size_t)d1 * HCH + c2i]);
            float v0 = acc[mt][nt][0] + a0.x + b0.x;
            float v1 = acc[mt][nt][1] + a0.y + b0.y;
            float v2 = acc[mt][nt][2] + a1.x + b1.x;
            float v3 = acc[mt][nt][3] + a1.y + b1.y;
            v0 = (v0 > 0.f) ? v0 : NEG_SLOPE * v0;
            v1 = (v1 > 0.f) ? v1 : NEG_SLOPE * v1;
            v2 = (v2 > 0.f) ? v2 : NEG_SLOPE * v2;
            v3 = (v3 > 0.f) ? v3 : NEG_SLOPE * v3;
            p0 += v0 * at.x + v1 * at.y;
            p1 += v2 * at.x + v3 * at.y;
        }
        p0 += __shfl_xor_sync(0xffffffffu, p0, 1);
        p0 += __shfl_xor_sync(0xffffffffu, p0, 2);
        p1 += __shfl_xor_sync(0xffffffffu, p1, 1);
        p1 += __shfl_xor_sync(0xffffffffu, p1, 2);
        if (tig == 0) {
            atomicAdd(&g_logits[e0 * H + h], p0);
            atomicAdd(&g_logits[e1 * H + h], p1);
        }
    }
}

__global__ void k_zlog(int count) {
    int t = blockIdx.x * blockDim.x + threadIdx.x;
    if (t < count) g_logits[t] = 0.f;
}

// ---------------- weight / input conversion to fp16 ----------------
__global__ void k_wconv(const float* __restrict__ Wl1, const float* __restrict__ Wr1,
                        const float* __restrict__ Wl2, const float* __restrict__ Wr2,
                        const float* __restrict__ We1, const float* __restrict__ We2,
                        const float* __restrict__ x)
{
    int t = blockIdx.x * blockDim.x + threadIdx.x;
    const int s1 = HC1 * DNODE;
    const int s2 = HC2 * HC1;
    const int s3 = HC1 * DEDGE;
    const int s4 = HC2 * DEDGE;
    if (t < s1) { g_w1h[t] = __float2half_rn(Wl1[t]); g_w1h[s1 + t] = __float2half_rn(Wr1[t]); }
    if (t < s2) { g_w2h[t] = __float2half_rn(Wl2[t]); g_w2h[s2 + t] = __float2half_rn(Wr2[t]); }
    if (t < s3) g_we1h[t] = __float2half_rn(We1[t]);
    if (t < s4) g_we2h[t] = __float2half_rn(We2[t]);
    if (t < NN * DNODE) g_xh[t] = __float2half_rn(x[t]);
}

// ---------------- index detection / normalization ----------------
__global__ void k_detect(const int* __restrict__ ei) {
    int is64 = 1;
    for (int i = 0; i < 16; i++)
        if (ei[2 * i + 1] != 0) is64 = 0;
    g_is64 = is64;
}
__global__ void k_norm_idx(const int* __restrict__ ei, const int* __restrict__ batch) {
    int t = blockIdx.x * blockDim.x + threadIdx.x;
    int is64 = g_is64;
    if (t < EE) {
        g_src[t] = is64 ? ei[2 * t]        : ei[t];
        g_dst[t] = is64 ? ei[2 * (EE + t)] : ei[EE + t];
    }
    if (t < NN) g_batch[t] = is64 ? batch[2 * t] : batch[t];
}
__global__ void k_zero() {
    int t = blockIdx.x * blockDim.x + threadIdx.x;
    if (t < NN) { g_deg[t] = 0; g_cur[t] = 0; }
    if (t < NN * DEDGE) g_easum[t] = 0.f;
    if (t < GG * HC2) g_pool[t] = 0.f;
    if (t < GG) g_cnt[t] = 0.f;
}
__global__ void k_deg_easum(const float* __restrict__ ea) {
    int t = blockIdx.x * blockDim.x + threadIdx.x;
    if (t >= EE * DEDGE) return;
    int e = t >> 5, d = t & 31;
    int dst = g_dst[e];
    atomicAdd(&g_easum[dst * DEDGE + d], ea[t]);
    if (d == 0) atomicAdd(&g_deg[dst], 1);
}
__global__ void k_ea2(const float* __restrict__ ea) {
    int t = blockIdx.x * blockDim.x + threadIdx.x;
    if (t >= ET * DEDGE) return;
    if (t < EE * DEDGE) {
        g_ea2h[t] = __float2half_rn(ea[t]);
    } else {
        int u = t - EE * DEDGE;
        int n = u >> 5;
        g_ea2h[t] = __float2half_rn(g_easum[u] / fmaxf((float)g_deg[n], 1.f));
    }
}
__global__ void k_scan() {
    __shared__ int part[256];
    int t = threadIdx.x;
    int base = t * 32;
    int loc[32];
    int s = 0;
    #pragma unroll
    for (int i = 0; i < 32; i++) { loc[i] = s; s += g_deg[base + i] + 1; }
    part[t] = s;
    __syncthreads();
    if (t == 0) {
        int acc = 0;
        for (int i = 0; i < 256; i++) { int v = part[i]; part[i] = acc; acc += v; }
        g_off[NN] = acc;
    }
    __syncthreads();
    int p = part[t];
    #pragma unroll
    for (int i = 0; i < 32; i++) g_off[base + i] = p + loc[i];
}
__global__ void k_csr() {
    int e = blockIdx.x * blockDim.x + threadIdx.x;
    if (e >= ET) return;
    int node = (e < EE) ? g_dst[e] : (e - EE);
    int pos = g_off[node] + atomicAdd(&g_cur[node], 1);
    g_csr[pos] = e;
}

// ---------------- fp32 SGEMM for the tiny MLP (M=64) ----------------
__global__ __launch_bounds__(256) void k_sgemm(
    const float* __restrict__ A, const float* __restrict__ Bm,
    const float* __restrict__ bias, float* __restrict__ Cm,
    int M, int Nc, int K, int act)
{
    constexpr int BM = 128, BN = 128, BK = 16, TM = 8, TN = 8;
    __shared__ float As[BK][BM];
    __shared__ float Bs[BK][BN];
    int tid = threadIdx.x;
    int tx = tid % 16, ty = tid / 16;
    int rowBase = blockIdx.y * BM;
    int colBase = blockIdx.x * BN;
    float acc[TM][TN];
    #pragma unroll
    for (int i = 0; i < TM; i++)
        #pragma unroll
        for (int j = 0; j < TN; j++) acc[i][j] = 0.f;
    for (int k0 = 0; k0 < K; k0 += BK) {
        #pragma unroll
        for (int i = 0; i < 2; i++) {
            int f4 = tid + i * 256;
            int r = f4 >> 2;
            int kk = (f4 & 3) * 4;
            int gr = rowBase + r;
            float4 v = make_float4(0.f, 0.f, 0.f, 0.f);
            if (gr < M) v = *reinterpret_cast<const float4*>(A + (size_t)gr * K + k0 + kk);
            As[kk + 0][r] = v.x; As[kk + 1][r] = v.y; As[kk + 2][r] = v.z; As[kk + 3][r] = v.w;
            int gc = colBase + r;
            float4 w = make_float4(0.f, 0.f, 0.f, 0.f);
            if (gc < Nc) w = *reinterpret_cast<const float4*>(Bm + (size_t)gc * K + k0 + kk);
            Bs[kk + 0][r] = w.x; Bs[kk + 1][r] = w.y; Bs[kk + 2][r] = w.z; Bs[kk + 3][r] = w.w;
        }
        __syncthreads();
        #pragma unroll
        for (int k = 0; k < BK; k++) {
            float a[TM], b[TN];
            #pragma unroll
            for (int i = 0; i < TM; i++) a[i] = As[k][ty * TM + i];
            #pragma unroll
            for (int j = 0; j < TN; j++) b[j] = Bs[k][tx * TN + j];
            #pragma unroll
            for (int i = 0; i < TM; i++)
                #pragma unroll
                for (int j = 0; j < TN; j++) acc[i][j] = fmaf(a[i], b[j], acc[i][j]);
        }
        __syncthreads();
    }
    #pragma unroll
    for (int i = 0; i < TM; i++) {
        int gr = rowBase + ty * TM + i;
        if (gr >= M) continue;
        #pragma unroll
        for (int j = 0; j < TN; j++) {
            int gc = colBase + tx * TN + j;
            if (gc >= Nc) continue;
            float v = acc[i][j];
            if (bias) v += bias[gc];
            if (act) v = fmaxf(v, 0.f);
            Cm[(size_t)gr * Nc + gc] = v;
        }
    }
}

// ---------------- segment softmax + weighted gather (CSR) ----------------
template <int H, int RELU, int OUTH>
__global__ void k_aggregate(const float* __restrict__ bias, void* __restrict__ out) {
    int n = blockIdx.x;
    int h = threadIdx.x >> 5, lane = threadIdx.x & 31;
    int s0 = g_off[n], s1 = g_off[n + 1];
    float mx = -1e30f;
    for (int i = s0 + lane; i < s1; i += 32) mx = fmaxf(mx, g_logits[g_csr[i] * H + h]);
    mx = warp_max(mx);
    float den = 0.f;
    for (int i = s0 + lane; i < s1; i += 32) den += __expf(g_logits[g_csr[i] * H + h] - mx);
    den = warp_sum(den);
    float inv = 1.f / den;
    const int HCH = H * (CC / 2);
    const __half2* xl = reinterpret_cast<const __half2*>(g_xl);
    float2 acc[4];
    #pragma unroll
    for (int j = 0; j < 4; j++) acc[j] = make_float2(0.f, 0.f);
    for (int i = s0; i < s1; i++) {
        int e = g_csr[i];
        float w = __expf(g_logits[e * H + h] - mx) * inv;
        int s = (e < EE) ? g_src[e] : (e - EE);
        const __half2* row = xl + (size_t)s * HCH + h * 128 + lane;
        #pragma unroll
        for (int j = 0; j < 4; j++) {
            float2 f = __half22float2(row[32 * j]);
            acc[j].x = fmaf(w, f.x, acc[j].x);
            acc[j].y = fmaf(w, f.y, acc[j].y);
        }
    }
    #pragma unroll
    for (int j = 0; j < 4; j++) {
        int col = h * CC + 2 * (lane + 32 * j);
        float2 b = *reinterpret_cast<const float2*>(bias + col);
        float v0 = acc[j].x + b.x, v1 = acc[j].y + b.y;
        if (RELU) { v0 = fmaxf(v0, 0.f); v1 = fmaxf(v1, 0.f); }
        if (OUTH) {
            __half* oh = (__half*)out;
            *reinterpret_cast<__half2*>(oh + (size_t)n * (H * CC) + col) = __floats2half2_rn(v0, v1);
        } else {
            float* of = (float*)out;
            *reinterpret_cast<float2*>(of + (size_t)n * (H * CC) + col) = make_float2(v0, v1);
        }
    }
}

// ---------------- pooling + final ----------------
__global__ void k_pool() {
    int t = blockIdx.x * blockDim.x + threadIdx.x;
    if (t >= NN * HC2) return;
    int n = t >> 10, c = t & 1023;
    int b = g_batch[n];
    atomicAdd(&g_pool[b * HC2 + c], g_h2[t]);
    if (c == 0) atomicAdd(&g_cnt[b], 1.f);
}
__global__ void k_pool_div() {
    int t = blockIdx.x * blockDim.x + threadIdx.x;
    if (t >= GG * HC2) return;
    g_pool[t] /= fmaxf(g_cnt[t >> 10], 1.f);
}
__global__ void k_final(const float* __restrict__ W3, const float* __restrict__ b3,
                        float* __restrict__ out) {
    int g = blockIdx.x, lane = threadIdx.x;
    float acc = 0.f;
    #pragma unroll
    for (int j = 0; j < 8; j++) acc += g_m2[g * 256 + lane + 32 * j] * W3[lane + 32 * j];
    acc = warp_sum(acc);
    if (lane == 0) out[g] = 1.f / (1.f + expf(-(acc + b3[0])));
}

// ---------------- host launch ----------------
static inline void launch_sgemm(const float* A, const float* B, const float* bias,
                                float* C, int M, int Nc, int K, int act) {
    dim3 grid((Nc + 127) / 128, (M + 127) / 128);
    k_sgemm<<<grid, 256>>>(A, B, bias, C, M, Nc, K, act);
}

extern "C" void kernel_launch(void* const* d_in, const int* in_sizes, int n_in,
                              void* d_out, int out_size) {
    const float* x     = (const float*)d_in[0];
    const int*   ei    = (const int*)  d_in[1];
    const float* ea    = (const float*)d_in[2];
    const int*   batch = (const int*)  d_in[3];
    const float* Wl1 = (const float*)d_in[4],  *bl1 = (const float*)d_in[5];
    const float* Wr1 = (const float*)d_in[6],  *br1 = (const float*)d_in[7];
    const float* We1 = (const float*)d_in[8],  *att1 = (const float*)d_in[9];
    const float* bias1 = (const float*)d_in[10];
    const float* Wl2 = (const float*)d_in[11], *bl2 = (const float*)d_in[12];
    const float* Wr2 = (const float*)d_in[13], *br2 = (const float*)d_in[14];
    const float* We2 = (const float*)d_in[15], *att2 = (const float*)d_in[16];
    const float* bias2 = (const float*)d_in[17];
    const float* W1 = (const float*)d_in[18], *b1 = (const float*)d_in[19];
    const float* W2 = (const float*)d_in[20], *b2 = (const float*)d_in[21];
    const float* W3 = (const float*)d_in[22], *b3 = (const float*)d_in[23];
    float* out = (float*)d_out;

    cudaFuncSetAttribute(k_mma_dual, cudaFuncAttributeMaxDynamicSharedMemorySize, GEMM_SMEM_BYTES);

    float *p_h2, *p_pool, *p_m1, *p_m2;
    __half *p_xl, *p_xr, *p_h1h, *p_ea2h, *p_w1h, *p_w2h, *p_we1h, *p_we2h, *p_xh;
    cudaGetSymbolAddress((void**)&p_xl,    g_xl);
    cudaGetSymbolAddress((void**)&p_xr,    g_xr);
    cudaGetSymbolAddress((void**)&p_h1h,   g_h1h);
    cudaGetSymbolAddress((void**)&p_ea2h,  g_ea2h);
    cudaGetSymbolAddress((void**)&p_w1h,   g_w1h);
    cudaGetSymbolAddress((void**)&p_w2h,   g_w2h);
    cudaGetSymbolAddress((void**)&p_we1h,  g_we1h);
    cudaGetSymbolAddress((void**)&p_we2h,  g_we2h);
    cudaGetSymbolAddress((void**)&p_xh,    g_xh);
    cudaGetSymbolAddress((void**)&p_h2,    g_h2);
    cudaGetSymbolAddress((void**)&p_pool,  g_pool);
    cudaGetSymbolAddress((void**)&p_m1,    g_m1);
    cudaGetSymbolAddress((void**)&p_m2,    g_m2);

    // --- graph preprocessing + conversions ---
    k_detect<<<1, 1>>>(ei);
    k_norm_idx<<<(EE + 255) / 256, 256>>>(ei, batch);
    k_zero<<<(NN * DEDGE + 255) / 256, 256>>>();
    k_wconv<<<(HC2 * HC1 + 255) / 256, 256>>>(Wl1, Wr1, Wl2, Wr2, We1, We2, x);
    k_deg_easum<<<(EE * DEDGE + 255) / 256, 256>>>(ea);
    k_ea2<<<(ET * DEDGE + 255) / 256, 256>>>(ea);
    k_scan<<<1, 256>>>();
    k_csr<<<(ET + 255) / 256, 256>>>();

    // --- GATv2 layer 1: fused xl|xr GEMM (N = 4096, K = 64) ---
    k_zlog<<<(ET * H1C + 255) / 256, 256>>>(ET * H1C);
    k_mma_dual<<<dim3(2 * HC1 / 128, NN / 128), 256, GEMM_SMEM_BYTES>>>(
        p_xh, p_w1h, bl1, br1, p_xl, p_xr, NN, 2 * HC1, DNODE);
    k_ee_logits<H1C><<<dim3(HC1 / 128, ET / 128), 256>>>(p_ea2h, p_we1h, att1);
    k_aggregate<H1C, 1, 1><<<NN, H1C * 32>>>(bias1, p_h1h);

    // --- GATv2 layer 2: fused xl|xr GEMM (N = 2048, K = 2048) ---
    k_zlog<<<(ET * H2C + 255) / 256, 256>>>(ET * H2C);
    k_mma_dual<<<dim3(2 * HC2 / 128, NN / 128), 256, GEMM_SMEM_BYTES>>>(
        p_h1h, p_w2h, bl2, br2, p_xl, p_xr, NN, 2 * HC2, HC1);
    k_ee_logits<H2C><<<dim3(HC2 / 128, ET / 128), 256>>>(p_ea2h, p_we2h, att2);
    k_aggregate<H2C, 0, 0><<<NN, H2C * 32>>>(bias2, p_h2);

    // --- pool + MLP ---
    k_pool<<<(NN * HC2 + 255) / 256, 256>>>();
    k_pool_div<<<(GG * HC2 + 255) / 256, 256>>>();
    launch_sgemm(p_pool, W1, b1, p_m1, GG, 512, HC2, 1);
    launch_sgemm(p_m1,  W2, b2, p_m2, GG, 256, 512, 1);
    k_final<<<GG, 32>>>(W3, b3, out);
}

// round 8
// speedup vs baseline: 4.0395x; 1.0117x over previous
#include <cuda_runtime.h>
#include <cuda_fp16.h>
#include <math.h>
#include <stdint.h>

// ---------------- problem constants ----------------
#define NN   8192
#define EE   65536
#define GG   64
#define DNODE 64
#define DEDGE 32
#define CC   256
#define H1C  8
#define H2C  4
#define ET   (EE + NN)          // 73728 = 576*128
#define HC1  (H1C * CC)         // 2048
#define HC2  (H2C * CC)         // 1024
#define NEG_SLOPE 0.2f

// ---------------- device scratch ----------------
__device__ int    g_is64;
__device__ int    g_src[EE];
__device__ int    g_dst[EE];
__device__ int    g_batch[NN];
__device__ int    g_deg[NN];
__device__ int    g_cur[NN];
__device__ int    g_off[NN + 1];
__device__ int    g_csr[ET];
__device__ float  g_easum[NN * DEDGE];
__device__ __half g_ea2h[ET * DEDGE];
__device__ __half g_xh[NN * DNODE];
__device__ __half g_xl[NN * HC1];
__device__ __half g_xr[NN * HC1];
__device__ __half g_h1h[NN * HC1];
__device__ float  g_logits[ET * H1C * 4];    // 4 deterministic partials per (e,h)
__device__ float  g_h2[NN * HC2];
__device__ float  g_pool[GG * HC2];
__device__ float  g_cnt[GG];
__device__ float  g_m1[GG * 512];
__device__ float  g_m2[GG * 256];
__device__ __half g_w1h[2 * HC1 * DNODE];
__device__ __half g_w2h[2 * HC2 * HC1];
__device__ __half g_we1h[HC1 * DEDGE];
__device__ __half g_we2h[HC2 * DEDGE];

// ---------------- helpers ----------------
__device__ __forceinline__ float warp_sum(float v) {
    #pragma unroll
    for (int o = 16; o; o >>= 1) v += __shfl_xor_sync(0xffffffffu, v, o);
    return v;
}
__device__ __forceinline__ float warp_max(float v) {
    #pragma unroll
    for (int o = 16; o; o >>= 1) v = fmaxf(v, __shfl_xor_sync(0xffffffffu, v, o));
    return v;
}
__device__ __forceinline__ uint32_t smem_u32(const void* p) {
    uint32_t a;
    asm("{ .reg .u64 t; cvta.to.shared.u64 t, %1; cvt.u32.u64 %0, t; }" : "=r"(a) : "l"(p));
    return a;
}
__device__ __forceinline__ void mma_f16(float* c, uint4 a, uint2 b) {
    asm volatile(
        "mma.sync.aligned.m16n8k16.row.col.f32.f16.f16.f32 "
        "{%0,%1,%2,%3},{%4,%5,%6,%7},{%8,%9},{%0,%1,%2,%3};"
        : "+f"(c[0]), "+f"(c[1]), "+f"(c[2]), "+f"(c[3])
        : "r"(a.x), "r"(a.y), "r"(a.z), "r"(a.w), "r"(b.x), "r"(b.y));
}
__device__ __forceinline__ uint4 ldsm4(uint32_t addr) {
    uint4 r;
    asm volatile("ldmatrix.sync.aligned.m8n8.x4.shared.b16 {%0,%1,%2,%3}, [%4];"
        : "=r"(r.x), "=r"(r.y), "=r"(r.z), "=r"(r.w) : "r"(addr));
    return r;
}
__device__ __forceinline__ void cp16(uint32_t dst, const void* src) {
    asm volatile("cp.async.cg.shared.global [%0], [%1], 16;" :: "r"(dst), "l"(src));
}

// =================================================================
// cp.async + ldmatrix fp16 GEMM (3-stage, XOR swizzle) — proven R7.
// =================================================================
#define GEMM_STAGE_BYTES 32768
#define GEMM_SMEM_BYTES  (3 * GEMM_STAGE_BYTES)

__device__ __forceinline__ void issue_stage(
    const __half* __restrict__ A, const __half* __restrict__ B, int K,
    int rowBase, int colBase, int k0, uint32_t abase, int tid)
{
    #pragma unroll
    for (int i = 0; i < 4; i++) {
        int id = i * 256 + tid;
        int r = id >> 3, c = id & 7;
        uint32_t off = (uint32_t)(r * 128 + ((c ^ (r & 7)) << 4));
        cp16(abase + off,         A + (size_t)(rowBase + r) * K + k0 + c * 8);
        cp16(abase + 16384 + off, B + (size_t)(colBase + r) * K + k0 + c * 8);
    }
    asm volatile("cp.async.commit_group;" ::: "memory");
}

__global__ __launch_bounds__(256, 2) void k_mma_dual(
    const __half* __restrict__ A, const __half* __restrict__ B,
    const float* __restrict__ biasL, const float* __restrict__ biasR,
    __half* __restrict__ outL, __half* __restrict__ outR,
    int M, int N, int K)
{
    extern __shared__ char smem[];
    uint32_t sb = smem_u32(smem);
    int tid = threadIdx.x;
    int wid = tid >> 5, lane = tid & 31;
    int mw = wid & 3, nw = wid >> 2;
    int gid = lane >> 2, tig = lane & 3;
    int rowBase = blockIdx.y * 128, colBase = blockIdx.x * 128;

    float acc[2][8][4];
    #pragma unroll
    for (int mt = 0; mt < 2; mt++)
        #pragma unroll
        for (int nt = 0; nt < 8; nt++)
            #pragma unroll
            for (int q = 0; q < 4; q++) acc[mt][nt][q] = 0.f;

    const int NCH = K >> 6;
    issue_stage(A, B, K, rowBase, colBase, 0, sb, tid);
    if (NCH > 1) issue_stage(A, B, K, rowBase, colBase, 64, sb + GEMM_STAGE_BYTES, tid);

    int arow = mw * 32 + (lane & 15);
    int achoff = lane >> 4;
    int brow = nw * 64 + ((lane >> 4) << 3) + (lane & 7);
    int bchoff = (lane >> 3) & 1;

    for (int c = 0; c < NCH; c++) {
        if (c + 2 <= NCH) asm volatile("cp.async.wait_group 1;" ::: "memory");
        else              asm volatile("cp.async.wait_group 0;" ::: "memory");
        __syncthreads();
        if (c + 2 < NCH)
            issue_stage(A, B, K, rowBase, colBase, (c + 2) << 6,
                        sb + ((c + 2) % 3) * GEMM_STAGE_BYTES, tid);

        uint32_t Ab = sb + (c % 3) * GEMM_STAGE_BYTES;
        uint32_t Bb = Ab + 16384;
        #pragma unroll
        for (int kstep = 0; kstep < 4; kstep++) {
            uint4 afr[2];
            #pragma unroll
            for (int mt = 0; mt < 2; mt++) {
                int row = arow + mt * 16;
                int ch = kstep * 2 + achoff;
                afr[mt] = ldsm4(Ab + row * 128 + ((ch ^ (row & 7)) << 4));
            }
            uint2 bfr[8];
            #pragma unroll
            for (int ntp = 0; ntp < 4; ntp++) {
                int row = brow + ntp * 16;
                int ch = kstep * 2 + bchoff;
                uint4 t = ldsm4(Bb + row * 128 + ((ch ^ (row & 7)) << 4));
                bfr[2 * ntp]     = make_uint2(t.x, t.y);
                bfr[2 * ntp + 1] = make_uint2(t.z, t.w);
            }
            #pragma unroll
            for (int mt = 0; mt < 2; mt++)
                #pragma unroll
                for (int nt = 0; nt < 8; nt++)
                    mma_f16(acc[mt][nt], afr[mt], bfr[nt]);
        }
    }

    int halfN = N >> 1;
    bool isR = (colBase >= halfN);
    const float* bias = isR ? biasR : biasL;
    __half* outp = isR ? outR : outL;
    int cb = colBase - (isR ? halfN : 0);

    #pragma unroll
    for (int mt = 0; mt < 2; mt++) {
        int row0 = rowBase + mw * 32 + mt * 16 + gid;
        #pragma unroll
        for (int nt = 0; nt < 8; nt++) {
            int col = cb + nw * 64 + nt * 8 + tig * 2;
            float b0 = bias[col], b1 = bias[col + 1];
            float c0 = acc[mt][nt][0] + b0, c1 = acc[mt][nt][1] + b1;
            float c2 = acc[mt][nt][2] + b0, c3 = acc[mt][nt][3] + b1;
            *reinterpret_cast<__half2*>(outp + (size_t)row0 * halfN + col)       = __floats2half2_rn(c0, c1);
            *reinterpret_cast<__half2*>(outp + (size_t)(row0 + 8) * halfN + col) = __floats2half2_rn(c2, c3);
        }
    }
}

// =================================================================
// Fused edge-feature GEMM + logits -> deterministic partial stores.
// partial index q = (tile parity)*2 + nw; logit = sum of 4 partials.
// =================================================================
__device__ __forceinline__ void ldg_tile_h(
    const __half* __restrict__ A, const __half* __restrict__ B, int K,
    int rowBase, int colBase, int kc, int tid, uint2* pa, uint2* pb)
{
    #pragma unroll
    for (int i = 0; i < 4; i++) {
        int id = i * 256 + tid;
        int r = id >> 3, c4 = id & 7;
        pa[i] = *reinterpret_cast<const uint2*>(A + (size_t)(rowBase + r) * K + kc + c4 * 4);
        pb[i] = *reinterpret_cast<const uint2*>(B + (size_t)(colBase + r) * K + kc + c4 * 4);
    }
}
__device__ __forceinline__ void sts_tile(
    uint32_t* __restrict__ sA, uint32_t* __restrict__ sB,
    int tid, const uint2* pa, const uint2* pb)
{
    #pragma unroll
    for (int i = 0; i < 4; i++) {
        int id = i * 256 + tid;
        int r = id >> 3, c4 = id & 7;
        int kstep = c4 >> 2;
        int pl = (c4 & 3) * 2;
        int mtile = r >> 4, ri = r & 15;
        int regA = ((pl & 4) ? 2 : 0) + (ri >> 3);
        int laneA = (ri & 7) * 4 + (pl & 3);
        int baseA = (kstep * 8 + mtile) * 128;
        sA[baseA + laneA * 4 + regA]       = pa[i].x;
        sA[baseA + (laneA + 1) * 4 + regA] = pa[i].y;
        int ntile = r >> 3, ni = r & 7;
        int regB = (pl & 4) ? 1 : 0;
        int laneB = ni * 4 + (pl & 3);
        int baseB = (kstep * 16 + ntile) * 64;
        sB[baseB + laneB * 2 + regB]       = pb[i].x;
        sB[baseB + (laneB + 1) * 2 + regB] = pb[i].y;
    }
}

template <int H>
__global__ __launch_bounds__(256) void k_ee_logits(
    const __half* __restrict__ A, const __half* __restrict__ B,
    const float* __restrict__ att)
{
    __shared__ uint32_t sm[4096];
    int tid = threadIdx.x;
    int wid = tid >> 5, lane = tid & 31;
    int mw = wid & 3, nw = wid >> 2;
    int gid = lane >> 2, tig = lane & 3;
    int rowBase = blockIdx.y * 128, colBase = blockIdx.x * 128;

    float acc[2][8][4];
    #pragma unroll
    for (int mt = 0; mt < 2; mt++)
        #pragma unroll
        for (int nt = 0; nt < 8; nt++)
            #pragma unroll
            for (int q = 0; q < 4; q++) acc[mt][nt][q] = 0.f;

    uint2 pa[4], pb[4];
    ldg_tile_h(A, B, DEDGE, rowBase, colBase, 0, tid, pa, pb);
    sts_tile(sm, sm + 2048, tid, pa, pb);
    __syncthreads();

    #pragma unroll
    for (int kstep = 0; kstep < 2; kstep++) {
        uint4 afr[2];
        #pragma unroll
        for (int mt = 0; mt < 2; mt++)
            afr[mt] = *reinterpret_cast<const uint4*>(
                sm + (kstep * 8 + mw * 2 + mt) * 128 + lane * 4);
        uint2 bfr[8];
        #pragma unroll
        for (int nt = 0; nt < 8; nt++)
            bfr[nt] = *reinterpret_cast<const uint2*>(
                sm + 2048 + (kstep * 16 + nw * 8 + nt) * 64 + lane * 2);
        #pragma unroll
        for (int mt = 0; mt < 2; mt++)
            #pragma unroll
            for (int nt = 0; nt < 8; nt++)
                mma_f16(acc[mt][nt], afr[mt], bfr[nt]);
    }

    int h = colBase >> 8;
    int q = ((blockIdx.x & 1) << 1) | nw;
    const int HCH = H * (CC / 2);
    const __half2* xl = reinterpret_cast<const __half2*>(g_xl);
    const __half2* xr = reinterpret_cast<const __half2*>(g_xr);

    #pragma unroll
    for (int mt = 0; mt < 2; mt++) {
        int e0 = rowBase + mw * 32 + mt * 16 + gid;
        int e1 = e0 + 8;
        int s0, d0, s1, d1;
        if (e0 < EE) { s0 = g_src[e0]; d0 = g_dst[e0]; } else { s0 = d0 = e0 - EE; }
        if (e1 < EE) { s1 = g_src[e1]; d1 = g_dst[e1]; } else { s1 = d1 = e1 - EE; }
        float p0 = 0.f, p1 = 0.f;
        #pragma unroll
        for (int nt = 0; nt < 8; nt++) {
            int col = colBase + nw * 64 + nt * 8 + tig * 2;
            int c2i = col >> 1;
            float2 at = *reinterpret_cast<const float2*>(att + h * CC + (col & (CC - 1)));
            float2 a0 = __half22float2(xl[(size_t)s0 * HCH + c2i]);
            float2 b0 = __half22float2(xr[(size_t)d0 * HCH + c2i]);
            float2 a1 = __half22float2(xl[(size_t)s1 * HCH + c2i]);
            float2 b1 = __half22float2(xr[(size_t)d1 * HCH + c2i]);
            float v0 = acc[mt][nt][0] + a0.x + b0.x;
            float v1 = acc[mt][nt][1] + a0.y + b0.y;
            float v2 = acc[mt][nt][2] + a1.x + b1.x;
            float v3 = acc[mt][nt][3] + a1.y + b1.y;
            v0 = (v0 > 0.f) ? v0 : NEG_SLOPE * v0;
            v1 = (v1 > 0.f) ? v1 : NEG_SLOPE * v1;
            v2 = (v2 > 0.f) ? v2 : NEG_SLOPE * v2;
            v3 = (v3 > 0.f) ? v3 : NEG_SLOPE * v3;
            p0 += v0 * at.x + v1 * at.y;
            p1 += v2 * at.x + v3 * at.y;
        }
        p0 += __shfl_xor_sync(0xffffffffu, p0, 1);
        p0 += __shfl_xor_sync(0xffffffffu, p0, 2);
        p1 += __shfl_xor_sync(0xffffffffu, p1, 1);
        p1 += __shfl_xor_sync(0xffffffffu, p1, 2);
        if (tig == 0) {
            g_logits[(e0 * H + h) * 4 + q] = p0;
            g_logits[(e1 * H + h) * 4 + q] = p1;
        }
    }
}

// ---------------- weight / input conversion ----------------
__global__ void k_wconv(const float* __restrict__ Wl1, const float* __restrict__ Wr1,
                        const float* __restrict__ Wl2, const float* __restrict__ Wr2,
                        const float* __restrict__ We1, const float* __restrict__ We2,
                        const float* __restrict__ x)
{
    int t = blockIdx.x * blockDim.x + threadIdx.x;
    const int s1 = HC1 * DNODE;
    const int s2 = HC2 * HC1;
    const int s3 = HC1 * DEDGE;
    const int s4 = HC2 * DEDGE;
    if (t < s1) { g_w1h[t] = __float2half_rn(Wl1[t]); g_w1h[s1 + t] = __float2half_rn(Wr1[t]); }
    if (t < s2) { g_w2h[t] = __float2half_rn(Wl2[t]); g_w2h[s2 + t] = __float2half_rn(Wr2[t]); }
    if (t < s3) g_we1h[t] = __float2half_rn(We1[t]);
    if (t < s4) g_we2h[t] = __float2half_rn(We2[t]);
    if (t < NN * DNODE) g_xh[t] = __float2half_rn(x[t]);
}

// ---------------- index / graph prep ----------------
__global__ void k_detect(const int* __restrict__ ei) {
    int is64 = 1;
    for (int i = 0; i < 16; i++)
        if (ei[2 * i + 1] != 0) is64 = 0;
    g_is64 = is64;
}
__global__ void k_norm_idx(const int* __restrict__ ei, const int* __restrict__ batch) {
    int t = blockIdx.x * blockDim.x + threadIdx.x;
    int is64 = g_is64;
    if (t < EE) {
        g_src[t] = is64 ? ei[2 * t]        : ei[t];
        g_dst[t] = is64 ? ei[2 * (EE + t)] : ei[EE + t];
    }
    if (t < NN) g_batch[t] = is64 ? batch[2 * t] : batch[t];
}
__global__ void k_zero() {
    int t = blockIdx.x * blockDim.x + threadIdx.x;
    if (t < NN) { g_deg[t] = 0; g_cur[t] = 0; }
    if (t < NN * DEDGE) g_easum[t] = 0.f;
    if (t < GG * HC2) g_pool[t] = 0.f;
    if (t < GG) g_cnt[t] = 0.f;
}
__global__ void k_deg_easum(const float* __restrict__ ea) {
    int t = blockIdx.x * blockDim.x + threadIdx.x;
    if (t >= EE * DEDGE) return;
    int e = t >> 5, d = t & 31;
    int dst = g_dst[e];
    atomicAdd(&g_easum[dst * DEDGE + d], ea[t]);
    if (d == 0) atomicAdd(&g_deg[dst], 1);
}
__global__ void k_ea2(const float* __restrict__ ea) {
    int t = blockIdx.x * blockDim.x + threadIdx.x;
    if (t >= ET * DEDGE) return;
    if (t < EE * DEDGE) {
        g_ea2h[t] = __float2half_rn(ea[t]);
    } else {
        int u = t - EE * DEDGE;
        int n = u >> 5;
        g_ea2h[t] = __float2half_rn(g_easum[u] / fmaxf((float)g_deg[n], 1.f));
    }
}
__global__ void k_scan() {
    __shared__ int part[256];
    int t = threadIdx.x;
    int base = t * 32;
    int loc[32];
    int s = 0;
    #pragma unroll
    for (int i = 0; i < 32; i++) { loc[i] = s; s += g_deg[base + i] + 1; }
    part[t] = s;
    __syncthreads();
    if (t == 0) {
        int acc = 0;
        for (int i = 0; i < 256; i++) { int v = part[i]; part[i] = acc; acc += v; }
        g_off[NN] = acc;
    }
    __syncthreads();
    int p = part[t];
    #pragma unroll
    for (int i = 0; i < 32; i++) g_off[base + i] = p + loc[i];
}
__global__ void k_csr() {
    int e = blockIdx.x * blockDim.x + threadIdx.x;
    if (e >= ET) return;
    int node = (e < EE) ? g_dst[e] : (e - EE);
    int pos = g_off[node] + atomicAdd(&g_cur[node], 1);
    g_csr[pos] = e;
}

// ---------------- fp32 SGEMM for the tiny MLP ----------------
__global__ __launch_bounds__(256) void k_sgemm(
    const float* __restrict__ A, const float* __restrict__ Bm,
    const float* __restrict__ bias, float* __restrict__ Cm,
    int M, int Nc, int K, int act)
{
    constexpr int BM = 128, BN = 128, BK = 16, TM = 8, TN = 8;
    __shared__ float As[BK][BM];
    __shared__ float Bs[BK][BN];
    int tid = threadIdx.x;
    int tx = tid % 16, ty = tid / 16;
    int rowBase = blockIdx.y * BM;
    int colBase = blockIdx.x * BN;
    float acc[TM][TN];
    #pragma unroll
    for (int i = 0; i < TM; i++)
        #pragma unroll
        for (int j = 0; j < TN; j++) acc[i][j] = 0.f;
    for (int k0 = 0; k0 < K; k0 += BK) {
        #pragma unroll
        for (int i = 0; i < 2; i++) {
            int f4 = tid + i * 256;
            int r = f4 >> 2;
            int kk = (f4 & 3) * 4;
            int gr = rowBase + r;
            float4 v = make_float4(0.f, 0.f, 0.f, 0.f);
            if (gr < M) v = *reinterpret_cast<const float4*>(A + (size_t)gr * K + k0 + kk);
            As[kk + 0][r] = v.x; As[kk + 1][r] = v.y; As[kk + 2][r] = v.z; As[kk + 3][r] = v.w;
            int gc = colBase + r;
            float4 w = make_float4(0.f, 0.f, 0.f, 0.f);
            if (gc < Nc) w = *reinterpret_cast<const float4*>(Bm + (size_t)gc * K + k0 + kk);
            Bs[kk + 0][r] = w.x; Bs[kk + 1][r] = w.y; Bs[kk + 2][r] = w.z; Bs[kk + 3][r] = w.w;
        }
        __syncthreads();
        #pragma unroll
        for (int k = 0; k < BK; k++) {
            float a[TM], b[TN];
            #pragma unroll
            for (int i = 0; i < TM; i++) a[i] = As[k][ty * TM + i];
            #pragma unroll
            for (int j = 0; j < TN; j++) b[j] = Bs[k][tx * TN + j];
            #pragma unroll
            for (int i = 0; i < TM; i++)
                #pragma unroll
                for (int j = 0; j < TN; j++) acc[i][j] = fmaf(a[i], b[j], acc[i][j]);
        }
        __syncthreads();
    }
    #pragma unroll
    for (int i = 0; i < TM; i++) {
        int gr = rowBase + ty * TM + i;
        if (gr >= M) continue;
        #pragma unroll
        for (int j = 0; j < TN; j++) {
            int gc = colBase + tx * TN + j;
            if (gc >= Nc) continue;
            float v = acc[i][j];
            if (bias) v += bias[gc];
            if (act) v = fmaxf(v, 0.f);
            Cm[(size_t)gr * Nc + gc] = v;
        }
    }
}

// ---------------- segment softmax + weighted gather ----------------
template <int H, int RELU, int OUTH>
__global__ void k_aggregate(const float* __restrict__ bias, void* __restrict__ out) {
    int n = blockIdx.x;
    int h = threadIdx.x >> 5, lane = threadIdx.x & 31;
    int s0 = g_off[n], s1 = g_off[n + 1];
    int cnt = s1 - s0;
    const int HCH = H * (CC / 2);
    const __half2* xl = reinterpret_cast<const __half2*>(g_xl);
    float2 acc[4];
    #pragma unroll
    for (int j = 0; j < 4; j++) acc[j] = make_float2(0.f, 0.f);

    if (cnt <= 64) {
        // register-cached path: each lane holds up to 2 (edge, logit) entries
        int ce0 = -1, ce1 = -1;
        float lv0 = -1e30f, lv1 = -1e30f;
        if (lane < cnt) {
            ce0 = g_csr[s0 + lane];
            float4 lg = *reinterpret_cast<const float4*>(&g_logits[(ce0 * H + h) * 4]);
            lv0 = (lg.x + lg.y) + (lg.z + lg.w);
        }
        if (lane + 32 < cnt) {
            ce1 = g_csr[s0 + lane + 32];
            float4 lg = *reinterpret_cast<const float4*>(&g_logits[(ce1 * H + h) * 4]);
            lv1 = (lg.x + lg.y) + (lg.z + lg.w);
        }
        float mx = warp_max(fmaxf(lv0, lv1));
        float ex0 = (lane < cnt)      ? __expf(lv0 - mx) : 0.f;
        float ex1 = (lane + 32 < cnt) ? __expf(lv1 - mx) : 0.f;
        float inv = 1.f / warp_sum(ex0 + ex1);
        for (int i = 0; i < cnt; i++) {
            int srcl = i & 31;
            float w = __shfl_sync(0xffffffffu, (i < 32) ? ex0 : ex1, srcl) * inv;
            int e = __shfl_sync(0xffffffffu, (i < 32) ? ce0 : ce1, srcl);
            int s = (e < EE) ? g_src[e] : (e - EE);
            const __half2* row = xl + (size_t)s * HCH + h * 128 + lane;
            #pragma unroll
            for (int j = 0; j < 4; j++) {
                float2 f = __half22float2(row[32 * j]);
                acc[j].x = fmaf(w, f.x, acc[j].x);
                acc[j].y = fmaf(w, f.y, acc[j].y);
            }
        }
    } else {
        // fallback: multi-pass
        float mx = -1e30f;
        for (int i = s0 + lane; i < s1; i += 32) {
            float4 lg = *reinterpret_cast<const float4*>(&g_logits[(g_csr[i] * H + h) * 4]);
            mx = fmaxf(mx, (lg.x + lg.y) + (lg.z + lg.w));
        }
        mx = warp_max(mx);
        float den = 0.f;
        for (int i = s0 + lane; i < s1; i += 32) {
            float4 lg = *reinterpret_cast<const float4*>(&g_logits[(g_csr[i] * H + h) * 4]);
            den += __expf((lg.x + lg.y) + (lg.z + lg.w) - mx);
        }
        den = warp_sum(den);
        float inv = 1.f / den;
        for (int i = s0; i < s1; i++) {
            int e = g_csr[i];
            float4 lg = *reinterpret_cast<const float4*>(&g_logits[(e * H + h) * 4]);
            float w = __expf((lg.x + lg.y) + (lg.z + lg.w) - mx) * inv;
            int s = (e < EE) ? g_src[e] : (e - EE);
            const __half2* row = xl + (size_t)s * HCH + h * 128 + lane;
            #pragma unroll
            for (int j = 0; j < 4; j++) {
                float2 f = __half22float2(row[32 * j]);
                acc[j].x = fmaf(w, f.x, acc[j].x);
                acc[j].y = fmaf(w, f.y, acc[j].y);
            }
        }
    }

    #pragma unroll
    for (int j = 0; j < 4; j++) {
        int col = h * CC + 2 * (lane + 32 * j);
        float2 b = *reinterpret_cast<const float2*>(bias + col);
        float v0 = acc[j].x + b.x, v1 = acc[j].y + b.y;
        if (RELU) { v0 = fmaxf(v0, 0.f); v1 = fmaxf(v1, 0.f); }
        if (OUTH) {
            __half* oh = (__half*)out;
            *reinterpret_cast<__half2*>(oh + (size_t)n * (H * CC) + col) = __floats2half2_rn(v0, v1);
        } else {
            float* of = (float*)out;
            *reinterpret_cast<float2*>(of + (size_t)n * (H * CC) + col) = make_float2(v0, v1);
        }
    }
}

// ---------------- pooling + final ----------------
__global__ void k_pool() {
    int t = blockIdx.x * blockDim.x + threadIdx.x;
    if (t >= NN * HC2) return;
    int n = t >> 10, c = t & 1023;
    int b = g_batch[n];
    atomicAdd(&g_pool[b * HC2 + c], g_h2[t]);
    if (c == 0) atomicAdd(&g_cnt[b], 1.f);
}
__global__ void k_pool_div() {
    int t = blockIdx.x * blockDim.x + threadIdx.x;
    if (t >= GG * HC2) return;
    g_pool[t] /= fmaxf(g_cnt[t >> 10], 1.f);
}
__global__ void k_final(const float* __restrict__ W3, const float* __restrict__ b3,
                        float* __restrict__ out) {
    int g = blockIdx.x, lane = threadIdx.x;
    float acc = 0.f;
    #pragma unroll
    for (int j = 0; j < 8; j++) acc += g_m2[g * 256 + lane + 32 * j] * W3[lane + 32 * j];
    acc = warp_sum(acc);
    if (lane == 0) out[g] = 1.f / (1.f + expf(-(acc + b3[0])));
}

// ---------------- host launch ----------------
static inline void launch_sgemm(const float* A, const float* B, const float* bias,
                                float* C, int M, int Nc, int K, int act) {
    dim3 grid((Nc + 127) / 128, (M + 127) / 128);
    k_sgemm<<<grid, 256>>>(A, B, bias, C, M, Nc, K, act);
}

extern "C" void kernel_launch(void* const* d_in, const int* in_sizes, int n_in,
                              void* d_out, int out_size) {
    const float* x     = (const float*)d_in[0];
    const int*   ei    = (const int*)  d_in[1];
    const float* ea    = (const float*)d_in[2];
    const int*   batch = (const int*)  d_in[3];
    const float* Wl1 = (const float*)d_in[4],  *bl1 = (const float*)d_in[5];
    const float* Wr1 = (const float*)d_in[6],  *br1 = (const float*)d_in[7];
    const float* We1 = (const float*)d_in[8],  *att1 = (const float*)d_in[9];
    const float* bias1 = (const float*)d_in[10];
    const float* Wl2 = (const float*)d_in[11], *bl2 = (const float*)d_in[12];
    const float* Wr2 = (const float*)d_in[13], *br2 = (const float*)d_in[14];
    const float* We2 = (const float*)d_in[15], *att2 = (const float*)d_in[16];
    const float* bias2 = (const float*)d_in[17];
    const float* W1 = (const float*)d_in[18], *b1 = (const float*)d_in[19];
    const float* W2 = (const float*)d_in[20], *b2 = (const float*)d_in[21];
    const float* W3 = (const float*)d_in[22], *b3 = (const float*)d_in[23];
    float* out = (float*)d_out;

    cudaFuncSetAttribute(k_mma_dual, cudaFuncAttributeMaxDynamicSharedMemorySize, GEMM_SMEM_BYTES);

    float *p_h2, *p_pool, *p_m1, *p_m2;
    __half *p_xl, *p_xr, *p_h1h, *p_ea2h, *p_w1h, *p_w2h, *p_we1h, *p_we2h, *p_xh;
    cudaGetSymbolAddress((void**)&p_xl,    g_xl);
    cudaGetSymbolAddress((void**)&p_xr,    g_xr);
    cudaGetSymbolAddress((void**)&p_h1h,   g_h1h);
    cudaGetSymbolAddress((void**)&p_ea2h,  g_ea2h);
    cudaGetSymbolAddress((void**)&p_w1h,   g_w1h);
    cudaGetSymbolAddress((void**)&p_w2h,   g_w2h);
    cudaGetSymbolAddress((void**)&p_we1h,  g_we1h);
    cudaGetSymbolAddress((void**)&p_we2h,  g_we2h);
    cudaGetSymbolAddress((void**)&p_xh,    g_xh);
    cudaGetSymbolAddress((void**)&p_h2,    g_h2);
    cudaGetSymbolAddress((void**)&p_pool,  g_pool);
    cudaGetSymbolAddress((void**)&p_m1,    g_m1);
    cudaGetSymbolAddress((void**)&p_m2,    g_m2);

    // --- prep (ordered so launch #5 = layer-1 k_mma_dual for ncu) ---
    k_detect<<<1, 1>>>(ei);                                         // 0
    k_norm_idx<<<(EE + 255) / 256, 256>>>(ei, batch);               // 1
    k_wconv<<<(HC2 * HC1 + 255) / 256, 256>>>(Wl1, Wr1, Wl2, Wr2, We1, We2, x);  // 2
    k_zero<<<(NN * DEDGE + 255) / 256, 256>>>();                    // 3
    k_deg_easum<<<(EE * DEDGE + 255) / 256, 256>>>(ea);             // 4
    k_mma_dual<<<dim3(2 * HC1 / 128, NN / 128), 256, GEMM_SMEM_BYTES>>>(   // 5 <- ncu
        p_xh, p_w1h, bl1, br1, p_xl, p_xr, NN, 2 * HC1, DNODE);
    k_ea2<<<(ET * DEDGE + 255) / 256, 256>>>(ea);                   // 6
    k_scan<<<1, 256>>>();                                           // 7
    k_csr<<<(ET + 255) / 256, 256>>>();                             // 8

    // --- GATv2 layer 1 ---
    k_ee_logits<H1C><<<dim3(HC1 / 128, ET / 128), 256>>>(p_ea2h, p_we1h, att1);
    k_aggregate<H1C, 1, 1><<<NN, H1C * 32>>>(bias1, p_h1h);

    // --- GATv2 layer 2 ---
    k_mma_dual<<<dim3(2 * HC2 / 128, NN / 128), 256, GEMM_SMEM_BYTES>>>(
        p_h1h, p_w2h, bl2, br2, p_xl, p_xr, NN, 2 * HC2, HC1);
    k_ee_logits<H2C><<<dim3(HC2 / 128, ET / 128), 256>>>(p_ea2h, p_we2h, att2);
    k_aggregate<H2C, 0, 0><<<NN, H2C * 32>>>(bias2, p_h2);

    // --- pool + MLP ---
    k_pool<<<(NN * HC2 + 255) / 256, 256>>>();
    k_pool_div<<<(GG * HC2 + 255) / 256, 256>>>();
    launch_sgemm(p_pool, W1, b1, p_m1, GG, 512, HC2, 1);
    launch_sgemm(p_m1,  W2, b2, p_m2, GG, 256, 512, 1);
    k_final<<<GG, 32>>>(W3, b3, out);
}

// round 9
// speedup vs baseline: 4.1866x; 1.0364x over previous
#include <cuda_runtime.h>
#include <cuda_fp16.h>
#include <math.h>
#include <stdint.h>

// ---------------- problem constants ----------------
#define NN   8192
#define EE   65536
#define GG   64
#define DNODE 64
#define DEDGE 32
#define CC   256
#define H1C  8
#define H2C  4
#define ET   (EE + NN)          // 73728 = 576*128
#define HC1  (H1C * CC)         // 2048
#define HC2  (H2C * CC)         // 1024
#define NEG_SLOPE 0.2f

// ---------------- device scratch ----------------
__device__ int    g_is64;
__device__ int    g_src[EE];
__device__ int    g_dst[EE];
__device__ int    g_batch[NN];
__device__ int    g_deg[NN];
__device__ int    g_cur[NN];
__device__ int    g_off[NN + 1];
__device__ int    g_pos[ET];                 // edge -> csr position
__device__ int    g_psrc[ET];                // csr position -> src node
__device__ int    g_pdst[ET];                // csr position -> dst node (sorted runs)
__device__ float  g_easum[NN * DEDGE];
__device__ __half g_ea2h[ET * DEDGE];        // csr-ordered edge attrs
__device__ __half g_xh[NN * DNODE];
__device__ __half g_xl[NN * HC1];
__device__ __half g_xr[NN * HC1];
__device__ __half g_h1h[NN * HC1];
__device__ float  g_logits[ET * H1C * 4];    // csr-ordered, 4 partials per (pos,h)
__device__ float  g_h2[NN * HC2];
__device__ float  g_pool[GG * HC2];
__device__ float  g_cnt[GG];
__device__ float  g_m1[GG * 512];
__device__ float  g_m2[GG * 256];
__device__ __half g_w1h[2 * HC1 * DNODE];
__device__ __half g_w2h[2 * HC2 * HC1];
__device__ __half g_we1h[HC1 * DEDGE];
__device__ __half g_we2h[HC2 * DEDGE];

// ---------------- helpers ----------------
__device__ __forceinline__ float warp_sum(float v) {
    #pragma unroll
    for (int o = 16; o; o >>= 1) v += __shfl_xor_sync(0xffffffffu, v, o);
    return v;
}
__device__ __forceinline__ float warp_max(float v) {
    #pragma unroll
    for (int o = 16; o; o >>= 1) v = fmaxf(v, __shfl_xor_sync(0xffffffffu, v, o));
    return v;
}
__device__ __forceinline__ uint32_t smem_u32(const void* p) {
    uint32_t a;
    asm("{ .reg .u64 t; cvta.to.shared.u64 t, %1; cvt.u32.u64 %0, t; }" : "=r"(a) : "l"(p));
    return a;
}
__device__ __forceinline__ void mma_f16(float* c, uint4 a, uint2 b) {
    asm volatile(
        "mma.sync.aligned.m16n8k16.row.col.f32.f16.f16.f32 "
        "{%0,%1,%2,%3},{%4,%5,%6,%7},{%8,%9},{%0,%1,%2,%3};"
        : "+f"(c[0]), "+f"(c[1]), "+f"(c[2]), "+f"(c[3])
        : "r"(a.x), "r"(a.y), "r"(a.z), "r"(a.w), "r"(b.x), "r"(b.y));
}
__device__ __forceinline__ uint4 ldsm4(uint32_t addr) {
    uint4 r;
    asm volatile("ldmatrix.sync.aligned.m8n8.x4.shared.b16 {%0,%1,%2,%3}, [%4];"
        : "=r"(r.x), "=r"(r.y), "=r"(r.z), "=r"(r.w) : "r"(addr));
    return r;
}
__device__ __forceinline__ void cp16(uint32_t dst, const void* src) {
    asm volatile("cp.async.cg.shared.global [%0], [%1], 16;" :: "r"(dst), "l"(src));
}

// =================================================================
// cp.async + ldmatrix fp16 GEMM (3-stage, XOR swizzle) — proven R7.
// =================================================================
#define GEMM_STAGE_BYTES 32768
#define GEMM_SMEM_BYTES  (3 * GEMM_STAGE_BYTES)

__device__ __forceinline__ void issue_stage(
    const __half* __restrict__ A, const __half* __restrict__ B, int K,
    int rowBase, int colBase, int k0, uint32_t abase, int tid)
{
    #pragma unroll
    for (int i = 0; i < 4; i++) {
        int id = i * 256 + tid;
        int r = id >> 3, c = id & 7;
        uint32_t off = (uint32_t)(r * 128 + ((c ^ (r & 7)) << 4));
        cp16(abase + off,         A + (size_t)(rowBase + r) * K + k0 + c * 8);
        cp16(abase + 16384 + off, B + (size_t)(colBase + r) * K + k0 + c * 8);
    }
    asm volatile("cp.async.commit_group;" ::: "memory");
}

__global__ __launch_bounds__(256, 2) void k_mma_dual(
    const __half* __restrict__ A, const __half* __restrict__ B,
    const float* __restrict__ biasL, const float* __restrict__ biasR,
    __half* __restrict__ outL, __half* __restrict__ outR,
    int M, int N, int K)
{
    extern __shared__ char smem[];
    uint32_t sb = smem_u32(smem);
    int tid = threadIdx.x;
    int wid = tid >> 5, lane = tid & 31;
    int mw = wid & 3, nw = wid >> 2;
    int gid = lane >> 2, tig = lane & 3;
    int rowBase = blockIdx.y * 128, colBase = blockIdx.x * 128;

    float acc[2][8][4];
    #pragma unroll
    for (int mt = 0; mt < 2; mt++)
        #pragma unroll
        for (int nt = 0; nt < 8; nt++)
            #pragma unroll
            for (int q = 0; q < 4; q++) acc[mt][nt][q] = 0.f;

    const int NCH = K >> 6;
    issue_stage(A, B, K, rowBase, colBase, 0, sb, tid);
    if (NCH > 1) issue_stage(A, B, K, rowBase, colBase, 64, sb + GEMM_STAGE_BYTES, tid);

    int arow = mw * 32 + (lane & 15);
    int achoff = lane >> 4;
    int brow = nw * 64 + ((lane >> 4) << 3) + (lane & 7);
    int bchoff = (lane >> 3) & 1;

    for (int c = 0; c < NCH; c++) {
        if (c + 2 <= NCH) asm volatile("cp.async.wait_group 1;" ::: "memory");
        else              asm volatile("cp.async.wait_group 0;" ::: "memory");
        __syncthreads();
        if (c + 2 < NCH)
            issue_stage(A, B, K, rowBase, colBase, (c + 2) << 6,
                        sb + ((c + 2) % 3) * GEMM_STAGE_BYTES, tid);

        uint32_t Ab = sb + (c % 3) * GEMM_STAGE_BYTES;
        uint32_t Bb = Ab + 16384;
        #pragma unroll
        for (int kstep = 0; kstep < 4; kstep++) {
            uint4 afr[2];
            #pragma unroll
            for (int mt = 0; mt < 2; mt++) {
                int row = arow + mt * 16;
                int ch = kstep * 2 + achoff;
                afr[mt] = ldsm4(Ab + row * 128 + ((ch ^ (row & 7)) << 4));
            }
            uint2 bfr[8];
            #pragma unroll
            for (int ntp = 0; ntp < 4; ntp++) {
                int row = brow + ntp * 16;
                int ch = kstep * 2 + bchoff;
                uint4 t = ldsm4(Bb + row * 128 + ((ch ^ (row & 7)) << 4));
                bfr[2 * ntp]     = make_uint2(t.x, t.y);
                bfr[2 * ntp + 1] = make_uint2(t.z, t.w);
            }
            #pragma unroll
            for (int mt = 0; mt < 2; mt++)
                #pragma unroll
                for (int nt = 0; nt < 8; nt++)
                    mma_f16(acc[mt][nt], afr[mt], bfr[nt]);
        }
    }

    int halfN = N >> 1;
    bool isR = (colBase >= halfN);
    const float* bias = isR ? biasR : biasL;
    __half* outp = isR ? outR : outL;
    int cb = colBase - (isR ? halfN : 0);

    #pragma unroll
    for (int mt = 0; mt < 2; mt++) {
        int row0 = rowBase + mw * 32 + mt * 16 + gid;
        #pragma unroll
        for (int nt = 0; nt < 8; nt++) {
            int col = cb + nw * 64 + nt * 8 + tig * 2;
            float b0 = bias[col], b1 = bias[col + 1];
            float c0 = acc[mt][nt][0] + b0, c1 = acc[mt][nt][1] + b1;
            float c2 = acc[mt][nt][2] + b0, c3 = acc[mt][nt][3] + b1;
            *reinterpret_cast<__half2*>(outp + (size_t)row0 * halfN + col)       = __floats2half2_rn(c0, c1);
            *reinterpret_cast<__half2*>(outp + (size_t)(row0 + 8) * halfN + col) = __floats2half2_rn(c2, c3);
        }
    }
}

// =================================================================
// Fused edge-feature GEMM + logits (csr-ordered edges).
// =================================================================
__device__ __forceinline__ void ldg_tile_h(
    const __half* __restrict__ A, const __half* __restrict__ B, int K,
    int rowBase, int colBase, int kc, int tid, uint2* pa, uint2* pb)
{
    #pragma unroll
    for (int i = 0; i < 4; i++) {
        int id = i * 256 + tid;
        int r = id >> 3, c4 = id & 7;
        pa[i] = *reinterpret_cast<const uint2*>(A + (size_t)(rowBase + r) * K + kc + c4 * 4);
        pb[i] = *reinterpret_cast<const uint2*>(B + (size_t)(colBase + r) * K + kc + c4 * 4);
    }
}
__device__ __forceinline__ void sts_tile(
    uint32_t* __restrict__ sA, uint32_t* __restrict__ sB,
    int tid, const uint2* pa, const uint2* pb)
{
    #pragma unroll
    for (int i = 0; i < 4; i++) {
        int id = i * 256 + tid;
        int r = id >> 3, c4 = id & 7;
        int kstep = c4 >> 2;
        int pl = (c4 & 3) * 2;
        int mtile = r >> 4, ri = r & 15;
        int regA = ((pl & 4) ? 2 : 0) + (ri >> 3);
        int laneA = (ri & 7) * 4 + (pl & 3);
        int baseA = (kstep * 8 + mtile) * 128;
        sA[baseA + laneA * 4 + regA]       = pa[i].x;
        sA[baseA + (laneA + 1) * 4 + regA] = pa[i].y;
        int ntile = r >> 3, ni = r & 7;
        int regB = (pl & 4) ? 1 : 0;
        int laneB = ni * 4 + (pl & 3);
        int baseB = (kstep * 16 + ntile) * 64;
        sB[baseB + laneB * 2 + regB]       = pb[i].x;
        sB[baseB + (laneB + 1) * 2 + regB] = pb[i].y;
    }
}

template <int H>
__global__ __launch_bounds__(256) void k_ee_logits(
    const __half* __restrict__ A, const __half* __restrict__ B,
    const float* __restrict__ att)
{
    __shared__ uint32_t sm[4096];
    int tid = threadIdx.x;
    int wid = tid >> 5, lane = tid & 31;
    int mw = wid & 3, nw = wid >> 2;
    int gid = lane >> 2, tig = lane & 3;
    int rowBase = blockIdx.y * 128, colBase = blockIdx.x * 128;

    float acc[2][8][4];
    #pragma unroll
    for (int mt = 0; mt < 2; mt++)
        #pragma unroll
        for (int nt = 0; nt < 8; nt++)
            #pragma unroll
            for (int q = 0; q < 4; q++) acc[mt][nt][q] = 0.f;

    uint2 pa[4], pb[4];
    ldg_tile_h(A, B, DEDGE, rowBase, colBase, 0, tid, pa, pb);
    sts_tile(sm, sm + 2048, tid, pa, pb);
    __syncthreads();

    #pragma unroll
    for (int kstep = 0; kstep < 2; kstep++) {
        uint4 afr[2];
        #pragma unroll
        for (int mt = 0; mt < 2; mt++)
            afr[mt] = *reinterpret_cast<const uint4*>(
                sm + (kstep * 8 + mw * 2 + mt) * 128 + lane * 4);
        uint2 bfr[8];
        #pragma unroll
        for (int nt = 0; nt < 8; nt++)
            bfr[nt] = *reinterpret_cast<const uint2*>(
                sm + 2048 + (kstep * 16 + nw * 8 + nt) * 64 + lane * 2);
        #pragma unroll
        for (int mt = 0; mt < 2; mt++)
            #pragma unroll
            for (int nt = 0; nt < 8; nt++)
                mma_f16(acc[mt][nt], afr[mt], bfr[nt]);
    }

    int h = colBase >> 8;
    int q = ((blockIdx.x & 1) << 1) | nw;
    const int HCH = H * (CC / 2);
    const __half2* xl = reinterpret_cast<const __half2*>(g_xl);
    const __half2* xr = reinterpret_cast<const __half2*>(g_xr);

    #pragma unroll
    for (int mt = 0; mt < 2; mt++) {
        int e0 = rowBase + mw * 32 + mt * 16 + gid;
        int e1 = e0 + 8;
        int s0 = g_psrc[e0], d0 = g_pdst[e0];
        int s1 = g_psrc[e1], d1 = g_pdst[e1];
        float p0 = 0.f, p1 = 0.f;
        #pragma unroll
        for (int nt = 0; nt < 8; nt++) {
            int col = colBase + nw * 64 + nt * 8 + tig * 2;
            int c2i = col >> 1;
            float2 at = *reinterpret_cast<const float2*>(att + h * CC + (col & (CC - 1)));
            float2 a0 = __half22float2(xl[(size_t)s0 * HCH + c2i]);
            float2 b0 = __half22float2(xr[(size_t)d0 * HCH + c2i]);
            float2 a1 = __half22float2(xl[(size_t)s1 * HCH + c2i]);
            float2 b1 = __half22float2(xr[(size_t)d1 * HCH + c2i]);
            float v0 = acc[mt][nt][0] + a0.x + b0.x;
            float v1 = acc[mt][nt][1] + a0.y + b0.y;
            float v2 = acc[mt][nt][2] + a1.x + b1.x;
            float v3 = acc[mt][nt][3] + a1.y + b1.y;
            v0 = (v0 > 0.f) ? v0 : NEG_SLOPE * v0;
            v1 = (v1 > 0.f) ? v1 : NEG_SLOPE * v1;
            v2 = (v2 > 0.f) ? v2 : NEG_SLOPE * v2;
            v3 = (v3 > 0.f) ? v3 : NEG_SLOPE * v3;
            p0 += v0 * at.x + v1 * at.y;
            p1 += v2 * at.x + v3 * at.y;
        }
        p0 += __shfl_xor_sync(0xffffffffu, p0, 1);
        p0 += __shfl_xor_sync(0xffffffffu, p0, 2);
        p1 += __shfl_xor_sync(0xffffffffu, p1, 1);
        p1 += __shfl_xor_sync(0xffffffffu, p1, 2);
        if (tig == 0) {
            g_logits[(e0 * H + h) * 4 + q] = p0;
            g_logits[(e1 * H + h) * 4 + q] = p1;
        }
    }
}

// ---------------- weight / input conversion ----------------
__global__ void k_wconv(const float* __restrict__ Wl1, const float* __restrict__ Wr1,
                        const float* __restrict__ Wl2, const float* __restrict__ Wr2,
                        const float* __restrict__ We1, const float* __restrict__ We2,
                        const float* __restrict__ x)
{
    int t = blockIdx.x * blockDim.x + threadIdx.x;
    const int s1 = HC1 * DNODE;
    const int s2 = HC2 * HC1;
    const int s3 = HC1 * DEDGE;
    const int s4 = HC2 * DEDGE;
    if (t < s1) { g_w1h[t] = __float2half_rn(Wl1[t]); g_w1h[s1 + t] = __float2half_rn(Wr1[t]); }
    if (t < s2) { g_w2h[t] = __float2half_rn(Wl2[t]); g_w2h[s2 + t] = __float2half_rn(Wr2[t]); }
    if (t < s3) g_we1h[t] = __float2half_rn(We1[t]);
    if (t < s4) g_we2h[t] = __float2half_rn(We2[t]);
    if (t < NN * DNODE) g_xh[t] = __float2half_rn(x[t]);
}

// ---------------- index / graph prep ----------------
__global__ void k_detect(const int* __restrict__ ei) {
    int is64 = 1;
    for (int i = 0; i < 16; i++)
        if (ei[2 * i + 1] != 0) is64 = 0;
    g_is64 = is64;
}
__global__ void k_norm_idx(const int* __restrict__ ei, const int* __restrict__ batch) {
    int t = blockIdx.x * blockDim.x + threadIdx.x;
    int is64 = g_is64;
    if (t < EE) {
        g_src[t] = is64 ? ei[2 * t]        : ei[t];
        g_dst[t] = is64 ? ei[2 * (EE + t)] : ei[EE + t];
    }
    if (t < NN) g_batch[t] = is64 ? batch[2 * t] : batch[t];
}
__global__ void k_zero() {
    int t = blockIdx.x * blockDim.x + threadIdx.x;
    if (t < NN) { g_deg[t] = 0; g_cur[t] = 0; }
    if (t < NN * DEDGE) g_easum[t] = 0.f;
    if (t < GG * HC2) g_pool[t] = 0.f;
    if (t < GG) g_cnt[t] = 0.f;
}
__global__ void k_deg_easum(const float* __restrict__ ea) {
    int t = blockIdx.x * blockDim.x + threadIdx.x;
    if (t >= EE * DEDGE) return;
    int e = t >> 5, d = t & 31;
    int dst = g_dst[e];
    atomicAdd(&g_easum[dst * DEDGE + d], ea[t]);
    if (d == 0) atomicAdd(&g_deg[dst], 1);
}
__global__ void k_scan() {
    __shared__ int part[256];
    int t = threadIdx.x;
    int base = t * 32;
    int loc[32];
    int s = 0;
    #pragma unroll
    for (int i = 0; i < 32; i++) { loc[i] = s; s += g_deg[base + i] + 1; }
    part[t] = s;
    __syncthreads();
    if (t == 0) {
        int acc = 0;
        for (int i = 0; i < 256; i++) { int v = part[i]; part[i] = acc; acc += v; }
        g_off[NN] = acc;
    }
    __syncthreads();
    int p = part[t];
    #pragma unroll
    for (int i = 0; i < 32; i++) g_off[base + i] = p + loc[i];
}
__global__ void k_csr() {
    int e = blockIdx.x * blockDim.x + threadIdx.x;
    if (e >= ET) return;
    int s, node;
    if (e < EE) { s = g_src[e]; node = g_dst[e]; } else { s = node = e - EE; }
    int pos = g_off[node] + atomicAdd(&g_cur[node], 1);
    g_pos[e]   = pos;
    g_psrc[pos] = s;
    g_pdst[pos] = node;
}
// ea2 in csr order (runs after k_csr)
__global__ void k_ea2(const float* __restrict__ ea) {
    int t = blockIdx.x * blockDim.x + threadIdx.x;
    if (t >= ET * DEDGE) return;
    int e = t >> 5, d = t & 31;
    float v;
    if (e < EE) {
        v = ea[t];
    } else {
        int n = e - EE;
        v = g_easum[n * DEDGE + d] / fmaxf((float)g_deg[n], 1.f);
    }
    g_ea2h[g_pos[e] * DEDGE + d] = __float2half_rn(v);
}

// ---------------- fp32 SGEMM for the tiny MLP ----------------
__global__ __launch_bounds__(256) void k_sgemm(
    const float* __restrict__ A, const float* __restrict__ Bm,
    const float* __restrict__ bias, float* __restrict__ Cm,
    int M, int Nc, int K, int act)
{
    constexpr int BM = 128, BN = 128, BK = 16, TM = 8, TN = 8;
    __shared__ float As[BK][BM];
    __shared__ float Bs[BK][BN];
    int tid = threadIdx.x;
    int tx = tid % 16, ty = tid / 16;
    int rowBase = blockIdx.y * BM;
    int colBase = blockIdx.x * BN;
    float acc[TM][TN];
    #pragma unroll
    for (int i = 0; i < TM; i++)
        #pragma unroll
        for (int j = 0; j < TN; j++) acc[i][j] = 0.f;
    for (int k0 = 0; k0 < K; k0 += BK) {
        #pragma unroll
        for (int i = 0; i < 2; i++) {
            int f4 = tid + i * 256;
            int r = f4 >> 2;
            int kk = (f4 & 3) * 4;
            int gr = rowBase + r;
            float4 v = make_float4(0.f, 0.f, 0.f, 0.f);
            if (gr < M) v = *reinterpret_cast<const float4*>(A + (size_t)gr * K + k0 + kk);
            As[kk + 0][r] = v.x; As[kk + 1][r] = v.y; As[kk + 2][r] = v.z; As[kk + 3][r] = v.w;
            int gc = colBase + r;
            float4 w = make_float4(0.f, 0.f, 0.f, 0.f);
            if (gc < Nc) w = *reinterpret_cast<const float4*>(Bm + (size_t)gc * K + k0 + kk);
            Bs[kk + 0][r] = w.x; Bs[kk + 1][r] = w.y; Bs[kk + 2][r] = w.z; Bs[kk + 3][r] = w.w;
        }
        __syncthreads();
        #pragma unroll
        for (int k = 0; k < BK; k++) {
            float a[TM], b[TN];
            #pragma unroll
            for (int i = 0; i < TM; i++) a[i] = As[k][ty * TM + i];
            #pragma unroll
            for (int j = 0; j < TN; j++) b[j] = Bs[k][tx * TN + j];
            #pragma unroll
            for (int i = 0; i < TM; i++)
                #pragma unroll
                for (int j = 0; j < TN; j++) acc[i][j] = fmaf(a[i], b[j], acc[i][j]);
        }
        __syncthreads();
    }
    #pragma unroll
    for (int i = 0; i < TM; i++) {
        int gr = rowBase + ty * TM + i;
        if (gr >= M) continue;
        #pragma unroll
        for (int j = 0; j < TN; j++) {
            int gc = colBase + tx * TN + j;
            if (gc >= Nc) continue;
            float v = acc[i][j];
            if (bias) v += bias[gc];
            if (act) v = fmaxf(v, 0.f);
            Cm[(size_t)gr * Nc + gc] = v;
        }
    }
}

// ---------------- segment softmax + weighted gather (csr order) ----------------
template <int H, int RELU, int OUTH>
__global__ void k_aggregate(const float* __restrict__ bias, void* __restrict__ out) {
    int n = blockIdx.x;
    int h = threadIdx.x >> 5, lane = threadIdx.x & 31;
    int s0 = g_off[n], s1 = g_off[n + 1];
    int cnt = s1 - s0;
    const int HCH = H * (CC / 2);
    const __half2* xl = reinterpret_cast<const __half2*>(g_xl);
    float2 acc[4];
    #pragma unroll
    for (int j = 0; j < 4; j++) acc[j] = make_float2(0.f, 0.f);

    if (cnt <= 64) {
        int cs0 = 0, cs1 = 0;
        float lv0 = -1e30f, lv1 = -1e30f;
        if (lane < cnt) {
            int p = s0 + lane;
            cs0 = g_psrc[p];
            float4 lg = *reinterpret_cast<const float4*>(&g_logits[(p * H + h) * 4]);
            lv0 = (lg.x + lg.y) + (lg.z + lg.w);
        }
        if (lane + 32 < cnt) {
            int p = s0 + lane + 32;
            cs1 = g_psrc[p];
            float4 lg = *reinterpret_cast<const float4*>(&g_logits[(p * H + h) * 4]);
            lv1 = (lg.x + lg.y) + (lg.z + lg.w);
        }
        float mx = warp_max(fmaxf(lv0, lv1));
        float ex0 = (lane < cnt)      ? __expf(lv0 - mx) : 0.f;
        float ex1 = (lane + 32 < cnt) ? __expf(lv1 - mx) : 0.f;
        float inv = 1.f / warp_sum(ex0 + ex1);
        for (int i = 0; i < cnt; i++) {
            int srcl = i & 31;
            float w = __shfl_sync(0xffffffffu, (i < 32) ? ex0 : ex1, srcl) * inv;
            int s = __shfl_sync(0xffffffffu, (i < 32) ? cs0 : cs1, srcl);
            const __half2* row = xl + (size_t)s * HCH + h * 128 + lane;
            #pragma unroll
            for (int j = 0; j < 4; j++) {
                float2 f = __half22float2(row[32 * j]);
                acc[j].x = fmaf(w, f.x, acc[j].x);
                acc[j].y = fmaf(w, f.y, acc[j].y);
            }
        }
    } else {
        float mx = -1e30f;
        for (int i = s0 + lane; i < s1; i += 32) {
            float4 lg = *reinterpret_cast<const float4*>(&g_logits[(i * H + h) * 4]);
            mx = fmaxf(mx, (lg.x + lg.y) + (lg.z + lg.w));
        }
        mx = warp_max(mx);
        float den = 0.f;
        for (int i = s0 + lane; i < s1; i += 32) {
            float4 lg = *reinterpret_cast<const float4*>(&g_logits[(i * H + h) * 4]);
            den += __expf((lg.x + lg.y) + (lg.z + lg.w) - mx);
        }
        den = warp_sum(den);
        float inv = 1.f / den;
        for (int i = s0; i < s1; i++) {
            float4 lg = *reinterpret_cast<const float4*>(&g_logits[(i * H + h) * 4]);
            float w = __expf((lg.x + lg.y) + (lg.z + lg.w) - mx) * inv;
            int s = g_psrc[i];
            const __half2* row = xl + (size_t)s * HCH + h * 128 + lane;
            #pragma unroll
            for (int j = 0; j < 4; j++) {
                float2 f = __half22float2(row[32 * j]);
                acc[j].x = fmaf(w, f.x, acc[j].x);
                acc[j].y = fmaf(w, f.y, acc[j].y);
            }
        }
    }

    #pragma unroll
    for (int j = 0; j < 4; j++) {
        int col = h * CC + 2 * (lane + 32 * j);
        float2 b = *reinterpret_cast<const float2*>(bias + col);
        float v0 = acc[j].x + b.x, v1 = acc[j].y + b.y;
        if (RELU) { v0 = fmaxf(v0, 0.f); v1 = fmaxf(v1, 0.f); }
        if (OUTH) {
            __half* oh = (__half*)out;
            *reinterpret_cast<__half2*>(oh + (size_t)n * (H * CC) + col) = __floats2half2_rn(v0, v1);
        } else {
            float* of = (float*)out;
            *reinterpret_cast<float2*>(of + (size_t)n * (H * CC) + col) = make_float2(v0, v1);
        }
    }
}

// ---------------- pooling + final ----------------
__global__ void k_pool() {
    int t = blockIdx.x * blockDim.x + threadIdx.x;
    if (t >= NN * HC2) return;
    int n = t >> 10, c = t & 1023;
    int b = g_batch[n];
    atomicAdd(&g_pool[b * HC2 + c], g_h2[t]);
    if (c == 0) atomicAdd(&g_cnt[b], 1.f);
}
__global__ void k_pool_div() {
    int t = blockIdx.x * blockDim.x + threadIdx.x;
    if (t >= GG * HC2) return;
    g_pool[t] /= fmaxf(g_cnt[t >> 10], 1.f);
}
__global__ void k_final(const float* __restrict__ W3, const float* __restrict__ b3,
                        float* __restrict__ out) {
    int g = blockIdx.x, lane = threadIdx.x;
    float acc = 0.f;
    #pragma unroll
    for (int j = 0; j < 8; j++) acc += g_m2[g * 256 + lane + 32 * j] * W3[lane + 32 * j];
    acc = warp_sum(acc);
    if (lane == 0) out[g] = 1.f / (1.f + expf(-(acc + b3[0])));
}

// ---------------- host launch ----------------
static inline void launch_sgemm(const float* A, const float* B, const float* bias,
                                float* C, int M, int Nc, int K, int act) {
    dim3 grid((Nc + 127) / 128, (M + 127) / 128);
    k_sgemm<<<grid, 256>>>(A, B, bias, C, M, Nc, K, act);
}

extern "C" void kernel_launch(void* const* d_in, const int* in_sizes, int n_in,
                              void* d_out, int out_size) {
    const float* x     = (const float*)d_in[0];
    const int*   ei    = (const int*)  d_in[1];
    const float* ea    = (const float*)d_in[2];
    const int*   batch = (const int*)  d_in[3];
    const float* Wl1 = (const float*)d_in[4],  *bl1 = (const float*)d_in[5];
    const float* Wr1 = (const float*)d_in[6],  *br1 = (const float*)d_in[7];
    const float* We1 = (const float*)d_in[8],  *att1 = (const float*)d_in[9];
    const float* bias1 = (const float*)d_in[10];
    const float* Wl2 = (const float*)d_in[11], *bl2 = (const float*)d_in[12];
    const float* Wr2 = (const float*)d_in[13], *br2 = (const float*)d_in[14];
    const float* We2 = (const float*)d_in[15], *att2 = (const float*)d_in[16];
    const float* bias2 = (const float*)d_in[17];
    const float* W1 = (const float*)d_in[18], *b1 = (const float*)d_in[19];
    const float* W2 = (const float*)d_in[20], *b2 = (const float*)d_in[21];
    const float* W3 = (const float*)d_in[22], *b3 = (const float*)d_in[23];
    float* out = (float*)d_out;

    cudaFuncSetAttribute(k_mma_dual, cudaFuncAttributeMaxDynamicSharedMemorySize, GEMM_SMEM_BYTES);

    float *p_h2, *p_pool, *p_m1, *p_m2;
    __half *p_xl, *p_xr, *p_h1h, *p_ea2h, *p_w1h, *p_w2h, *p_we1h, *p_we2h, *p_xh;
    cudaGetSymbolAddress((void**)&p_xl,    g_xl);
    cudaGetSymbolAddress((void**)&p_xr,    g_xr);
    cudaGetSymbolAddress((void**)&p_h1h,   g_h1h);
    cudaGetSymbolAddress((void**)&p_ea2h,  g_ea2h);
    cudaGetSymbolAddress((void**)&p_w1h,   g_w1h);
    cudaGetSymbolAddress((void**)&p_w2h,   g_w2h);
    cudaGetSymbolAddress((void**)&p_we1h,  g_we1h);
    cudaGetSymbolAddress((void**)&p_we2h,  g_we2h);
    cudaGetSymbolAddress((void**)&p_xh,    g_xh);
    cudaGetSymbolAddress((void**)&p_h2,    g_h2);
    cudaGetSymbolAddress((void**)&p_pool,  g_pool);
    cudaGetSymbolAddress((void**)&p_m1,    g_m1);
    cudaGetSymbolAddress((void**)&p_m2,    g_m2);

    // --- prep (launch index 3 = layer-1 k_mma_dual for ncu capture) ---
    k_detect<<<1, 1>>>(ei);                                                  // 0
    k_wconv<<<(HC2 * HC1 + 255) / 256, 256>>>(Wl1, Wr1, Wl2, Wr2, We1, We2, x); // 1
    k_norm_idx<<<(EE + 255) / 256, 256>>>(ei, batch);                        // 2
    k_mma_dual<<<dim3(2 * HC1 / 128, NN / 128), 256, GEMM_SMEM_BYTES>>>(     // 3 <- ncu
        p_xh, p_w1h, bl1, br1, p_xl, p_xr, NN, 2 * HC1, DNODE);
    k_zero<<<(NN * DEDGE + 255) / 256, 256>>>();                             // 4
    k_deg_easum<<<(EE * DEDGE + 255) / 256, 256>>>(ea);                      // 5
    k_scan<<<1, 256>>>();                                                    // 6
    k_csr<<<(ET + 255) / 256, 256>>>();                                      // 7
    k_ea2<<<(ET * DEDGE + 255) / 256, 256>>>(ea);                            // 8

    // --- GATv2 layer 1 ---
    k_ee_logits<H1C><<<dim3(HC1 / 128, ET / 128), 256>>>(p_ea2h, p_we1h, att1);
    k_aggregate<H1C, 1, 1><<<NN, H1C * 32>>>(bias1, p_h1h);

    // --- GATv2 layer 2 ---
    k_mma_dual<<<dim3(2 * HC2 / 128, NN / 128), 256, GEMM_SMEM_BYTES>>>(
        p_h1h, p_w2h, bl2, br2, p_xl, p_xr, NN, 2 * HC2, HC1);
    k_ee_logits<H2C><<<dim3(HC2 / 128, ET / 128), 256>>>(p_ea2h, p_we2h, att2);
    k_aggregate<H2C, 0, 0><<<NN, H2C * 32>>>(bias2, p_h2);

    // --- pool + MLP ---
    k_pool<<<(NN * HC2 + 255) / 256, 256>>>();
    k_pool_div<<<(GG * HC2 + 255) / 256, 256>>>();
    launch_sgemm(p_pool, W1, b1, p_m1, GG, 512, HC2, 1);
    launch_sgemm(p_m1,  W2, b2, p_m2, GG, 256, 512, 1);
    k_final<<<GG, 32>>>(W3, b3, out);
}

// round 10
// speedup vs baseline: 4.2245x; 1.0091x over previous
#include <cuda_runtime.h>
#include <cuda_fp16.h>
#include <math.h>
#include <stdint.h>

// ---------------- problem constants ----------------
#define NN   8192
#define EE   65536
#define GG   64
#define DNODE 64
#define DEDGE 32
#define CC   256
#define H1C  8
#define H2C  4
#define ET   (EE + NN)          // 73728 = 576*128
#define HC1  (H1C * CC)         // 2048
#define HC2  (H2C * CC)         // 1024
#define NEG_SLOPE 0.2f

// ---------------- device scratch ----------------
__device__ int    g_is64;
__device__ int    g_src[EE];
__device__ int    g_dst[EE];
__device__ int    g_batch[NN];
__device__ int    g_deg[NN];
__device__ int    g_cur[NN];
__device__ int    g_off[NN + 1];
__device__ int    g_pedge[ET];               // csr position -> edge id
__device__ int    g_psrc[ET];                // csr position -> src node
__device__ int    g_pdst[ET];                // csr position -> dst node
__device__ float  g_easum[NN * DEDGE];
__device__ __half g_ea2h[ET * DEDGE];        // csr-ordered edge attrs
__device__ __half g_xh[NN * DNODE];
__device__ __half g_xl[NN * HC1];
__device__ __half g_xr[NN * HC1];
__device__ __half g_h1h[NN * HC1];
__device__ float  g_logits[ET * H1C * 4];    // csr-ordered, 4 partials per (pos,h)
__device__ float  g_pool[GG * HC2];
__device__ float  g_cnt[GG];
__device__ float  g_m1[GG * 512];
__device__ float  g_m2[GG * 256];
__device__ __half g_w1h[2 * HC1 * DNODE];
__device__ __half g_w2h[2 * HC2 * HC1];
__device__ __half g_we1h[HC1 * DEDGE];
__device__ __half g_we2h[HC2 * DEDGE];

// ---------------- helpers ----------------
__device__ __forceinline__ float warp_sum(float v) {
    #pragma unroll
    for (int o = 16; o; o >>= 1) v += __shfl_xor_sync(0xffffffffu, v, o);
    return v;
}
__device__ __forceinline__ float warp_max(float v) {
    #pragma unroll
    for (int o = 16; o; o >>= 1) v = fmaxf(v, __shfl_xor_sync(0xffffffffu, v, o));
    return v;
}
__device__ __forceinline__ uint32_t smem_u32(const void* p) {
    uint32_t a;
    asm("{ .reg .u64 t; cvta.to.shared.u64 t, %1; cvt.u32.u64 %0, t; }" : "=r"(a) : "l"(p));
    return a;
}
__device__ __forceinline__ void mma_f16(float* c, uint4 a, uint2 b) {
    asm volatile(
        "mma.sync.aligned.m16n8k16.row.col.f32.f16.f16.f32 "
        "{%0,%1,%2,%3},{%4,%5,%6,%7},{%8,%9},{%0,%1,%2,%3};"
        : "+f"(c[0]), "+f"(c[1]), "+f"(c[2]), "+f"(c[3])
        : "r"(a.x), "r"(a.y), "r"(a.z), "r"(a.w), "r"(b.x), "r"(b.y));
}
__device__ __forceinline__ uint4 ldsm4(uint32_t addr) {
    uint4 r;
    asm volatile("ldmatrix.sync.aligned.m8n8.x4.shared.b16 {%0,%1,%2,%3}, [%4];"
        : "=r"(r.x), "=r"(r.y), "=r"(r.z), "=r"(r.w) : "r"(addr));
    return r;
}
__device__ __forceinline__ void cp16(uint32_t dst, const void* src) {
    asm volatile("cp.async.cg.shared.global [%0], [%1], 16;" :: "r"(dst), "l"(src));
}

// =================================================================
// cp.async + ldmatrix fp16 GEMM (3-stage, XOR swizzle) — proven R7-9.
// =================================================================
#define GEMM_STAGE_BYTES 32768
#define GEMM_SMEM_BYTES  (3 * GEMM_STAGE_BYTES)

__device__ __forceinline__ void issue_stage(
    const __half* __restrict__ A, const __half* __restrict__ B, int K,
    int rowBase, int colBase, int k0, uint32_t abase, int tid)
{
    #pragma unroll
    for (int i = 0; i < 4; i++) {
        int id = i * 256 + tid;
        int r = id >> 3, c = id & 7;
        uint32_t off = (uint32_t)(r * 128 + ((c ^ (r & 7)) << 4));
        cp16(abase + off,         A + (size_t)(rowBase + r) * K + k0 + c * 8);
        cp16(abase + 16384 + off, B + (size_t)(colBase + r) * K + k0 + c * 8);
    }
    asm volatile("cp.async.commit_group;" ::: "memory");
}

__global__ __launch_bounds__(256, 2) void k_mma_dual(
    const __half* __restrict__ A, const __half* __restrict__ B,
    const float* __restrict__ biasL, const float* __restrict__ biasR,
    __half* __restrict__ outL, __half* __restrict__ outR,
    int M, int N, int K)
{
    extern __shared__ char smem[];
    uint32_t sb = smem_u32(smem);
    int tid = threadIdx.x;
    int wid = tid >> 5, lane = tid & 31;
    int mw = wid & 3, nw = wid >> 2;
    int gid = lane >> 2, tig = lane & 3;
    int rowBase = blockIdx.y * 128, colBase = blockIdx.x * 128;

    float acc[2][8][4];
    #pragma unroll
    for (int mt = 0; mt < 2; mt++)
        #pragma unroll
        for (int nt = 0; nt < 8; nt++)
            #pragma unroll
            for (int q = 0; q < 4; q++) acc[mt][nt][q] = 0.f;

    const int NCH = K >> 6;
    issue_stage(A, B, K, rowBase, colBase, 0, sb, tid);
    if (NCH > 1) issue_stage(A, B, K, rowBase, colBase, 64, sb + GEMM_STAGE_BYTES, tid);

    int arow = mw * 32 + (lane & 15);
    int achoff = lane >> 4;
    int brow = nw * 64 + ((lane >> 4) << 3) + (lane & 7);
    int bchoff = (lane >> 3) & 1;

    for (int c = 0; c < NCH; c++) {
        if (c + 2 <= NCH) asm volatile("cp.async.wait_group 1;" ::: "memory");
        else              asm volatile("cp.async.wait_group 0;" ::: "memory");
        __syncthreads();
        if (c + 2 < NCH)
            issue_stage(A, B, K, rowBase, colBase, (c + 2) << 6,
                        sb + ((c + 2) % 3) * GEMM_STAGE_BYTES, tid);

        uint32_t Ab = sb + (c % 3) * GEMM_STAGE_BYTES;
        uint32_t Bb = Ab + 16384;
        #pragma unroll
        for (int kstep = 0; kstep < 4; kstep++) {
            uint4 afr[2];
            #pragma unroll
            for (int mt = 0; mt < 2; mt++) {
                int row = arow + mt * 16;
                int ch = kstep * 2 + achoff;
                afr[mt] = ldsm4(Ab + row * 128 + ((ch ^ (row & 7)) << 4));
            }
            uint2 bfr[8];
            #pragma unroll
            for (int ntp = 0; ntp < 4; ntp++) {
                int row = brow + ntp * 16;
                int ch = kstep * 2 + bchoff;
                uint4 t = ldsm4(Bb + row * 128 + ((ch ^ (row & 7)) << 4));
                bfr[2 * ntp]     = make_uint2(t.x, t.y);
                bfr[2 * ntp + 1] = make_uint2(t.z, t.w);
            }
            #pragma unroll
            for (int mt = 0; mt < 2; mt++)
                #pragma unroll
                for (int nt = 0; nt < 8; nt++)
                    mma_f16(acc[mt][nt], afr[mt], bfr[nt]);
        }
    }

    int halfN = N >> 1;
    bool isR = (colBase >= halfN);
    const float* bias = isR ? biasR : biasL;
    __half* outp = isR ? outR : outL;
    int cb = colBase - (isR ? halfN : 0);

    #pragma unroll
    for (int mt = 0; mt < 2; mt++) {
        int row0 = rowBase + mw * 32 + mt * 16 + gid;
        #pragma unroll
        for (int nt = 0; nt < 8; nt++) {
            int col = cb + nw * 64 + nt * 8 + tig * 2;
            float b0 = bias[col], b1 = bias[col + 1];
            float c0 = acc[mt][nt][0] + b0, c1 = acc[mt][nt][1] + b1;
            float c2 = acc[mt][nt][2] + b0, c3 = acc[mt][nt][3] + b1;
            *reinterpret_cast<__half2*>(outp + (size_t)row0 * halfN + col)       = __floats2half2_rn(c0, c1);
            *reinterpret_cast<__half2*>(outp + (size_t)(row0 + 8) * halfN + col) = __floats2half2_rn(c2, c3);
        }
    }
}

// =================================================================
// Fused edge-feature GEMM + logits (csr-ordered edges).
// =================================================================
__device__ __forceinline__ void ldg_tile_h(
    const __half* __restrict__ A, const __half* __restrict__ B, int K,
    int rowBase, int colBase, int kc, int tid, uint2* pa, uint2* pb)
{
    #pragma unroll
    for (int i = 0; i < 4; i++) {
        int id = i * 256 + tid;
        int r = id >> 3, c4 = id & 7;
        pa[i] = *reinterpret_cast<const uint2*>(A + (size_t)(rowBase + r) * K + kc + c4 * 4);
        pb[i] = *reinterpret_cast<const uint2*>(B + (size_t)(colBase + r) * K + kc + c4 * 4);
    }
}
__device__ __forceinline__ void sts_tile(
    uint32_t* __restrict__ sA, uint32_t* __restrict__ sB,
    int tid, const uint2* pa, const uint2* pb)
{
    #pragma unroll
    for (int i = 0; i < 4; i++) {
        int id = i * 256 + tid;
        int r = id >> 3, c4 = id & 7;
        int kstep = c4 >> 2;
        int pl = (c4 & 3) * 2;
        int mtile = r >> 4, ri = r & 15;
        int regA = ((pl & 4) ? 2 : 0) + (ri >> 3);
        int laneA = (ri & 7) * 4 + (pl & 3);
        int baseA = (kstep * 8 + mtile) * 128;
        sA[baseA + laneA * 4 + regA]       = pa[i].x;
        sA[baseA + (laneA + 1) * 4 + regA] = pa[i].y;
        int ntile = r >> 3, ni = r & 7;
        int regB = (pl & 4) ? 1 : 0;
        int laneB = ni * 4 + (pl & 3);
        int baseB = (kstep * 16 + ntile) * 64;
        sB[baseB + laneB * 2 + regB]       = pb[i].x;
        sB[baseB + (laneB + 1) * 2 + regB] = pb[i].y;
    }
}

template <int H>
__global__ __launch_bounds__(256) void k_ee_logits(
    const __half* __restrict__ A, const __half* __restrict__ B,
    const float* __restrict__ att)
{
    __shared__ uint32_t sm[4096];
    int tid = threadIdx.x;
    int wid = tid >> 5, lane = tid & 31;
    int mw = wid & 3, nw = wid >> 2;
    int gid = lane >> 2, tig = lane & 3;
    int rowBase = blockIdx.y * 128, colBase = blockIdx.x * 128;

    float acc[2][8][4];
    #pragma unroll
    for (int mt = 0; mt < 2; mt++)
        #pragma unroll
        for (int nt = 0; nt < 8; nt++)
            #pragma unroll
            for (int q = 0; q < 4; q++) acc[mt][nt][q] = 0.f;

    uint2 pa[4], pb[4];
    ldg_tile_h(A, B, DEDGE, rowBase, colBase, 0, tid, pa, pb);
    sts_tile(sm, sm + 2048, tid, pa, pb);
    __syncthreads();

    #pragma unroll
    for (int kstep = 0; kstep < 2; kstep++) {
        uint4 afr[2];
        #pragma unroll
        for (int mt = 0; mt < 2; mt++)
            afr[mt] = *reinterpret_cast<const uint4*>(
                sm + (kstep * 8 + mw * 2 + mt) * 128 + lane * 4);
        uint2 bfr[8];
        #pragma unroll
        for (int nt = 0; nt < 8; nt++)
            bfr[nt] = *reinterpret_cast<const uint2*>(
                sm + 2048 + (kstep * 16 + nw * 8 + nt) * 64 + lane * 2);
        #pragma unroll
        for (int mt = 0; mt < 2; mt++)
            #pragma unroll
            for (int nt = 0; nt < 8; nt++)
                mma_f16(acc[mt][nt], afr[mt], bfr[nt]);
    }

    int h = colBase >> 8;
    int q = ((blockIdx.x & 1) << 1) | nw;
    const int HCH = H * (CC / 2);
    const __half2* xl = reinterpret_cast<const __half2*>(g_xl);
    const __half2* xr = reinterpret_cast<const __half2*>(g_xr);

    #pragma unroll
    for (int mt = 0; mt < 2; mt++) {
        int e0 = rowBase + mw * 32 + mt * 16 + gid;
        int e1 = e0 + 8;
        int s0 = g_psrc[e0], d0 = g_pdst[e0];
        int s1 = g_psrc[e1], d1 = g_pdst[e1];
        float p0 = 0.f, p1 = 0.f;
        #pragma unroll
        for (int nt = 0; nt < 8; nt++) {
            int col = colBase + nw * 64 + nt * 8 + tig * 2;
            int c2i = col >> 1;
            float2 at = *reinterpret_cast<const float2*>(att + h * CC + (col & (CC - 1)));
            float2 a0 = __half22float2(xl[(size_t)s0 * HCH + c2i]);
            float2 b0 = __half22float2(xr[(size_t)d0 * HCH + c2i]);
            float2 a1 = __half22float2(xl[(size_t)s1 * HCH + c2i]);
            float2 b1 = __half22float2(xr[(size_t)d1 * HCH + c2i]);
            float v0 = acc[mt][nt][0] + a0.x + b0.x;
            float v1 = acc[mt][nt][1] + a0.y + b0.y;
            float v2 = acc[mt][nt][2] + a1.x + b1.x;
            float v3 = acc[mt][nt][3] + a1.y + b1.y;
            v0 = (v0 > 0.f) ? v0 : NEG_SLOPE * v0;
            v1 = (v1 > 0.f) ? v1 : NEG_SLOPE * v1;
            v2 = (v2 > 0.f) ? v2 : NEG_SLOPE * v2;
            v3 = (v3 > 0.f) ? v3 : NEG_SLOPE * v3;
            p0 += v0 * at.x + v1 * at.y;
            p1 += v2 * at.x + v3 * at.y;
        }
        p0 += __shfl_xor_sync(0xffffffffu, p0, 1);
        p0 += __shfl_xor_sync(0xffffffffu, p0, 2);
        p1 += __shfl_xor_sync(0xffffffffu, p1, 1);
        p1 += __shfl_xor_sync(0xffffffffu, p1, 2);
        if (tig == 0) {
            g_logits[(e0 * H + h) * 4 + q] = p0;
            g_logits[(e1 * H + h) * 4 + q] = p1;
        }
    }
}

// ---------------- weight / input conversion ----------------
__global__ void k_wconv(const float* __restrict__ Wl1, const float* __restrict__ Wr1,
                        const float* __restrict__ Wl2, const float* __restrict__ Wr2,
                        const float* __restrict__ We1, const float* __restrict__ We2,
                        const float* __restrict__ x)
{
    int t = blockIdx.x * blockDim.x + threadIdx.x;
    const int s1 = HC1 * DNODE;
    const int s2 = HC2 * HC1;
    const int s3 = HC1 * DEDGE;
    const int s4 = HC2 * DEDGE;
    if (t < s1) { g_w1h[t] = __float2half_rn(Wl1[t]); g_w1h[s1 + t] = __float2half_rn(Wr1[t]); }
    if (t < s2) { g_w2h[t] = __float2half_rn(Wl2[t]); g_w2h[s2 + t] = __float2half_rn(Wr2[t]); }
    if (t < s3) g_we1h[t] = __float2half_rn(We1[t]);
    if (t < s4) g_we2h[t] = __float2half_rn(We2[t]);
    if (t < NN * DNODE) g_xh[t] = __float2half_rn(x[t]);
}

// ---------------- graph prep ----------------
__global__ void k_detect(const int* __restrict__ ei) {
    int is64 = 1;
    for (int i = 0; i < 16; i++)
        if (ei[2 * i + 1] != 0) is64 = 0;
    g_is64 = is64;
}
// fused: index normalization + zeroing of accumulators
__global__ void k_prep(const int* __restrict__ ei, const int* __restrict__ batch) {
    int t = blockIdx.x * blockDim.x + threadIdx.x;
    int is64 = g_is64;
    if (t < EE) {
        g_src[t] = is64 ? ei[2 * t]        : ei[t];
        g_dst[t] = is64 ? ei[2 * (EE + t)] : ei[EE + t];
    }
    if (t < NN) {
        g_batch[t] = is64 ? batch[2 * t] : batch[t];
        g_deg[t] = 0;
        g_cur[t] = 0;
    }
    if (t < NN * DEDGE) g_easum[t] = 0.f;
    if (t < GG * HC2) g_pool[t] = 0.f;
}
__global__ void k_deg_easum(const float* __restrict__ ea) {
    int t = blockIdx.x * blockDim.x + threadIdx.x;
    if (t >= EE * DEDGE) return;
    int e = t >> 5, d = t & 31;
    int dst = g_dst[e];
    atomicAdd(&g_easum[dst * DEDGE + d], ea[t]);
    if (d == 0) atomicAdd(&g_deg[dst], 1);
}
// prefix scan of (deg+1) + per-graph node counts (batch is sorted)
__global__ void k_scan() {
    __shared__ int part[256];
    __shared__ int scnt[GG];
    int t = threadIdx.x;
    if (t < GG) scnt[t] = 0;
    __syncthreads();
    int base = t * 32;
    int loc[32];
    int s = 0;
    #pragma unroll
    for (int i = 0; i < 32; i++) {
        loc[i] = s; s += g_deg[base + i] + 1;
        atomicAdd(&scnt[g_batch[base + i]], 1);
    }
    part[t] = s;
    __syncthreads();
    if (t == 0) {
        int acc = 0;
        for (int i = 0; i < 256; i++) { int v = part[i]; part[i] = acc; acc += v; }
        g_off[NN] = acc;
    }
    __syncthreads();
    int p = part[t];
    #pragma unroll
    for (int i = 0; i < 32; i++) g_off[base + i] = p + loc[i];
    if (t < GG) g_cnt[t] = (float)scnt[t];
}
__global__ void k_csr() {
    int e = blockIdx.x * blockDim.x + threadIdx.x;
    if (e >= ET) return;
    int s, node;
    if (e < EE) { s = g_src[e]; node = g_dst[e]; } else { s = node = e - EE; }
    int pos = g_off[node] + atomicAdd(&g_cur[node], 1);
    g_pedge[pos] = e;
    g_psrc[pos]  = s;
    g_pdst[pos]  = node;
}
// ea2 in csr order, coalesced writes (iterate by position)
__global__ void k_ea2(const float* __restrict__ ea) {
    int t = blockIdx.x * blockDim.x + threadIdx.x;
    if (t >= ET * DEDGE) return;
    int pos = t >> 5, d = t & 31;
    int e = g_pedge[pos];
    float v;
    if (e < EE) {
        v = ea[e * DEDGE + d];
    } else {
        int n = e - EE;
        v = g_easum[n * DEDGE + d] / fmaxf((float)g_deg[n], 1.f);
    }
    g_ea2h[t] = __float2half_rn(v);
}

// ---------------- fp32 SGEMM for the tiny MLP ----------------
__global__ __launch_bounds__(256) void k_sgemm(
    const float* __restrict__ A, const float* __restrict__ Bm,
    const float* __restrict__ bias, float* __restrict__ Cm,
    int M, int Nc, int K, int act)
{
    constexpr int BM = 128, BN = 128, BK = 16, TM = 8, TN = 8;
    __shared__ float As[BK][BM];
    __shared__ float Bs[BK][BN];
    int tid = threadIdx.x;
    int tx = tid % 16, ty = tid / 16;
    int rowBase = blockIdx.y * BM;
    int colBase = blockIdx.x * BN;
    float acc[TM][TN];
    #pragma unroll
    for (int i = 0; i < TM; i++)
        #pragma unroll
        for (int j = 0; j < TN; j++) acc[i][j] = 0.f;
    for (int k0 = 0; k0 < K; k0 += BK) {
        #pragma unroll
        for (int i = 0; i < 2; i++) {
            int f4 = tid + i * 256;
            int r = f4 >> 2;
            int kk = (f4 & 3) * 4;
            int gr = rowBase + r;
            float4 v = make_float4(0.f, 0.f, 0.f, 0.f);
            if (gr < M) v = *reinterpret_cast<const float4*>(A + (size_t)gr * K + k0 + kk);
            As[kk + 0][r] = v.x; As[kk + 1][r] = v.y; As[kk + 2][r] = v.z; As[kk + 3][r] = v.w;
            int gc = colBase + r;
            float4 w = make_float4(0.f, 0.f, 0.f, 0.f);
            if (gc < Nc) w = *reinterpret_cast<const float4*>(Bm + (size_t)gc * K + k0 + kk);
            Bs[kk + 0][r] = w.x; Bs[kk + 1][r] = w.y; Bs[kk + 2][r] = w.z; Bs[kk + 3][r] = w.w;
        }
        __syncthreads();
        #pragma unroll
        for (int k = 0; k < BK; k++) {
            float a[TM], b[TN];
            #pragma unroll
            for (int i = 0; i < TM; i++) a[i] = As[k][ty * TM + i];
            #pragma unroll
            for (int j = 0; j < TN; j++) b[j] = Bs[k][tx * TN + j];
            #pragma unroll
            for (int i = 0; i < TM; i++)
                #pragma unroll
                for (int j = 0; j < TN; j++) acc[i][j] = fmaf(a[i], b[j], acc[i][j]);
        }
        __syncthreads();
    }
    #pragma unroll
    for (int i = 0; i < TM; i++) {
        int gr = rowBase + ty * TM + i;
        if (gr >= M) continue;
        #pragma unroll
        for (int j = 0; j < TN; j++) {
            int gc = colBase + tx * TN + j;
            if (gc >= Nc) continue;
            float v = acc[i][j];
            if (bias) v += bias[gc];
            if (act) v = fmaxf(v, 0.f);
            Cm[(size_t)gr * Nc + gc] = v;
        }
    }
}

// ---------------- segment softmax + weighted gather (csr order) ----------------
// OUTMODE: 0 = fp32 store, 1 = fp16 store, 2 = atomicAdd into g_pool
template <int H, int RELU, int OUTMODE>
__global__ void k_aggregate(const float* __restrict__ bias, void* __restrict__ out) {
    int n = blockIdx.x;
    int h = threadIdx.x >> 5, lane = threadIdx.x & 31;
    int s0 = g_off[n], s1 = g_off[n + 1];
    int cnt = s1 - s0;
    const int HCH = H * (CC / 2);
    const __half2* xl = reinterpret_cast<const __half2*>(g_xl);
    float2 acc[4];
    #pragma unroll
    for (int j = 0; j < 4; j++) acc[j] = make_float2(0.f, 0.f);

    if (cnt <= 64) {
        int cs0 = 0, cs1 = 0;
        float lv0 = -1e30f, lv1 = -1e30f;
        if (lane < cnt) {
            int p = s0 + lane;
            cs0 = g_psrc[p];
            float4 lg = *reinterpret_cast<const float4*>(&g_logits[(p * H + h) * 4]);
            lv0 = (lg.x + lg.y) + (lg.z + lg.w);
        }
        if (lane + 32 < cnt) {
            int p = s0 + lane + 32;
            cs1 = g_psrc[p];
            float4 lg = *reinterpret_cast<const float4*>(&g_logits[(p * H + h) * 4]);
            lv1 = (lg.x + lg.y) + (lg.z + lg.w);
        }
        float mx = warp_max(fmaxf(lv0, lv1));
        float ex0 = (lane < cnt)      ? __expf(lv0 - mx) : 0.f;
        float ex1 = (lane + 32 < cnt) ? __expf(lv1 - mx) : 0.f;
        float inv = 1.f / warp_sum(ex0 + ex1);
        for (int i = 0; i < cnt; i++) {
            int srcl = i & 31;
            float w = __shfl_sync(0xffffffffu, (i < 32) ? ex0 : ex1, srcl) * inv;
            int s = __shfl_sync(0xffffffffu, (i < 32) ? cs0 : cs1, srcl);
            const __half2* row = xl + (size_t)s * HCH + h * 128 + lane;
            #pragma unroll
            for (int j = 0; j < 4; j++) {
                float2 f = __half22float2(row[32 * j]);
                acc[j].x = fmaf(w, f.x, acc[j].x);
                acc[j].y = fmaf(w, f.y, acc[j].y);
            }
        }
    } else {
        float mx = -1e30f;
        for (int i = s0 + lane; i < s1; i += 32) {
            float4 lg = *reinterpret_cast<const float4*>(&g_logits[(i * H + h) * 4]);
            mx = fmaxf(mx, (lg.x + lg.y) + (lg.z + lg.w));
        }
        mx = warp_max(mx);
        float den = 0.f;
        for (int i = s0 + lane; i < s1; i += 32) {
            float4 lg = *reinterpret_cast<const float4*>(&g_logits[(i * H + h) * 4]);
            den += __expf((lg.x + lg.y) + (lg.z + lg.w) - mx);
        }
        den = warp_sum(den);
        float inv = 1.f / den;
        for (int i = s0; i < s1; i++) {
            float4 lg = *reinterpret_cast<const float4*>(&g_logits[(i * H + h) * 4]);
            float w = __expf((lg.x + lg.y) + (lg.z + lg.w) - mx) * inv;
            int s = g_psrc[i];
            const __half2* row = xl + (size_t)s * HCH + h * 128 + lane;
            #pragma unroll
            for (int j = 0; j < 4; j++) {
                float2 f = __half22float2(row[32 * j]);
                acc[j].x = fmaf(w, f.x, acc[j].x);
                acc[j].y = fmaf(w, f.y, acc[j].y);
            }
        }
    }

    int b = (OUTMODE == 2) ? g_batch[n] : 0;
    #pragma unroll
    for (int j = 0; j < 4; j++) {
        int col = h * CC + 2 * (lane + 32 * j);
        float2 bb = *reinterpret_cast<const float2*>(bias + col);
        float v0 = acc[j].x + bb.x, v1 = acc[j].y + bb.y;
        if (RELU) { v0 = fmaxf(v0, 0.f); v1 = fmaxf(v1, 0.f); }
        if (OUTMODE == 1) {
            __half* oh = (__half*)out;
            *reinterpret_cast<__half2*>(oh + (size_t)n * (H * CC) + col) = __floats2half2_rn(v0, v1);
        } else if (OUTMODE == 0) {
            float* of = (float*)out;
            *reinterpret_cast<float2*>(of + (size_t)n * (H * CC) + col) = make_float2(v0, v1);
        } else {
            atomicAdd(&g_pool[b * HC2 + col], v0);
            atomicAdd(&g_pool[b * HC2 + col + 1], v1);
        }
    }
}

// ---------------- pool divide + final ----------------
__global__ void k_pool_div() {
    int t = blockIdx.x * blockDim.x + threadIdx.x;
    if (t >= GG * HC2) return;
    g_pool[t] /= fmaxf(g_cnt[t >> 10], 1.f);
}
__global__ void k_final(const float* __restrict__ W3, const float* __restrict__ b3,
                        float* __restrict__ out) {
    int g = blockIdx.x, lane = threadIdx.x;
    float acc = 0.f;
    #pragma unroll
    for (int j = 0; j < 8; j++) acc += g_m2[g * 256 + lane + 32 * j] * W3[lane + 32 * j];
    acc = warp_sum(acc);
    if (lane == 0) out[g] = 1.f / (1.f + expf(-(acc + b3[0])));
}

// ---------------- host launch ----------------
static inline void launch_sgemm(const float* A, const float* B, const float* bias,
                                float* C, int M, int Nc, int K, int act) {
    dim3 grid((Nc + 127) / 128, (M + 127) / 128);
    k_sgemm<<<grid, 256>>>(A, B, bias, C, M, Nc, K, act);
}

extern "C" void kernel_launch(void* const* d_in, const int* in_sizes, int n_in,
                              void* d_out, int out_size) {
    const float* x     = (const float*)d_in[0];
    const int*   ei    = (const int*)  d_in[1];
    const float* ea    = (const float*)d_in[2];
    const int*   batch = (const int*)  d_in[3];
    const float* Wl1 = (const float*)d_in[4],  *bl1 = (const float*)d_in[5];
    const float* Wr1 = (const float*)d_in[6],  *br1 = (const float*)d_in[7];
    const float* We1 = (const float*)d_in[8],  *att1 = (const float*)d_in[9];
    const float* bias1 = (const float*)d_in[10];
    const float* Wl2 = (const float*)d_in[11], *bl2 = (const float*)d_in[12];
    const float* Wr2 = (const float*)d_in[13], *br2 = (const float*)d_in[14];
    const float* We2 = (const float*)d_in[15], *att2 = (const float*)d_in[16];
    const float* bias2 = (const float*)d_in[17];
    const float* W1 = (const float*)d_in[18], *b1 = (const float*)d_in[19];
    const float* W2 = (const float*)d_in[20], *b2 = (const float*)d_in[21];
    const float* W3 = (const float*)d_in[22], *b3 = (const float*)d_in[23];
    float* out = (float*)d_out;

    cudaFuncSetAttribute(k_mma_dual, cudaFuncAttributeMaxDynamicSharedMemorySize, GEMM_SMEM_BYTES);

    float *p_pool, *p_m1, *p_m2;
    __half *p_xl, *p_xr, *p_h1h, *p_ea2h, *p_w1h, *p_w2h, *p_we1h, *p_we2h, *p_xh;
    cudaGetSymbolAddress((void**)&p_xl,    g_xl);
    cudaGetSymbolAddress((void**)&p_xr,    g_xr);
    cudaGetSymbolAddress((void**)&p_h1h,   g_h1h);
    cudaGetSymbolAddress((void**)&p_ea2h,  g_ea2h);
    cudaGetSymbolAddress((void**)&p_w1h,   g_w1h);
    cudaGetSymbolAddress((void**)&p_w2h,   g_w2h);
    cudaGetSymbolAddress((void**)&p_we1h,  g_we1h);
    cudaGetSymbolAddress((void**)&p_we2h,  g_we2h);
    cudaGetSymbolAddress((void**)&p_xh,    g_xh);
    cudaGetSymbolAddress((void**)&p_pool,  g_pool);
    cudaGetSymbolAddress((void**)&p_m1,    g_m1);
    cudaGetSymbolAddress((void**)&p_m2,    g_m2);

    // --- prep (launch index 3 = layer-1 k_mma_dual for ncu capture) ---
    k_detect<<<1, 1>>>(ei);                                                  // 0
    k_wconv<<<(HC2 * HC1 + 255) / 256, 256>>>(Wl1, Wr1, Wl2, Wr2, We1, We2, x); // 1
    k_prep<<<(NN * DEDGE + 255) / 256, 256>>>(ei, batch);                    // 2
    k_mma_dual<<<dim3(2 * HC1 / 128, NN / 128), 256, GEMM_SMEM_BYTES>>>(     // 3 <- ncu
        p_xh, p_w1h, bl1, br1, p_xl, p_xr, NN, 2 * HC1, DNODE);
    k_deg_easum<<<(EE * DEDGE + 255) / 256, 256>>>(ea);                      // 4
    k_scan<<<1, 256>>>();                                                    // 5
    k_csr<<<(ET + 255) / 256, 256>>>();                                      // 6
    k_ea2<<<(ET * DEDGE + 255) / 256, 256>>>(ea);                            // 7

    // --- GATv2 layer 1 ---
    k_ee_logits<H1C><<<dim3(HC1 / 128, ET / 128), 256>>>(p_ea2h, p_we1h, att1);
    k_aggregate<H1C, 1, 1><<<NN, H1C * 32>>>(bias1, p_h1h);

    // --- GATv2 layer 2 (aggregate pools directly) ---
    k_mma_dual<<<dim3(2 * HC2 / 128, NN / 128), 256, GEMM_SMEM_BYTES>>>(
        p_h1h, p_w2h, bl2, br2, p_xl, p_xr, NN, 2 * HC2, HC1);
    k_ee_logits<H2C><<<dim3(HC2 / 128, ET / 128), 256>>>(p_ea2h, p_we2h, att2);
    k_aggregate<H2C, 0, 2><<<NN, H2C * 32>>>(bias2, nullptr);

    // --- pool + MLP ---
    k_pool_div<<<(GG * HC2 + 255) / 256, 256>>>();
    launch_sgemm(p_pool, W1, b1, p_m1, GG, 512, HC2, 1);
    launch_sgemm(p_m1,  W2, b2, p_m2, GG, 256, 512, 1);
    k_final<<<GG, 32>>>(W3, b3, out);
}

// round 11
// speedup vs baseline: 4.7668x; 1.1284x over previous
#include <cuda_runtime.h>
#include <cuda_fp16.h>
#include <math.h>
#include <stdint.h>

// ---------------- problem constants ----------------
#define NN   8192
#define EE   65536
#define GG   64
#define DNODE 64
#define DEDGE 32
#define CC   256
#define H1C  8
#define H2C  4
#define ET   (EE + NN)          // 73728 = 576*128
#define HC1  (H1C * CC)         // 2048
#define HC2  (H2C * CC)         // 1024
#define NEG_SLOPE 0.2f

// ---------------- device scratch ----------------
__device__ int    g_is64;
__device__ int    g_src[EE];
__device__ int    g_dst[EE];
__device__ int    g_batch[NN];
__device__ int    g_deg[NN];
__device__ int    g_cur[NN];
__device__ int    g_off[NN + 1];
__device__ int    g_pedge[ET];
__device__ int    g_psrc[ET];
__device__ int    g_pdst[ET];
__device__ float  g_easum[NN * DEDGE];
__device__ __half g_ea2h[ET * DEDGE];
__device__ __half g_xh[NN * DNODE];
__device__ __half g_xl[NN * HC1];
__device__ __half g_xr[NN * HC1];
__device__ __half g_h1h[NN * HC1];
__device__ float  g_logits[ET * H1C * 4];
__device__ float  g_pool[GG * HC2];
__device__ float  g_cnt[GG];
__device__ float  g_m1[GG * 512];
__device__ float  g_m2[GG * 256];
__device__ __half g_w1h[2 * HC1 * DNODE];
__device__ __half g_w2h[2 * HC2 * HC1];
__device__ __half g_we1h[HC1 * DEDGE];
__device__ __half g_we2h[HC2 * DEDGE];

// ---------------- helpers ----------------
__device__ __forceinline__ float warp_sum(float v) {
    #pragma unroll
    for (int o = 16; o; o >>= 1) v += __shfl_xor_sync(0xffffffffu, v, o);
    return v;
}
__device__ __forceinline__ float warp_max(float v) {
    #pragma unroll
    for (int o = 16; o; o >>= 1) v = fmaxf(v, __shfl_xor_sync(0xffffffffu, v, o));
    return v;
}
__device__ __forceinline__ uint32_t smem_u32(const void* p) {
    uint32_t a;
    asm("{ .reg .u64 t; cvta.to.shared.u64 t, %1; cvt.u32.u64 %0, t; }" : "=r"(a) : "l"(p));
    return a;
}
__device__ __forceinline__ void mma_f16(float* c, uint4 a, uint2 b) {
    asm volatile(
        "mma.sync.aligned.m16n8k16.row.col.f32.f16.f16.f32 "
        "{%0,%1,%2,%3},{%4,%5,%6,%7},{%8,%9},{%0,%1,%2,%3};"
        : "+f"(c[0]), "+f"(c[1]), "+f"(c[2]), "+f"(c[3])
        : "r"(a.x), "r"(a.y), "r"(a.z), "r"(a.w), "r"(b.x), "r"(b.y));
}
__device__ __forceinline__ uint4 ldsm4(uint32_t addr) {
    uint4 r;
    asm volatile("ldmatrix.sync.aligned.m8n8.x4.shared.b16 {%0,%1,%2,%3}, [%4];"
        : "=r"(r.x), "=r"(r.y), "=r"(r.z), "=r"(r.w) : "r"(addr));
    return r;
}
__device__ __forceinline__ void cp16(uint32_t dst, const void* src) {
    asm volatile("cp.async.cg.shared.global [%0], [%1], 16;" :: "r"(dst), "l"(src));
}

// =================================================================
// cp.async + ldmatrix fp16 GEMM (3-stage, XOR swizzle) — proven R7-10.
// =================================================================
#define GEMM_STAGE_BYTES 32768
#define GEMM_SMEM_BYTES  (3 * GEMM_STAGE_BYTES)

__device__ __forceinline__ void issue_stage(
    const __half* __restrict__ A, const __half* __restrict__ B, int K,
    int rowBase, int colBase, int k0, uint32_t abase, int tid)
{
    #pragma unroll
    for (int i = 0; i < 4; i++) {
        int id = i * 256 + tid;
        int r = id >> 3, c = id & 7;
        uint32_t off = (uint32_t)(r * 128 + ((c ^ (r & 7)) << 4));
        cp16(abase + off,         A + (size_t)(rowBase + r) * K + k0 + c * 8);
        cp16(abase + 16384 + off, B + (size_t)(colBase + r) * K + k0 + c * 8);
    }
    asm volatile("cp.async.commit_group;" ::: "memory");
}

__global__ __launch_bounds__(256, 2) void k_mma_dual(
    const __half* __restrict__ A, const __half* __restrict__ B,
    const float* __restrict__ biasL, const float* __restrict__ biasR,
    __half* __restrict__ outL, __half* __restrict__ outR,
    int M, int N, int K)
{
    extern __shared__ char smem[];
    uint32_t sb = smem_u32(smem);
    int tid = threadIdx.x;
    int wid = tid >> 5, lane = tid & 31;
    int mw = wid & 3, nw = wid >> 2;
    int gid = lane >> 2, tig = lane & 3;
    int rowBase = blockIdx.y * 128, colBase = blockIdx.x * 128;

    float acc[2][8][4];
    #pragma unroll
    for (int mt = 0; mt < 2; mt++)
        #pragma unroll
        for (int nt = 0; nt < 8; nt++)
            #pragma unroll
            for (int q = 0; q < 4; q++) acc[mt][nt][q] = 0.f;

    const int NCH = K >> 6;
    issue_stage(A, B, K, rowBase, colBase, 0, sb, tid);
    if (NCH > 1) issue_stage(A, B, K, rowBase, colBase, 64, sb + GEMM_STAGE_BYTES, tid);

    int arow = mw * 32 + (lane & 15);
    int achoff = lane >> 4;
    int brow = nw * 64 + ((lane >> 4) << 3) + (lane & 7);
    int bchoff = (lane >> 3) & 1;

    for (int c = 0; c < NCH; c++) {
        if (c + 2 <= NCH) asm volatile("cp.async.wait_group 1;" ::: "memory");
        else              asm volatile("cp.async.wait_group 0;" ::: "memory");
        __syncthreads();
        if (c + 2 < NCH)
            issue_stage(A, B, K, rowBase, colBase, (c + 2) << 6,
                        sb + ((c + 2) % 3) * GEMM_STAGE_BYTES, tid);

        uint32_t Ab = sb + (c % 3) * GEMM_STAGE_BYTES;
        uint32_t Bb = Ab + 16384;
        #pragma unroll
        for (int kstep = 0; kstep < 4; kstep++) {
            uint4 afr[2];
            #pragma unroll
            for (int mt = 0; mt < 2; mt++) {
                int row = arow + mt * 16;
                int ch = kstep * 2 + achoff;
                afr[mt] = ldsm4(Ab + row * 128 + ((ch ^ (row & 7)) << 4));
            }
            uint2 bfr[8];
            #pragma unroll
            for (int ntp = 0; ntp < 4; ntp++) {
                int row = brow + ntp * 16;
                int ch = kstep * 2 + bchoff;
                uint4 t = ldsm4(Bb + row * 128 + ((ch ^ (row & 7)) << 4));
                bfr[2 * ntp]     = make_uint2(t.x, t.y);
                bfr[2 * ntp + 1] = make_uint2(t.z, t.w);
            }
            #pragma unroll
            for (int mt = 0; mt < 2; mt++)
                #pragma unroll
                for (int nt = 0; nt < 8; nt++)
                    mma_f16(acc[mt][nt], afr[mt], bfr[nt]);
        }
    }

    int halfN = N >> 1;
    bool isR = (colBase >= halfN);
    const float* bias = isR ? biasR : biasL;
    __half* outp = isR ? outR : outL;
    int cb = colBase - (isR ? halfN : 0);

    #pragma unroll
    for (int mt = 0; mt < 2; mt++) {
        int row0 = rowBase + mw * 32 + mt * 16 + gid;
        #pragma unroll
        for (int nt = 0; nt < 8; nt++) {
            int col = cb + nw * 64 + nt * 8 + tig * 2;
            float b0 = bias[col], b1 = bias[col + 1];
            float c0 = acc[mt][nt][0] + b0, c1 = acc[mt][nt][1] + b1;
            float c2 = acc[mt][nt][2] + b0, c3 = acc[mt][nt][3] + b1;
            *reinterpret_cast<__half2*>(outp + (size_t)row0 * halfN + col)       = __floats2half2_rn(c0, c1);
            *reinterpret_cast<__half2*>(outp + (size_t)(row0 + 8) * halfN + col) = __floats2half2_rn(c2, c3);
        }
    }
}

// =================================================================
// Fused edge-feature GEMM + logits, smem-staged xl/xr gathers.
// Dynamic smem: [0,16KB) GEMM tiles; [16KB,+34KB) sXL; [+34KB) sXR.
// sXL/sXR: 128 edges x 68 half2 (64 used + 4 pad) = 272 B/row.
// =================================================================
#define EEL_XL_OFF 16384
#define EEL_XR_OFF (16384 + 128 * 272)
#define EEL_SMEM_BYTES (16384 + 2 * 128 * 272)

__device__ __forceinline__ void ldg_tile_h(
    const __half* __restrict__ A, const __half* __restrict__ B, int K,
    int rowBase, int colBase, int kc, int tid, uint2* pa, uint2* pb)
{
    #pragma unroll
    for (int i = 0; i < 4; i++) {
        int id = i * 256 + tid;
        int r = id >> 3, c4 = id & 7;
        pa[i] = *reinterpret_cast<const uint2*>(A + (size_t)(rowBase + r) * K + kc + c4 * 4);
        pb[i] = *reinterpret_cast<const uint2*>(B + (size_t)(colBase + r) * K + kc + c4 * 4);
    }
}
__device__ __forceinline__ void sts_tile(
    uint32_t* __restrict__ sA, uint32_t* __restrict__ sB,
    int tid, const uint2* pa, const uint2* pb)
{
    #pragma unroll
    for (int i = 0; i < 4; i++) {
        int id = i * 256 + tid;
        int r = id >> 3, c4 = id & 7;
        int kstep = c4 >> 2;
        int pl = (c4 & 3) * 2;
        int mtile = r >> 4, ri = r & 15;
        int regA = ((pl & 4) ? 2 : 0) + (ri >> 3);
        int laneA = (ri & 7) * 4 + (pl & 3);
        int baseA = (kstep * 8 + mtile) * 128;
        sA[baseA + laneA * 4 + regA]       = pa[i].x;
        sA[baseA + (laneA + 1) * 4 + regA] = pa[i].y;
        int ntile = r >> 3, ni = r & 7;
        int regB = (pl & 4) ? 1 : 0;
        int laneB = ni * 4 + (pl & 3);
        int baseB = (kstep * 16 + ntile) * 64;
        sB[baseB + laneB * 2 + regB]       = pb[i].x;
        sB[baseB + (laneB + 1) * 2 + regB] = pb[i].y;
    }
}

template <int H>
__global__ __launch_bounds__(256) void k_ee_logits(
    const __half* __restrict__ A, const __half* __restrict__ B,
    const float* __restrict__ att)
{
    extern __shared__ uint32_t sm[];
    uint32_t sb = smem_u32(sm);
    int tid = threadIdx.x;
    int wid = tid >> 5, lane = tid & 31;
    int mw = wid & 3, nw = wid >> 2;
    int gid = lane >> 2, tig = lane & 3;
    int rowBase = blockIdx.y * 128, colBase = blockIdx.x * 128;
    const int HC = H * CC;

    // ---- stage xl/xr row segments via cp.async (overlaps the ee GEMM) ----
    #pragma unroll
    for (int i = 0; i < 8; i++) {
        int idx = i * 256 + tid;            // 0..2047
        int el = idx >> 4, p = idx & 15;    // edge-local 0..127, 16B part 0..15
        int eg = rowBase + el;
        int s = g_psrc[eg], d = g_pdst[eg];
        cp16(sb + EEL_XL_OFF + el * 272 + p * 16, g_xl + (size_t)s * HC + colBase + p * 8);
        cp16(sb + EEL_XR_OFF + el * 272 + p * 16, g_xr + (size_t)d * HC + colBase + p * 8);
    }
    asm volatile("cp.async.commit_group;" ::: "memory");

    // ---- ee GEMM (register-staged, K=32) ----
    float acc[2][8][4];
    #pragma unroll
    for (int mt = 0; mt < 2; mt++)
        #pragma unroll
        for (int nt = 0; nt < 8; nt++)
            #pragma unroll
            for (int q = 0; q < 4; q++) acc[mt][nt][q] = 0.f;

    uint2 pa[4], pb[4];
    ldg_tile_h(A, B, DEDGE, rowBase, colBase, 0, tid, pa, pb);
    sts_tile(sm, sm + 2048, tid, pa, pb);
    __syncthreads();

    #pragma unroll
    for (int kstep = 0; kstep < 2; kstep++) {
        uint4 afr[2];
        #pragma unroll
        for (int mt = 0; mt < 2; mt++)
            afr[mt] = *reinterpret_cast<const uint4*>(
                sm + (kstep * 8 + mw * 2 + mt) * 128 + lane * 4);
        uint2 bfr[8];
        #pragma unroll
        for (int nt = 0; nt < 8; nt++)
            bfr[nt] = *reinterpret_cast<const uint2*>(
                sm + 2048 + (kstep * 16 + nw * 8 + nt) * 64 + lane * 2);
        #pragma unroll
        for (int mt = 0; mt < 2; mt++)
            #pragma unroll
            for (int nt = 0; nt < 8; nt++)
                mma_f16(acc[mt][nt], afr[mt], bfr[nt]);
    }

    // ---- wait for staged xl/xr, then fused logits epilogue from smem ----
    asm volatile("cp.async.wait_group 0;" ::: "memory");
    __syncthreads();

    int h = colBase >> 8;
    int q = ((blockIdx.x & 1) << 1) | nw;
    const __half2* sXL = reinterpret_cast<const __half2*>((const char*)sm + EEL_XL_OFF);
    const __half2* sXR = reinterpret_cast<const __half2*>((const char*)sm + EEL_XR_OFF);

    #pragma unroll
    for (int mt = 0; mt < 2; mt++) {
        int el0 = mw * 32 + mt * 16 + gid;     // local edge indices
        int el1 = el0 + 8;
        float p0 = 0.f, p1 = 0.f;
        #pragma unroll
        for (int nt = 0; nt < 8; nt++) {
            int coff = nw * 32 + nt * 4 + tig;  // half2 offset within segment
            int col = colBase + nw * 64 + nt * 8 + tig * 2;
            float2 at = *reinterpret_cast<const float2*>(att + h * CC + (col & (CC - 1)));
            float2 a0 = __half22float2(sXL[el0 * 68 + coff]);
            float2 b0 = __half22float2(sXR[el0 * 68 + coff]);
            float2 a1 = __half22float2(sXL[el1 * 68 + coff]);
            float2 b1 = __half22float2(sXR[el1 * 68 + coff]);
            float v0 = acc[mt][nt][0] + a0.x + b0.x;
            float v1 = acc[mt][nt][1] + a0.y + b0.y;
            float v2 = acc[mt][nt][2] + a1.x + b1.x;
            float v3 = acc[mt][nt][3] + a1.y + b1.y;
            v0 = (v0 > 0.f) ? v0 : NEG_SLOPE * v0;
            v1 = (v1 > 0.f) ? v1 : NEG_SLOPE * v1;
            v2 = (v2 > 0.f) ? v2 : NEG_SLOPE * v2;
            v3 = (v3 > 0.f) ? v3 : NEG_SLOPE * v3;
            p0 += v0 * at.x + v1 * at.y;
            p1 += v2 * at.x + v3 * at.y;
        }
        p0 += __shfl_xor_sync(0xffffffffu, p0, 1);
        p0 += __shfl_xor_sync(0xffffffffu, p0, 2);
        p1 += __shfl_xor_sync(0xffffffffu, p1, 1);
        p1 += __shfl_xor_sync(0xffffffffu, p1, 2);
        if (tig == 0) {
            g_logits[((rowBase + el0) * H + h) * 4 + q] = p0;
            g_logits[((rowBase + el1) * H + h) * 4 + q] = p1;
        }
    }
}

// ---------------- weight / input conversion ----------------
__global__ void k_wconv(const float* __restrict__ Wl1, const float* __restrict__ Wr1,
                        const float* __restrict__ Wl2, const float* __restrict__ Wr2,
                        const float* __restrict__ We1, const float* __restrict__ We2,
                        const float* __restrict__ x)
{
    int t = blockIdx.x * blockDim.x + threadIdx.x;
    const int s1 = HC1 * DNODE;
    const int s2 = HC2 * HC1;
    const int s3 = HC1 * DEDGE;
    const int s4 = HC2 * DEDGE;
    if (t < s1) { g_w1h[t] = __float2half_rn(Wl1[t]); g_w1h[s1 + t] = __float2half_rn(Wr1[t]); }
    if (t < s2) { g_w2h[t] = __float2half_rn(Wl2[t]); g_w2h[s2 + t] = __float2half_rn(Wr2[t]); }
    if (t < s3) g_we1h[t] = __float2half_rn(We1[t]);
    if (t < s4) g_we2h[t] = __float2half_rn(We2[t]);
    if (t < NN * DNODE) g_xh[t] = __float2half_rn(x[t]);
}

// ---------------- graph prep ----------------
__global__ void k_detect(const int* __restrict__ ei) {
    int is64 = 1;
    for (int i = 0; i < 16; i++)
        if (ei[2 * i + 1] != 0) is64 = 0;
    g_is64 = is64;
}
__global__ void k_prep(const int* __restrict__ ei, const int* __restrict__ batch) {
    int t = blockIdx.x * blockDim.x + threadIdx.x;
    int is64 = g_is64;
    if (t < EE) {
        g_src[t] = is64 ? ei[2 * t]        : ei[t];
        g_dst[t] = is64 ? ei[2 * (EE + t)] : ei[EE + t];
    }
    if (t < NN) {
        g_batch[t] = is64 ? batch[2 * t] : batch[t];
        g_deg[t] = 0;
        g_cur[t] = 0;
    }
    if (t < NN * DEDGE) g_easum[t] = 0.f;
    if (t < GG * HC2) g_pool[t] = 0.f;
}
__global__ void k_deg_easum(const float* __restrict__ ea) {
    int t = blockIdx.x * blockDim.x + threadIdx.x;
    if (t >= EE * DEDGE) return;
    int e = t >> 5, d = t & 31;
    int dst = g_dst[e];
    atomicAdd(&g_easum[dst * DEDGE + d], ea[t]);
    if (d == 0) atomicAdd(&g_deg[dst], 1);
}
__global__ void k_scan() {
    __shared__ int part[256];
    __shared__ int scnt[GG];
    int t = threadIdx.x;
    if (t < GG) scnt[t] = 0;
    __syncthreads();
    int base = t * 32;
    int loc[32];
    int s = 0;
    #pragma unroll
    for (int i = 0; i < 32; i++) {
        loc[i] = s; s += g_deg[base + i] + 1;
        atomicAdd(&scnt[g_batch[base + i]], 1);
    }
    part[t] = s;
    __syncthreads();
    if (t == 0) {
        int acc = 0;
        for (int i = 0; i < 256; i++) { int v = part[i]; part[i] = acc; acc += v; }
        g_off[NN] = acc;
    }
    __syncthreads();
    int p = part[t];
    #pragma unroll
    for (int i = 0; i < 32; i++) g_off[base + i] = p + loc[i];
    if (t < GG) g_cnt[t] = (float)scnt[t];
}
__global__ void k_csr() {
    int e = blockIdx.x * blockDim.x + threadIdx.x;
    if (e >= ET) return;
    int s, node;
    if (e < EE) { s = g_src[e]; node = g_dst[e]; } else { s = node = e - EE; }
    int pos = g_off[node] + atomicAdd(&g_cur[node], 1);
    g_pedge[pos] = e;
    g_psrc[pos]  = s;
    g_pdst[pos]  = node;
}
__global__ void k_ea2(const float* __restrict__ ea) {
    int t = blockIdx.x * blockDim.x + threadIdx.x;
    if (t >= ET * DEDGE) return;
    int pos = t >> 5, d = t & 31;
    int e = g_pedge[pos];
    float v;
    if (e < EE) {
        v = ea[e * DEDGE + d];
    } else {
        int n = e - EE;
        v = g_easum[n * DEDGE + d] / fmaxf((float)g_deg[n], 1.f);
    }
    g_ea2h[t] = __float2half_rn(v);
}

// ---------------- fp32 SGEMM for the tiny MLP ----------------
__global__ __launch_bounds__(256) void k_sgemm(
    const float* __restrict__ A, const float* __restrict__ Bm,
    const float* __restrict__ bias, float* __restrict__ Cm,
    int M, int Nc, int K, int act)
{
    constexpr int BM = 128, BN = 128, BK = 16, TM = 8, TN = 8;
    __shared__ float As[BK][BM];
    __shared__ float Bs[BK][BN];
    int tid = threadIdx.x;
    int tx = tid % 16, ty = tid / 16;
    int rowBase = blockIdx.y * BM;
    int colBase = blockIdx.x * BN;
    float acc[TM][TN];
    #pragma unroll
    for (int i = 0; i < TM; i++)
        #pragma unroll
        for (int j = 0; j < TN; j++) acc[i][j] = 0.f;
    for (int k0 = 0; k0 < K; k0 += BK) {
        #pragma unroll
        for (int i = 0; i < 2; i++) {
            int f4 = tid + i * 256;
            int r = f4 >> 2;
            int kk = (f4 & 3) * 4;
            int gr = rowBase + r;
            float4 v = make_float4(0.f, 0.f, 0.f, 0.f);
            if (gr < M) v = *reinterpret_cast<const float4*>(A + (size_t)gr * K + k0 + kk);
            As[kk + 0][r] = v.x; As[kk + 1][r] = v.y; As[kk + 2][r] = v.z; As[kk + 3][r] = v.w;
            int gc = colBase + r;
            float4 w = make_float4(0.f, 0.f, 0.f, 0.f);
            if (gc < Nc) w = *reinterpret_cast<const float4*>(Bm + (size_t)gc * K + k0 + kk);
            Bs[kk + 0][r] = w.x; Bs[kk + 1][r] = w.y; Bs[kk + 2][r] = w.z; Bs[kk + 3][r] = w.w;
        }
        __syncthreads();
        #pragma unroll
        for (int k = 0; k < BK; k++) {
            float a[TM], b[TN];
            #pragma unroll
            for (int i = 0; i < TM; i++) a[i] = As[k][ty * TM + i];
            #pragma unroll
            for (int j = 0; j < TN; j++) b[j] = Bs[k][tx * TN + j];
            #pragma unroll
            for (int i = 0; i < TM; i++)
                #pragma unroll
                for (int j = 0; j < TN; j++) acc[i][j] = fmaf(a[i], b[j], acc[i][j]);
        }
        __syncthreads();
    }
    #pragma unroll
    for (int i = 0; i < TM; i++) {
        int gr = rowBase + ty * TM + i;
        if (gr >= M) continue;
        #pragma unroll
        for (int j = 0; j < TN; j++) {
            int gc = colBase + tx * TN + j;
            if (gc >= Nc) continue;
            float v = acc[i][j];
            if (bias) v += bias[gc];
            if (act) v = fmaxf(v, 0.f);
            Cm[(size_t)gr * Nc + gc] = v;
        }
    }
}

// ---------------- segment softmax + weighted gather (csr order) ----------------
template <int H, int RELU, int OUTMODE>
__global__ void k_aggregate(const float* __restrict__ bias, void* __restrict__ out) {
    int n = blockIdx.x;
    int h = threadIdx.x >> 5, lane = threadIdx.x & 31;
    int s0 = g_off[n], s1 = g_off[n + 1];
    int cnt = s1 - s0;
    const int HCH = H * (CC / 2);
    const __half2* xl = reinterpret_cast<const __half2*>(g_xl);
    float2 acc[4];
    #pragma unroll
    for (int j = 0; j < 4; j++) acc[j] = make_float2(0.f, 0.f);

    if (cnt <= 64) {
        int cs0 = 0, cs1 = 0;
        float lv0 = -1e30f, lv1 = -1e30f;
        if (lane < cnt) {
            int p = s0 + lane;
            cs0 = g_psrc[p];
            float4 lg = *reinterpret_cast<const float4*>(&g_logits[(p * H + h) * 4]);
            lv0 = (lg.x + lg.y) + (lg.z + lg.w);
        }
        if (lane + 32 < cnt) {
            int p = s0 + lane + 32;
            cs1 = g_psrc[p];
            float4 lg = *reinterpret_cast<const float4*>(&g_logits[(p * H + h) * 4]);
            lv1 = (lg.x + lg.y) + (lg.z + lg.w);
        }
        float mx = warp_max(fmaxf(lv0, lv1));
        float ex0 = (lane < cnt)      ? __expf(lv0 - mx) : 0.f;
        float ex1 = (lane + 32 < cnt) ? __expf(lv1 - mx) : 0.f;
        float inv = 1.f / warp_sum(ex0 + ex1);
        for (int i = 0; i < cnt; i++) {
            int srcl = i & 31;
            float w = __shfl_sync(0xffffffffu, (i < 32) ? ex0 : ex1, srcl) * inv;
            int s = __shfl_sync(0xffffffffu, (i < 32) ? cs0 : cs1, srcl);
            const __half2* row = xl + (size_t)s * HCH + h * 128 + lane;
            #pragma unroll
            for (int j = 0; j < 4; j++) {
                float2 f = __half22float2(row[32 * j]);
                acc[j].x = fmaf(w, f.x, acc[j].x);
                acc[j].y = fmaf(w, f.y, acc[j].y);
            }
        }
    } else {
        float mx = -1e30f;
        for (int i = s0 + lane; i < s1; i += 32) {
            float4 lg = *reinterpret_cast<const float4*>(&g_logits[(i * H + h) * 4]);
            mx = fmaxf(mx, (lg.x + lg.y) + (lg.z + lg.w));
        }
        mx = warp_max(mx);
        float den = 0.f;
        for (int i = s0 + lane; i < s1; i += 32) {
            float4 lg = *reinterpret_cast<const float4*>(&g_logits[(i * H + h) * 4]);
            den += __expf((lg.x + lg.y) + (lg.z + lg.w) - mx);
        }
        den = warp_sum(den);
        float inv = 1.f / den;
        for (int i = s0; i < s1; i++) {
            float4 lg = *reinterpret_cast<const float4*>(&g_logits[(i * H + h) * 4]);
            float w = __expf((lg.x + lg.y) + (lg.z + lg.w) - mx) * inv;
            int s = g_psrc[i];
            const __half2* row = xl + (size_t)s * HCH + h * 128 + lane;
            #pragma unroll
            for (int j = 0; j < 4; j++) {
                float2 f = __half22float2(row[32 * j]);
                acc[j].x = fmaf(w, f.x, acc[j].x);
                acc[j].y = fmaf(w, f.y, acc[j].y);
            }
        }
    }

    int b = (OUTMODE == 2) ? g_batch[n] : 0;
    #pragma unroll
    for (int j = 0; j < 4; j++) {
        int col = h * CC + 2 * (lane + 32 * j);
        float2 bb = *reinterpret_cast<const float2*>(bias + col);
        float v0 = acc[j].x + bb.x, v1 = acc[j].y + bb.y;
        if (RELU) { v0 = fmaxf(v0, 0.f); v1 = fmaxf(v1, 0.f); }
        if (OUTMODE == 1) {
            __half* oh = (__half*)out;
            *reinterpret_cast<__half2*>(oh + (size_t)n * (H * CC) + col) = __floats2half2_rn(v0, v1);
        } else if (OUTMODE == 0) {
            float* of = (float*)out;
            *reinterpret_cast<float2*>(of + (size_t)n * (H * CC) + col) = make_float2(v0, v1);
        } else {
            atomicAdd(&g_pool[b * HC2 + col], v0);
            atomicAdd(&g_pool[b * HC2 + col + 1], v1);
        }
    }
}

// ---------------- pool divide + final ----------------
__global__ void k_pool_div() {
    int t = blockIdx.x * blockDim.x + threadIdx.x;
    if (t >= GG * HC2) return;
    g_pool[t] /= fmaxf(g_cnt[t >> 10], 1.f);
}
__global__ void k_final(const float* __restrict__ W3, const float* __restrict__ b3,
                        float* __restrict__ out) {
    int g = blockIdx.x, lane = threadIdx.x;
    float acc = 0.f;
    #pragma unroll
    for (int j = 0; j < 8; j++) acc += g_m2[g * 256 + lane + 32 * j] * W3[lane + 32 * j];
    acc = warp_sum(acc);
    if (lane == 0) out[g] = 1.f / (1.f + expf(-(acc + b3[0])));
}

// ---------------- host launch ----------------
static inline void launch_sgemm(const float* A, const float* B, const float* bias,
                                float* C, int M, int Nc, int K, int act) {
    dim3 grid((Nc + 127) / 128, (M + 127) / 128);
    k_sgemm<<<grid, 256>>>(A, B, bias, C, M, Nc, K, act);
}

extern "C" void kernel_launch(void* const* d_in, const int* in_sizes, int n_in,
                              void* d_out, int out_size) {
    const float* x     = (const float*)d_in[0];
    const int*   ei    = (const int*)  d_in[1];
    const float* ea    = (const float*)d_in[2];
    const int*   batch = (const int*)  d_in[3];
    const float* Wl1 = (const float*)d_in[4],  *bl1 = (const float*)d_in[5];
    const float* Wr1 = (const float*)d_in[6],  *br1 = (const float*)d_in[7];
    const float* We1 = (const float*)d_in[8],  *att1 = (const float*)d_in[9];
    const float* bias1 = (const float*)d_in[10];
    const float* Wl2 = (const float*)d_in[11], *bl2 = (const float*)d_in[12];
    const float* Wr2 = (const float*)d_in[13], *br2 = (const float*)d_in[14];
    const float* We2 = (const float*)d_in[15], *att2 = (const float*)d_in[16];
    const float* bias2 = (const float*)d_in[17];
    const float* W1 = (const float*)d_in[18], *b1 = (const float*)d_in[19];
    const float* W2 = (const float*)d_in[20], *b2 = (const float*)d_in[21];
    const float* W3 = (const float*)d_in[22], *b3 = (const float*)d_in[23];
    float* out = (float*)d_out;

    cudaFuncSetAttribute(k_mma_dual, cudaFuncAttributeMaxDynamicSharedMemorySize, GEMM_SMEM_BYTES);
    cudaFuncSetAttribute(k_ee_logits<H1C>, cudaFuncAttributeMaxDynamicSharedMemorySize, EEL_SMEM_BYTES);
    cudaFuncSetAttribute(k_ee_logits<H2C>, cudaFuncAttributeMaxDynamicSharedMemorySize, EEL_SMEM_BYTES);

    float *p_pool, *p_m1, *p_m2;
    __half *p_xl, *p_xr, *p_h1h, *p_ea2h, *p_w1h, *p_w2h, *p_we1h, *p_we2h, *p_xh;
    cudaGetSymbolAddress((void**)&p_xl,    g_xl);
    cudaGetSymbolAddress((void**)&p_xr,    g_xr);
    cudaGetSymbolAddress((void**)&p_h1h,   g_h1h);
    cudaGetSymbolAddress((void**)&p_ea2h,  g_ea2h);
    cudaGetSymbolAddress((void**)&p_w1h,   g_w1h);
    cudaGetSymbolAddress((void**)&p_w2h,   g_w2h);
    cudaGetSymbolAddress((void**)&p_we1h,  g_we1h);
    cudaGetSymbolAddress((void**)&p_we2h,  g_we2h);
    cudaGetSymbolAddress((void**)&p_xh,    g_xh);
    cudaGetSymbolAddress((void**)&p_pool,  g_pool);
    cudaGetSymbolAddress((void**)&p_m1,    g_m1);
    cudaGetSymbolAddress((void**)&p_m2,    g_m2);

    // --- prep (launch index 3 = layer-1 k_mma_dual for ncu capture) ---
    k_detect<<<1, 1>>>(ei);                                                  // 0
    k_wconv<<<(HC2 * HC1 + 255) / 256, 256>>>(Wl1, Wr1, Wl2, Wr2, We1, We2, x); // 1
    k_prep<<<(NN * DEDGE + 255) / 256, 256>>>(ei, batch);                    // 2
    k_mma_dual<<<dim3(2 * HC1 / 128, NN / 128), 256, GEMM_SMEM_BYTES>>>(     // 3 <- ncu
        p_xh, p_w1h, bl1, br1, p_xl, p_xr, NN, 2 * HC1, DNODE);
    k_deg_easum<<<(EE * DEDGE + 255) / 256, 256>>>(ea);                      // 4
    k_scan<<<1, 256>>>();                                                    // 5
    k_csr<<<(ET + 255) / 256, 256>>>();                                      // 6
    k_ea2<<<(ET * DEDGE + 255) / 256, 256>>>(ea);                            // 7

    // --- GATv2 layer 1 ---
    k_ee_logits<H1C><<<dim3(HC1 / 128, ET / 128), 256, EEL_SMEM_BYTES>>>(p_ea2h, p_we1h, att1);
    k_aggregate<H1C, 1, 1><<<NN, H1C * 32>>>(bias1, p_h1h);

    // --- GATv2 layer 2 (aggregate pools directly) ---
    k_mma_dual<<<dim3(2 * HC2 / 128, NN / 128), 256, GEMM_SMEM_BYTES>>>(
        p_h1h, p_w2h, bl2, br2, p_xl, p_xr, NN, 2 * HC2, HC1);
    k_ee_logits<H2C><<<dim3(HC2 / 128, ET / 128), 256, EEL_SMEM_BYTES>>>(p_ea2h, p_we2h, att2);
    k_aggregate<H2C, 0, 2><<<NN, H2C * 32>>>(bias2, nullptr);

    // --- pool + MLP ---
    k_pool_div<<<(GG * HC2 + 255) / 256, 256>>>();
    launch_sgemm(p_pool, W1, b1, p_m1, GG, 512, HC2, 1);
    launch_sgemm(p_m1,  W2, b2, p_m2, GG, 256, 512, 1);
    k_final<<<GG, 32>>>(W3, b3, out);
}

// round 12
// speedup vs baseline: 4.7827x; 1.0033x over previous
#include <cuda_runtime.h>
#include <cuda_fp16.h>
#include <math.h>
#include <stdint.h>

// ---------------- problem constants ----------------
#define NN   8192
#define EE   65536
#define GG   64
#define DNODE 64
#define DEDGE 32
#define CC   256
#define H1C  8
#define H2C  4
#define ET   (EE + NN)          // 73728 = 576*128
#define HC1  (H1C * CC)         // 2048
#define HC2  (H2C * CC)         // 1024
#define NEG_SLOPE 0.2f

// ---------------- device scratch ----------------
__device__ int    g_is64;
__device__ int    g_src[EE];
__device__ int    g_dst[EE];
__device__ int    g_batch[NN];
__device__ int    g_deg[NN];
__device__ int    g_cur[NN];
__device__ int    g_off[NN + 1];
__device__ int    g_pedge[ET];
__device__ int    g_psrc[ET];
__device__ int    g_pdst[ET];
__device__ float  g_easum[NN * DEDGE];
__device__ __half g_ea2h[ET * DEDGE];
__device__ __half g_xh[NN * DNODE];
__device__ __half g_xl[NN * HC1];
__device__ __half g_xr[NN * HC1];
__device__ __half g_h1h[NN * HC1];
__device__ float  g_logits[ET * H1C * 4];
__device__ float  g_pool[GG * HC2];
__device__ float  g_cnt[GG];
__device__ float  g_m1[GG * 512];
__device__ float  g_m2[GG * 256];
__device__ __half g_w1h[2 * HC1 * DNODE];
__device__ __half g_w2h[2 * HC2 * HC1];
__device__ __half g_we1h[HC1 * DEDGE];
__device__ __half g_we2h[HC2 * DEDGE];

// ---------------- helpers ----------------
__device__ __forceinline__ float warp_sum(float v) {
    #pragma unroll
    for (int o = 16; o; o >>= 1) v += __shfl_xor_sync(0xffffffffu, v, o);
    return v;
}
__device__ __forceinline__ float warp_max(float v) {
    #pragma unroll
    for (int o = 16; o; o >>= 1) v = fmaxf(v, __shfl_xor_sync(0xffffffffu, v, o));
    return v;
}
__device__ __forceinline__ uint32_t smem_u32(const void* p) {
    uint32_t a;
    asm("{ .reg .u64 t; cvta.to.shared.u64 t, %1; cvt.u32.u64 %0, t; }" : "=r"(a) : "l"(p));
    return a;
}
__device__ __forceinline__ void mma_f16(float* c, uint4 a, uint2 b) {
    asm volatile(
        "mma.sync.aligned.m16n8k16.row.col.f32.f16.f16.f32 "
        "{%0,%1,%2,%3},{%4,%5,%6,%7},{%8,%9},{%0,%1,%2,%3};"
        : "+f"(c[0]), "+f"(c[1]), "+f"(c[2]), "+f"(c[3])
        : "r"(a.x), "r"(a.y), "r"(a.z), "r"(a.w), "r"(b.x), "r"(b.y));
}
__device__ __forceinline__ uint4 ldsm4(uint32_t addr) {
    uint4 r;
    asm volatile("ldmatrix.sync.aligned.m8n8.x4.shared.b16 {%0,%1,%2,%3}, [%4];"
        : "=r"(r.x), "=r"(r.y), "=r"(r.z), "=r"(r.w) : "r"(addr));
    return r;
}
__device__ __forceinline__ void cp16(uint32_t dst, const void* src) {
    asm volatile("cp.async.cg.shared.global [%0], [%1], 16;" :: "r"(dst), "l"(src));
}

// =================================================================
// cp.async + ldmatrix fp16 GEMM (3-stage, XOR swizzle) — proven R7-11.
// =================================================================
#define GEMM_STAGE_BYTES 32768
#define GEMM_SMEM_BYTES  (3 * GEMM_STAGE_BYTES)

__device__ __forceinline__ void issue_stage(
    const __half* __restrict__ A, const __half* __restrict__ B, int K,
    int rowBase, int colBase, int k0, uint32_t abase, int tid)
{
    #pragma unroll
    for (int i = 0; i < 4; i++) {
        int id = i * 256 + tid;
        int r = id >> 3, c = id & 7;
        uint32_t off = (uint32_t)(r * 128 + ((c ^ (r & 7)) << 4));
        cp16(abase + off,         A + (size_t)(rowBase + r) * K + k0 + c * 8);
        cp16(abase + 16384 + off, B + (size_t)(colBase + r) * K + k0 + c * 8);
    }
    asm volatile("cp.async.commit_group;" ::: "memory");
}

__global__ __launch_bounds__(256, 2) void k_mma_dual(
    const __half* __restrict__ A, const __half* __restrict__ B,
    const float* __restrict__ biasL, const float* __restrict__ biasR,
    __half* __restrict__ outL, __half* __restrict__ outR,
    int M, int N, int K)
{
    extern __shared__ char smem[];
    uint32_t sb = smem_u32(smem);
    int tid = threadIdx.x;
    int wid = tid >> 5, lane = tid & 31;
    int mw = wid & 3, nw = wid >> 2;
    int gid = lane >> 2, tig = lane & 3;
    int rowBase = blockIdx.y * 128, colBase = blockIdx.x * 128;

    float acc[2][8][4];
    #pragma unroll
    for (int mt = 0; mt < 2; mt++)
        #pragma unroll
        for (int nt = 0; nt < 8; nt++)
            #pragma unroll
            for (int q = 0; q < 4; q++) acc[mt][nt][q] = 0.f;

    const int NCH = K >> 6;
    issue_stage(A, B, K, rowBase, colBase, 0, sb, tid);
    if (NCH > 1) issue_stage(A, B, K, rowBase, colBase, 64, sb + GEMM_STAGE_BYTES, tid);

    int arow = mw * 32 + (lane & 15);
    int achoff = lane >> 4;
    int brow = nw * 64 + ((lane >> 4) << 3) + (lane & 7);
    int bchoff = (lane >> 3) & 1;

    for (int c = 0; c < NCH; c++) {
        if (c + 2 <= NCH) asm volatile("cp.async.wait_group 1;" ::: "memory");
        else              asm volatile("cp.async.wait_group 0;" ::: "memory");
        __syncthreads();
        if (c + 2 < NCH)
            issue_stage(A, B, K, rowBase, colBase, (c + 2) << 6,
                        sb + ((c + 2) % 3) * GEMM_STAGE_BYTES, tid);

        uint32_t Ab = sb + (c % 3) * GEMM_STAGE_BYTES;
        uint32_t Bb = Ab + 16384;
        #pragma unroll
        for (int kstep = 0; kstep < 4; kstep++) {
            uint4 afr[2];
            #pragma unroll
            for (int mt = 0; mt < 2; mt++) {
                int row = arow + mt * 16;
                int ch = kstep * 2 + achoff;
                afr[mt] = ldsm4(Ab + row * 128 + ((ch ^ (row & 7)) << 4));
            }
            uint2 bfr[8];
            #pragma unroll
            for (int ntp = 0; ntp < 4; ntp++) {
                int row = brow + ntp * 16;
                int ch = kstep * 2 + bchoff;
                uint4 t = ldsm4(Bb + row * 128 + ((ch ^ (row & 7)) << 4));
                bfr[2 * ntp]     = make_uint2(t.x, t.y);
                bfr[2 * ntp + 1] = make_uint2(t.z, t.w);
            }
            #pragma unroll
            for (int mt = 0; mt < 2; mt++)
                #pragma unroll
                for (int nt = 0; nt < 8; nt++)
                    mma_f16(acc[mt][nt], afr[mt], bfr[nt]);
        }
    }

    int halfN = N >> 1;
    bool isR = (colBase >= halfN);
    const float* bias = isR ? biasR : biasL;
    __half* outp = isR ? outR : outL;
    int cb = colBase - (isR ? halfN : 0);

    #pragma unroll
    for (int mt = 0; mt < 2; mt++) {
        int row0 = rowBase + mw * 32 + mt * 16 + gid;
        #pragma unroll
        for (int nt = 0; nt < 8; nt++) {
            int col = cb + nw * 64 + nt * 8 + tig * 2;
            float b0 = bias[col], b1 = bias[col + 1];
            float c0 = acc[mt][nt][0] + b0, c1 = acc[mt][nt][1] + b1;
            float c2 = acc[mt][nt][2] + b0, c3 = acc[mt][nt][3] + b1;
            *reinterpret_cast<__half2*>(outp + (size_t)row0 * halfN + col)       = __floats2half2_rn(c0, c1);
            *reinterpret_cast<__half2*>(outp + (size_t)(row0 + 8) * halfN + col) = __floats2half2_rn(c2, c3);
        }
    }
}

// =================================================================
// Fused edge-feature GEMM + logits, smem-staged xl/xr gathers (R11).
// =================================================================
#define EEL_XL_OFF 16384
#define EEL_XR_OFF (16384 + 128 * 272)
#define EEL_SMEM_BYTES (16384 + 2 * 128 * 272)

__device__ __forceinline__ void ldg_tile_h(
    const __half* __restrict__ A, const __half* __restrict__ B, int K,
    int rowBase, int colBase, int kc, int tid, uint2* pa, uint2* pb)
{
    #pragma unroll
    for (int i = 0; i < 4; i++) {
        int id = i * 256 + tid;
        int r = id >> 3, c4 = id & 7;
        pa[i] = *reinterpret_cast<const uint2*>(A + (size_t)(rowBase + r) * K + kc + c4 * 4);
        pb[i] = *reinterpret_cast<const uint2*>(B + (size_t)(colBase + r) * K + kc + c4 * 4);
    }
}
__device__ __forceinline__ void sts_tile(
    uint32_t* __restrict__ sA, uint32_t* __restrict__ sB,
    int tid, const uint2* pa, const uint2* pb)
{
    #pragma unroll
    for (int i = 0; i < 4; i++) {
        int id = i * 256 + tid;
        int r = id >> 3, c4 = id & 7;
        int kstep = c4 >> 2;
        int pl = (c4 & 3) * 2;
        int mtile = r >> 4, ri = r & 15;
        int regA = ((pl & 4) ? 2 : 0) + (ri >> 3);
        int laneA = (ri & 7) * 4 + (pl & 3);
        int baseA = (kstep * 8 + mtile) * 128;
        sA[baseA + laneA * 4 + regA]       = pa[i].x;
        sA[baseA + (laneA + 1) * 4 + regA] = pa[i].y;
        int ntile = r >> 3, ni = r & 7;
        int regB = (pl & 4) ? 1 : 0;
        int laneB = ni * 4 + (pl & 3);
        int baseB = (kstep * 16 + ntile) * 64;
        sB[baseB + laneB * 2 + regB]       = pb[i].x;
        sB[baseB + (laneB + 1) * 2 + regB] = pb[i].y;
    }
}

template <int H>
__global__ __launch_bounds__(256) void k_ee_logits(
    const __half* __restrict__ A, const __half* __restrict__ B,
    const float* __restrict__ att)
{
    extern __shared__ uint32_t sm[];
    uint32_t sb = smem_u32(sm);
    int tid = threadIdx.x;
    int wid = tid >> 5, lane = tid & 31;
    int mw = wid & 3, nw = wid >> 2;
    int gid = lane >> 2, tig = lane & 3;
    int rowBase = blockIdx.y * 128, colBase = blockIdx.x * 128;
    const int HC = H * CC;

    #pragma unroll
    for (int i = 0; i < 8; i++) {
        int idx = i * 256 + tid;
        int el = idx >> 4, p = idx & 15;
        int eg = rowBase + el;
        int s = g_psrc[eg], d = g_pdst[eg];
        cp16(sb + EEL_XL_OFF + el * 272 + p * 16, g_xl + (size_t)s * HC + colBase + p * 8);
        cp16(sb + EEL_XR_OFF + el * 272 + p * 16, g_xr + (size_t)d * HC + colBase + p * 8);
    }
    asm volatile("cp.async.commit_group;" ::: "memory");

    float acc[2][8][4];
    #pragma unroll
    for (int mt = 0; mt < 2; mt++)
        #pragma unroll
        for (int nt = 0; nt < 8; nt++)
            #pragma unroll
            for (int q = 0; q < 4; q++) acc[mt][nt][q] = 0.f;

    uint2 pa[4], pb[4];
    ldg_tile_h(A, B, DEDGE, rowBase, colBase, 0, tid, pa, pb);
    sts_tile(sm, sm + 2048, tid, pa, pb);
    __syncthreads();

    #pragma unroll
    for (int kstep = 0; kstep < 2; kstep++) {
        uint4 afr[2];
        #pragma unroll
        for (int mt = 0; mt < 2; mt++)
            afr[mt] = *reinterpret_cast<const uint4*>(
                sm + (kstep * 8 + mw * 2 + mt) * 128 + lane * 4);
        uint2 bfr[8];
        #pragma unroll
        for (int nt = 0; nt < 8; nt++)
            bfr[nt] = *reinterpret_cast<const uint2*>(
                sm + 2048 + (kstep * 16 + nw * 8 + nt) * 64 + lane * 2);
        #pragma unroll
        for (int mt = 0; mt < 2; mt++)
            #pragma unroll
            for (int nt = 0; nt < 8; nt++)
                mma_f16(acc[mt][nt], afr[mt], bfr[nt]);
    }

    asm volatile("cp.async.wait_group 0;" ::: "memory");
    __syncthreads();

    int h = colBase >> 8;
    int q = ((blockIdx.x & 1) << 1) | nw;
    const __half2* sXL = reinterpret_cast<const __half2*>((const char*)sm + EEL_XL_OFF);
    const __half2* sXR = reinterpret_cast<const __half2*>((const char*)sm + EEL_XR_OFF);

    #pragma unroll
    for (int mt = 0; mt < 2; mt++) {
        int el0 = mw * 32 + mt * 16 + gid;
        int el1 = el0 + 8;
        float p0 = 0.f, p1 = 0.f;
        #pragma unroll
        for (int nt = 0; nt < 8; nt++) {
            int coff = nw * 32 + nt * 4 + tig;
            int col = colBase + nw * 64 + nt * 8 + tig * 2;
            float2 at = *reinterpret_cast<const float2*>(att + h * CC + (col & (CC - 1)));
            float2 a0 = __half22float2(sXL[el0 * 68 + coff]);
            float2 b0 = __half22float2(sXR[el0 * 68 + coff]);
            float2 a1 = __half22float2(sXL[el1 * 68 + coff]);
            float2 b1 = __half22float2(sXR[el1 * 68 + coff]);
            float v0 = acc[mt][nt][0] + a0.x + b0.x;
            float v1 = acc[mt][nt][1] + a0.y + b0.y;
            float v2 = acc[mt][nt][2] + a1.x + b1.x;
            float v3 = acc[mt][nt][3] + a1.y + b1.y;
            v0 = (v0 > 0.f) ? v0 : NEG_SLOPE * v0;
            v1 = (v1 > 0.f) ? v1 : NEG_SLOPE * v1;
            v2 = (v2 > 0.f) ? v2 : NEG_SLOPE * v2;
            v3 = (v3 > 0.f) ? v3 : NEG_SLOPE * v3;
            p0 += v0 * at.x + v1 * at.y;
            p1 += v2 * at.x + v3 * at.y;
        }
        p0 += __shfl_xor_sync(0xffffffffu, p0, 1);
        p0 += __shfl_xor_sync(0xffffffffu, p0, 2);
        p1 += __shfl_xor_sync(0xffffffffu, p1, 1);
        p1 += __shfl_xor_sync(0xffffffffu, p1, 2);
        if (tig == 0) {
            g_logits[((rowBase + el0) * H + h) * 4 + q] = p0;
            g_logits[((rowBase + el1) * H + h) * 4 + q] = p1;
        }
    }
}

// ---------------- weight / input conversion ----------------
__global__ void k_wconv(const float* __restrict__ Wl1, const float* __restrict__ Wr1,
                        const float* __restrict__ Wl2, const float* __restrict__ Wr2,
                        const float* __restrict__ We1, const float* __restrict__ We2,
                        const float* __restrict__ x)
{
    int t = blockIdx.x * blockDim.x + threadIdx.x;
    const int s1 = HC1 * DNODE;
    const int s2 = HC2 * HC1;
    const int s3 = HC1 * DEDGE;
    const int s4 = HC2 * DEDGE;
    if (t < s1) { g_w1h[t] = __float2half_rn(Wl1[t]); g_w1h[s1 + t] = __float2half_rn(Wr1[t]); }
    if (t < s2) { g_w2h[t] = __float2half_rn(Wl2[t]); g_w2h[s2 + t] = __float2half_rn(Wr2[t]); }
    if (t < s3) g_we1h[t] = __float2half_rn(We1[t]);
    if (t < s4) g_we2h[t] = __float2half_rn(We2[t]);
    if (t < NN * DNODE) g_xh[t] = __float2half_rn(x[t]);
}

// ---------------- graph prep ----------------
__global__ void k_detect(const int* __restrict__ ei) {
    int is64 = 1;
    for (int i = 0; i < 16; i++)
        if (ei[2 * i + 1] != 0) is64 = 0;
    g_is64 = is64;
}
__global__ void k_prep(const int* __restrict__ ei, const int* __restrict__ batch) {
    int t = blockIdx.x * blockDim.x + threadIdx.x;
    int is64 = g_is64;
    if (t < EE) {
        g_src[t] = is64 ? ei[2 * t]        : ei[t];
        g_dst[t] = is64 ? ei[2 * (EE + t)] : ei[EE + t];
    }
    if (t < NN) {
        g_batch[t] = is64 ? batch[2 * t] : batch[t];
        g_deg[t] = 0;
        g_cur[t] = 0;
    }
    if (t < NN * DEDGE) g_easum[t] = 0.f;
    if (t < GG * HC2) g_pool[t] = 0.f;
}
__global__ void k_deg_easum(const float* __restrict__ ea) {
    int t = blockIdx.x * blockDim.x + threadIdx.x;
    if (t >= EE * DEDGE) return;
    int e = t >> 5, d = t & 31;
    int dst = g_dst[e];
    atomicAdd(&g_easum[dst * DEDGE + d], ea[t]);
    if (d == 0) atomicAdd(&g_deg[dst], 1);
}
__global__ void k_scan() {
    __shared__ int part[256];
    __shared__ int scnt[GG];
    int t = threadIdx.x;
    if (t < GG) scnt[t] = 0;
    __syncthreads();
    int base = t * 32;
    int loc[32];
    int s = 0;
    #pragma unroll
    for (int i = 0; i < 32; i++) {
        loc[i] = s; s += g_deg[base + i] + 1;
        atomicAdd(&scnt[g_batch[base + i]], 1);
    }
    part[t] = s;
    __syncthreads();
    if (t == 0) {
        int acc = 0;
        for (int i = 0; i < 256; i++) { int v = part[i]; part[i] = acc; acc += v; }
        g_off[NN] = acc;
    }
    __syncthreads();
    int p = part[t];
    #pragma unroll
    for (int i = 0; i < 32; i++) g_off[base + i] = p + loc[i];
    if (t < GG) g_cnt[t] = (float)scnt[t];
}
__global__ void k_csr() {
    int e = blockIdx.x * blockDim.x + threadIdx.x;
    if (e >= ET) return;
    int s, node;
    if (e < EE) { s = g_src[e]; node = g_dst[e]; } else { s = node = e - EE; }
    int pos = g_off[node] + atomicAdd(&g_cur[node], 1);
    g_pedge[pos] = e;
    g_psrc[pos]  = s;
    g_pdst[pos]  = node;
}
__global__ void k_ea2(const float* __restrict__ ea) {
    int t = blockIdx.x * blockDim.x + threadIdx.x;
    if (t >= ET * DEDGE) return;
    int pos = t >> 5, d = t & 31;
    int e = g_pedge[pos];
    float v;
    if (e < EE) {
        v = ea[e * DEDGE + d];
    } else {
        int n = e - EE;
        v = g_easum[n * DEDGE + d] / fmaxf((float)g_deg[n], 1.f);
    }
    g_ea2h[t] = __float2half_rn(v);
}

// ---------------- fp32 SGEMM for the tiny MLP ----------------
__global__ __launch_bounds__(256) void k_sgemm(
    const float* __restrict__ A, const float* __restrict__ Bm,
    const float* __restrict__ bias, float* __restrict__ Cm,
    int M, int Nc, int K, int act)
{
    constexpr int BM = 128, BN = 128, BK = 16, TM = 8, TN = 8;
    __shared__ float As[BK][BM];
    __shared__ float Bs[BK][BN];
    int tid = threadIdx.x;
    int tx = tid % 16, ty = tid / 16;
    int rowBase = blockIdx.y * BM;
    int colBase = blockIdx.x * BN;
    float acc[TM][TN];
    #pragma unroll
    for (int i = 0; i < TM; i++)
        #pragma unroll
        for (int j = 0; j < TN; j++) acc[i][j] = 0.f;
    for (int k0 = 0; k0 < K; k0 += BK) {
        #pragma unroll
        for (int i = 0; i < 2; i++) {
            int f4 = tid + i * 256;
            int r = f4 >> 2;
            int kk = (f4 & 3) * 4;
            int gr = rowBase + r;
            float4 v = make_float4(0.f, 0.f, 0.f, 0.f);
            if (gr < M) v = *reinterpret_cast<const float4*>(A + (size_t)gr * K + k0 + kk);
            As[kk + 0][r] = v.x; As[kk + 1][r] = v.y; As[kk + 2][r] = v.z; As[kk + 3][r] = v.w;
            int gc = colBase + r;
            float4 w = make_float4(0.f, 0.f, 0.f, 0.f);
            if (gc < Nc) w = *reinterpret_cast<const float4*>(Bm + (size_t)gc * K + k0 + kk);
            Bs[kk + 0][r] = w.x; Bs[kk + 1][r] = w.y; Bs[kk + 2][r] = w.z; Bs[kk + 3][r] = w.w;
        }
        __syncthreads();
        #pragma unroll
        for (int k = 0; k < BK; k++) {
            float a[TM], b[TN];
            #pragma unroll
            for (int i = 0; i < TM; i++) a[i] = As[k][ty * TM + i];
            #pragma unroll
            for (int j = 0; j < TN; j++) b[j] = Bs[k][tx * TN + j];
            #pragma unroll
            for (int i = 0; i < TM; i++)
                #pragma unroll
                for (int j = 0; j < TN; j++) acc[i][j] = fmaf(a[i], b[j], acc[i][j]);
        }
        __syncthreads();
    }
    #pragma unroll
    for (int i = 0; i < TM; i++) {
        int gr = rowBase + ty * TM + i;
        if (gr >= M) continue;
        #pragma unroll
        for (int j = 0; j < TN; j++) {
            int gc = colBase + tx * TN + j;
            if (gc >= Nc) continue;
            float v = acc[i][j];
            if (bias) v += bias[gc];
            if (act) v = fmaxf(v, 0.f);
            Cm[(size_t)gr * Nc + gc] = v;
        }
    }
}

// ---------------- segment softmax + weighted gather (csr order) ----------------
template <int H, int RELU, int OUTMODE>
__global__ void k_aggregate(const float* __restrict__ bias, void* __restrict__ out) {
    int n = blockIdx.x;
    int h = threadIdx.x >> 5, lane = threadIdx.x & 31;
    int s0 = g_off[n], s1 = g_off[n + 1];
    int cnt = s1 - s0;
    const int HCH = H * (CC / 2);
    const __half2* xl = reinterpret_cast<const __half2*>(g_xl);
    float2 acc[4];
    #pragma unroll
    for (int j = 0; j < 4; j++) acc[j] = make_float2(0.f, 0.f);

    if (cnt <= 64) {
        int cs0 = 0, cs1 = 0;
        float lv0 = -1e30f, lv1 = -1e30f;
        if (lane < cnt) {
            int p = s0 + lane;
            cs0 = g_psrc[p];
            float4 lg = *reinterpret_cast<const float4*>(&g_logits[(p * H + h) * 4]);
            lv0 = (lg.x + lg.y) + (lg.z + lg.w);
        }
        if (lane + 32 < cnt) {
            int p = s0 + lane + 32;
            cs1 = g_psrc[p];
            float4 lg = *reinterpret_cast<const float4*>(&g_logits[(p * H + h) * 4]);
            lv1 = (lg.x + lg.y) + (lg.z + lg.w);
        }
        float mx = warp_max(fmaxf(lv0, lv1));
        float ex0 = (lane < cnt)      ? __expf(lv0 - mx) : 0.f;
        float ex1 = (lane + 32 < cnt) ? __expf(lv1 - mx) : 0.f;
        float inv = 1.f / warp_sum(ex0 + ex1);
        for (int i = 0; i < cnt; i++) {
            int srcl = i & 31;
            float w = __shfl_sync(0xffffffffu, (i < 32) ? ex0 : ex1, srcl) * inv;
            int s = __shfl_sync(0xffffffffu, (i < 32) ? cs0 : cs1, srcl);
            const __half2* row = xl + (size_t)s * HCH + h * 128 + lane;
            #pragma unroll
            for (int j = 0; j < 4; j++) {
                float2 f = __half22float2(row[32 * j]);
                acc[j].x = fmaf(w, f.x, acc[j].x);
                acc[j].y = fmaf(w, f.y, acc[j].y);
            }
        }
    } else {
        float mx = -1e30f;
        for (int i = s0 + lane; i < s1; i += 32) {
            float4 lg = *reinterpret_cast<const float4*>(&g_logits[(i * H + h) * 4]);
            mx = fmaxf(mx, (lg.x + lg.y) + (lg.z + lg.w));
        }
        mx = warp_max(mx);
        float den = 0.f;
        for (int i = s0 + lane; i < s1; i += 32) {
            float4 lg = *reinterpret_cast<const float4*>(&g_logits[(i * H + h) * 4]);
            den += __expf((lg.x + lg.y) + (lg.z + lg.w) - mx);
        }
        den = warp_sum(den);
        float inv = 1.f / den;
        for (int i = s0; i < s1; i++) {
            float4 lg = *reinterpret_cast<const float4*>(&g_logits[(i * H + h) * 4]);
            float w = __expf((lg.x + lg.y) + (lg.z + lg.w) - mx) * inv;
            int s = g_psrc[i];
            const __half2* row = xl + (size_t)s * HCH + h * 128 + lane;
            #pragma unroll
            for (int j = 0; j < 4; j++) {
                float2 f = __half22float2(row[32 * j]);
                acc[j].x = fmaf(w, f.x, acc[j].x);
                acc[j].y = fmaf(w, f.y, acc[j].y);
            }
        }
    }

    int b = (OUTMODE == 2) ? g_batch[n] : 0;
    #pragma unroll
    for (int j = 0; j < 4; j++) {
        int col = h * CC + 2 * (lane + 32 * j);
        float2 bb = *reinterpret_cast<const float2*>(bias + col);
        float v0 = acc[j].x + bb.x, v1 = acc[j].y + bb.y;
        if (RELU) { v0 = fmaxf(v0, 0.f); v1 = fmaxf(v1, 0.f); }
        if (OUTMODE == 1) {
            __half* oh = (__half*)out;
            *reinterpret_cast<__half2*>(oh + (size_t)n * (H * CC) + col) = __floats2half2_rn(v0, v1);
        } else if (OUTMODE == 0) {
            float* of = (float*)out;
            *reinterpret_cast<float2*>(of + (size_t)n * (H * CC) + col) = make_float2(v0, v1);
        } else {
            atomicAdd(&g_pool[b * HC2 + col], v0);
            atomicAdd(&g_pool[b * HC2 + col + 1], v1);
        }
    }
}

// ---------------- pool divide + final ----------------
__global__ void k_pool_div() {
    int t = blockIdx.x * blockDim.x + threadIdx.x;
    if (t >= GG * HC2) return;
    g_pool[t] /= fmaxf(g_cnt[t >> 10], 1.f);
}
__global__ void k_final(const float* __restrict__ W3, const float* __restrict__ b3,
                        float* __restrict__ out) {
    int g = blockIdx.x, lane = threadIdx.x;
    float acc = 0.f;
    #pragma unroll
    for (int j = 0; j < 8; j++) acc += g_m2[g * 256 + lane + 32 * j] * W3[lane + 32 * j];
    acc = warp_sum(acc);
    if (lane == 0) out[g] = 1.f / (1.f + expf(-(acc + b3[0])));
}

// ---------------- host launch ----------------
static inline void launch_sgemm(const float* A, const float* B, const float* bias,
                                float* C, int M, int Nc, int K, int act) {
    dim3 grid((Nc + 127) / 128, (M + 127) / 128);
    k_sgemm<<<grid, 256>>>(A, B, bias, C, M, Nc, K, act);
}

extern "C" void kernel_launch(void* const* d_in, const int* in_sizes, int n_in,
                              void* d_out, int out_size) {
    const float* x     = (const float*)d_in[0];
    const int*   ei    = (const int*)  d_in[1];
    const float* ea    = (const float*)d_in[2];
    const int*   batch = (const int*)  d_in[3];
    const float* Wl1 = (const float*)d_in[4],  *bl1 = (const float*)d_in[5];
    const float* Wr1 = (const float*)d_in[6],  *br1 = (const float*)d_in[7];
    const float* We1 = (const float*)d_in[8],  *att1 = (const float*)d_in[9];
    const float* bias1 = (const float*)d_in[10];
    const float* Wl2 = (const float*)d_in[11], *bl2 = (const float*)d_in[12];
    const float* Wr2 = (const float*)d_in[13], *br2 = (const float*)d_in[14];
    const float* We2 = (const float*)d_in[15], *att2 = (const float*)d_in[16];
    const float* bias2 = (const float*)d_in[17];
    const float* W1 = (const float*)d_in[18], *b1 = (const float*)d_in[19];
    const float* W2 = (const float*)d_in[20], *b2 = (const float*)d_in[21];
    const float* W3 = (const float*)d_in[22], *b3 = (const float*)d_in[23];
    float* out = (float*)d_out;

    static int s_init = 0;
    static cudaStream_t s1;
    static cudaEvent_t eFork, eJoin;
    if (!s_init) {
        cudaFuncSetAttribute(k_mma_dual, cudaFuncAttributeMaxDynamicSharedMemorySize, GEMM_SMEM_BYTES);
        cudaFuncSetAttribute(k_ee_logits<H1C>, cudaFuncAttributeMaxDynamicSharedMemorySize, EEL_SMEM_BYTES);
        cudaFuncSetAttribute(k_ee_logits<H2C>, cudaFuncAttributeMaxDynamicSharedMemorySize, EEL_SMEM_BYTES);
        cudaStreamCreateWithFlags(&s1, cudaStreamNonBlocking);
        cudaEventCreateWithFlags(&eFork, cudaEventDisableTiming);
        cudaEventCreateWithFlags(&eJoin, cudaEventDisableTiming);
        s_init = 1;
    }

    float *p_pool, *p_m1, *p_m2;
    __half *p_xl, *p_xr, *p_h1h, *p_ea2h, *p_w1h, *p_w2h, *p_we1h, *p_we2h, *p_xh;
    cudaGetSymbolAddress((void**)&p_xl,    g_xl);
    cudaGetSymbolAddress((void**)&p_xr,    g_xr);
    cudaGetSymbolAddress((void**)&p_h1h,   g_h1h);
    cudaGetSymbolAddress((void**)&p_ea2h,  g_ea2h);
    cudaGetSymbolAddress((void**)&p_w1h,   g_w1h);
    cudaGetSymbolAddress((void**)&p_w2h,   g_w2h);
    cudaGetSymbolAddress((void**)&p_we1h,  g_we1h);
    cudaGetSymbolAddress((void**)&p_we2h,  g_we2h);
    cudaGetSymbolAddress((void**)&p_xh,    g_xh);
    cudaGetSymbolAddress((void**)&p_pool,  g_pool);
    cudaGetSymbolAddress((void**)&p_m1,    g_m1);
    cudaGetSymbolAddress((void**)&p_m2,    g_m2);

    // --- fork: graph-prep chain on s1, GEMM path on default stream ---
    cudaEventRecord(eFork, 0);
    cudaStreamWaitEvent(s1, eFork, 0);

    // side stream: detect -> prep -> deg_easum -> scan -> csr -> ea2
    k_detect<<<1, 1, 0, s1>>>(ei);
    k_prep<<<(NN * DEDGE + 255) / 256, 256, 0, s1>>>(ei, batch);
    k_deg_easum<<<(EE * DEDGE + 255) / 256, 256, 0, s1>>>(ea);
    k_scan<<<1, 256, 0, s1>>>();
    k_csr<<<(ET + 255) / 256, 256, 0, s1>>>();
    k_ea2<<<(ET * DEDGE + 255) / 256, 256, 0, s1>>>(ea);
    cudaEventRecord(eJoin, s1);

    // default stream: wconv -> layer-1 GEMM (independent of prep chain)
    k_wconv<<<(HC2 * HC1 + 255) / 256, 256>>>(Wl1, Wr1, Wl2, Wr2, We1, We2, x);
    k_mma_dual<<<dim3(2 * HC1 / 128, NN / 128), 256, GEMM_SMEM_BYTES>>>(
        p_xh, p_w1h, bl1, br1, p_xl, p_xr, NN, 2 * HC1, DNODE);

    // join: ee_logits needs csr/ea2 + xl/xr
    cudaStreamWaitEvent(0, eJoin, 0);

    // --- GATv2 layer 1 ---
    k_ee_logits<H1C><<<dim3(HC1 / 128, ET / 128), 256, EEL_SMEM_BYTES>>>(p_ea2h, p_we1h, att1);
    k_aggregate<H1C, 1, 1><<<NN, H1C * 32>>>(bias1, p_h1h);

    // --- GATv2 layer 2 (aggregate pools directly) ---
    k_mma_dual<<<dim3(2 * HC2 / 128, NN / 128), 256, GEMM_SMEM_BYTES>>>(
        p_h1h, p_w2h, bl2, br2, p_xl, p_xr, NN, 2 * HC2, HC1);
    k_ee_logits<H2C><<<dim3(HC2 / 128, ET / 128), 256, EEL_SMEM_BYTES>>>(p_ea2h, p_we2h, att2);
    k_aggregate<H2C, 0, 2><<<NN, H2C * 32>>>(bias2, nullptr);

    // --- pool + MLP ---
    k_pool_div<<<(GG * HC2 + 255) / 256, 256>>>();
    launch_sgemm(p_pool, W1, b1, p_m1, GG, 512, HC2, 1);
    launch_sgemm(p_m1,  W2, b2, p_m2, GG, 256, 512, 1);
    k_final<<<GG, 32>>>(W3, b3, out);
}

// round 13
// speedup vs baseline: 4.8111x; 1.0059x over previous
#include <cuda_runtime.h>
#include <cuda_fp16.h>
#include <math.h>
#include <stdint.h>

// ---------------- problem constants ----------------
#define NN   8192
#define EE   65536
#define GG   64
#define DNODE 64
#define DEDGE 32
#define CC   256
#define H1C  8
#define H2C  4
#define ET   (EE + NN)          // 73728 = 576*128
#define HC1  (H1C * CC)         // 2048
#define HC2  (H2C * CC)         // 1024
#define NEG_SLOPE 0.2f

// ---------------- device scratch ----------------
__device__ int    g_is64;
__device__ int    g_src[EE];
__device__ int    g_dst[EE];
__device__ int    g_batch[NN];
__device__ int    g_deg[NN];
__device__ int    g_cur[NN];
__device__ int    g_off[NN + 1];
__device__ int    g_gstart[GG];
__device__ int    g_gend[GG];
__device__ int    g_pedge[ET];
__device__ int    g_psrc[ET];
__device__ int    g_pdst[ET];
__device__ __half g_ea2h[ET * DEDGE];
__device__ __half g_xh[NN * DNODE];
__device__ __half g_xl[NN * HC1];
__device__ __half g_xr[NN * HC1];
__device__ __half g_h1h[NN * HC1];
__device__ float  g_logits[ET * H1C * 4];
__device__ float  g_pool[GG * HC2];
__device__ float  g_m1[GG * 512];
__device__ float  g_m2[GG * 256];
__device__ __half g_w1h[2 * HC1 * DNODE];
__device__ __half g_w2h[2 * HC2 * HC1];
__device__ __half g_we1h[HC1 * DEDGE];
__device__ __half g_we2h[HC2 * DEDGE];

// ---------------- helpers ----------------
__device__ __forceinline__ float warp_sum(float v) {
    #pragma unroll
    for (int o = 16; o; o >>= 1) v += __shfl_xor_sync(0xffffffffu, v, o);
    return v;
}
__device__ __forceinline__ float warp_max(float v) {
    #pragma unroll
    for (int o = 16; o; o >>= 1) v = fmaxf(v, __shfl_xor_sync(0xffffffffu, v, o));
    return v;
}
__device__ __forceinline__ uint32_t smem_u32(const void* p) {
    uint32_t a;
    asm("{ .reg .u64 t; cvta.to.shared.u64 t, %1; cvt.u32.u64 %0, t; }" : "=r"(a) : "l"(p));
    return a;
}
__device__ __forceinline__ void mma_f16(float* c, uint4 a, uint2 b) {
    asm volatile(
        "mma.sync.aligned.m16n8k16.row.col.f32.f16.f16.f32 "
        "{%0,%1,%2,%3},{%4,%5,%6,%7},{%8,%9},{%0,%1,%2,%3};"
        : "+f"(c[0]), "+f"(c[1]), "+f"(c[2]), "+f"(c[3])
        : "r"(a.x), "r"(a.y), "r"(a.z), "r"(a.w), "r"(b.x), "r"(b.y));
}
__device__ __forceinline__ uint4 ldsm4(uint32_t addr) {
    uint4 r;
    asm volatile("ldmatrix.sync.aligned.m8n8.x4.shared.b16 {%0,%1,%2,%3}, [%4];"
        : "=r"(r.x), "=r"(r.y), "=r"(r.z), "=r"(r.w) : "r"(addr));
    return r;
}
__device__ __forceinline__ void cp16(uint32_t dst, const void* src) {
    asm volatile("cp.async.cg.shared.global [%0], [%1], 16;" :: "r"(dst), "l"(src));
}

// =================================================================
// cp.async + ldmatrix fp16 GEMM (3-stage, XOR swizzle) — proven R7-12.
// =================================================================
#define GEMM_STAGE_BYTES 32768
#define GEMM_SMEM_BYTES  (3 * GEMM_STAGE_BYTES)

__device__ __forceinline__ void issue_stage(
    const __half* __restrict__ A, const __half* __restrict__ B, int K,
    int rowBase, int colBase, int k0, uint32_t abase, int tid)
{
    #pragma unroll
    for (int i = 0; i < 4; i++) {
        int id = i * 256 + tid;
        int r = id >> 3, c = id & 7;
        uint32_t off = (uint32_t)(r * 128 + ((c ^ (r & 7)) << 4));
        cp16(abase + off,         A + (size_t)(rowBase + r) * K + k0 + c * 8);
        cp16(abase + 16384 + off, B + (size_t)(colBase + r) * K + k0 + c * 8);
    }
    asm volatile("cp.async.commit_group;" ::: "memory");
}

__global__ __launch_bounds__(256, 2) void k_mma_dual(
    const __half* __restrict__ A, const __half* __restrict__ B,
    const float* __restrict__ biasL, const float* __restrict__ biasR,
    __half* __restrict__ outL, __half* __restrict__ outR,
    int M, int N, int K)
{
    extern __shared__ char smem[];
    uint32_t sb = smem_u32(smem);
    int tid = threadIdx.x;
    int wid = tid >> 5, lane = tid & 31;
    int mw = wid & 3, nw = wid >> 2;
    int gid = lane >> 2, tig = lane & 3;
    int rowBase = blockIdx.y * 128, colBase = blockIdx.x * 128;

    float acc[2][8][4];
    #pragma unroll
    for (int mt = 0; mt < 2; mt++)
        #pragma unroll
        for (int nt = 0; nt < 8; nt++)
            #pragma unroll
            for (int q = 0; q < 4; q++) acc[mt][nt][q] = 0.f;

    const int NCH = K >> 6;
    issue_stage(A, B, K, rowBase, colBase, 0, sb, tid);
    if (NCH > 1) issue_stage(A, B, K, rowBase, colBase, 64, sb + GEMM_STAGE_BYTES, tid);

    int arow = mw * 32 + (lane & 15);
    int achoff = lane >> 4;
    int brow = nw * 64 + ((lane >> 4) << 3) + (lane & 7);
    int bchoff = (lane >> 3) & 1;

    for (int c = 0; c < NCH; c++) {
        if (c + 2 <= NCH) asm volatile("cp.async.wait_group 1;" ::: "memory");
        else              asm volatile("cp.async.wait_group 0;" ::: "memory");
        __syncthreads();
        if (c + 2 < NCH)
            issue_stage(A, B, K, rowBase, colBase, (c + 2) << 6,
                        sb + ((c + 2) % 3) * GEMM_STAGE_BYTES, tid);

        uint32_t Ab = sb + (c % 3) * GEMM_STAGE_BYTES;
        uint32_t Bb = Ab + 16384;
        #pragma unroll
        for (int kstep = 0; kstep < 4; kstep++) {
            uint4 afr[2];
            #pragma unroll
            for (int mt = 0; mt < 2; mt++) {
                int row = arow + mt * 16;
                int ch = kstep * 2 + achoff;
                afr[mt] = ldsm4(Ab + row * 128 + ((ch ^ (row & 7)) << 4));
            }
            uint2 bfr[8];
            #pragma unroll
            for (int ntp = 0; ntp < 4; ntp++) {
                int row = brow + ntp * 16;
                int ch = kstep * 2 + bchoff;
                uint4 t = ldsm4(Bb + row * 128 + ((ch ^ (row & 7)) << 4));
                bfr[2 * ntp]     = make_uint2(t.x, t.y);
                bfr[2 * ntp + 1] = make_uint2(t.z, t.w);
            }
            #pragma unroll
            for (int mt = 0; mt < 2; mt++)
                #pragma unroll
                for (int nt = 0; nt < 8; nt++)
                    mma_f16(acc[mt][nt], afr[mt], bfr[nt]);
        }
    }

    int halfN = N >> 1;
    bool isR = (colBase >= halfN);
    const float* bias = isR ? biasR : biasL;
    __half* outp = isR ? outR : outL;
    int cb = colBase - (isR ? halfN : 0);

    #pragma unroll
    for (int mt = 0; mt < 2; mt++) {
        int row0 = rowBase + mw * 32 + mt * 16 + gid;
        #pragma unroll
        for (int nt = 0; nt < 8; nt++) {
            int col = cb + nw * 64 + nt * 8 + tig * 2;
            float b0 = bias[col], b1 = bias[col + 1];
            float c0 = acc[mt][nt][0] + b0, c1 = acc[mt][nt][1] + b1;
            float c2 = acc[mt][nt][2] + b0, c3 = acc[mt][nt][3] + b1;
            *reinterpret_cast<__half2*>(outp + (size_t)row0 * halfN + col)       = __floats2half2_rn(c0, c1);
            *reinterpret_cast<__half2*>(outp + (size_t)(row0 + 8) * halfN + col) = __floats2half2_rn(c2, c3);
        }
    }
}

// =================================================================
// Fused edge-feature GEMM + logits, smem-staged xl/xr gathers (R11).
// =================================================================
#define EEL_XL_OFF 16384
#define EEL_XR_OFF (16384 + 128 * 272)
#define EEL_SMEM_BYTES (16384 + 2 * 128 * 272)

__device__ __forceinline__ void ldg_tile_h(
    const __half* __restrict__ A, const __half* __restrict__ B, int K,
    int rowBase, int colBase, int kc, int tid, uint2* pa, uint2* pb)
{
    #pragma unroll
    for (int i = 0; i < 4; i++) {
        int id = i * 256 + tid;
        int r = id >> 3, c4 = id & 7;
        pa[i] = *reinterpret_cast<const uint2*>(A + (size_t)(rowBase + r) * K + kc + c4 * 4);
        pb[i] = *reinterpret_cast<const uint2*>(B + (size_t)(colBase + r) * K + kc + c4 * 4);
    }
}
__device__ __forceinline__ void sts_tile(
    uint32_t* __restrict__ sA, uint32_t* __restrict__ sB,
    int tid, const uint2* pa, const uint2* pb)
{
    #pragma unroll
    for (int i = 0; i < 4; i++) {
        int id = i * 256 + tid;
        int r = id >> 3, c4 = id & 7;
        int kstep = c4 >> 2;
        int pl = (c4 & 3) * 2;
        int mtile = r >> 4, ri = r & 15;
        int regA = ((pl & 4) ? 2 : 0) + (ri >> 3);
        int laneA = (ri & 7) * 4 + (pl & 3);
        int baseA = (kstep * 8 + mtile) * 128;
        sA[baseA + laneA * 4 + regA]       = pa[i].x;
        sA[baseA + (laneA + 1) * 4 + regA] = pa[i].y;
        int ntile = r >> 3, ni = r & 7;
        int regB = (pl & 4) ? 1 : 0;
        int laneB = ni * 4 + (pl & 3);
        int baseB = (kstep * 16 + ntile) * 64;
        sB[baseB + laneB * 2 + regB]       = pb[i].x;
        sB[baseB + (laneB + 1) * 2 + regB] = pb[i].y;
    }
}

template <int H>
__global__ __launch_bounds__(256) void k_ee_logits(
    const __half* __restrict__ A, const __half* __restrict__ B,
    const float* __restrict__ att)
{
    extern __shared__ uint32_t sm[];
    uint32_t sb = smem_u32(sm);
    int tid = threadIdx.x;
    int wid = tid >> 5, lane = tid & 31;
    int mw = wid & 3, nw = wid >> 2;
    int gid = lane >> 2, tig = lane & 3;
    int rowBase = blockIdx.y * 128, colBase = blockIdx.x * 128;
    const int HC = H * CC;

    #pragma unroll
    for (int i = 0; i < 8; i++) {
        int idx = i * 256 + tid;
        int el = idx >> 4, p = idx & 15;
        int eg = rowBase + el;
        int s = g_psrc[eg], d = g_pdst[eg];
        cp16(sb + EEL_XL_OFF + el * 272 + p * 16, g_xl + (size_t)s * HC + colBase + p * 8);
        cp16(sb + EEL_XR_OFF + el * 272 + p * 16, g_xr + (size_t)d * HC + colBase + p * 8);
    }
    asm volatile("cp.async.commit_group;" ::: "memory");

    float acc[2][8][4];
    #pragma unroll
    for (int mt = 0; mt < 2; mt++)
        #pragma unroll
        for (int nt = 0; nt < 8; nt++)
            #pragma unroll
            for (int q = 0; q < 4; q++) acc[mt][nt][q] = 0.f;

    uint2 pa[4], pb[4];
    ldg_tile_h(A, B, DEDGE, rowBase, colBase, 0, tid, pa, pb);
    sts_tile(sm, sm + 2048, tid, pa, pb);
    __syncthreads();

    #pragma unroll
    for (int kstep = 0; kstep < 2; kstep++) {
        uint4 afr[2];
        #pragma unroll
        for (int mt = 0; mt < 2; mt++)
            afr[mt] = *reinterpret_cast<const uint4*>(
                sm + (kstep * 8 + mw * 2 + mt) * 128 + lane * 4);
        uint2 bfr[8];
        #pragma unroll
        for (int nt = 0; nt < 8; nt++)
            bfr[nt] = *reinterpret_cast<const uint2*>(
                sm + 2048 + (kstep * 16 + nw * 8 + nt) * 64 + lane * 2);
        #pragma unroll
        for (int mt = 0; mt < 2; mt++)
            #pragma unroll
            for (int nt = 0; nt < 8; nt++)
                mma_f16(acc[mt][nt], afr[mt], bfr[nt]);
    }

    asm volatile("cp.async.wait_group 0;" ::: "memory");
    __syncthreads();

    int h = colBase >> 8;
    int q = ((blockIdx.x & 1) << 1) | nw;
    const __half2* sXL = reinterpret_cast<const __half2*>((const char*)sm + EEL_XL_OFF);
    const __half2* sXR = reinterpret_cast<const __half2*>((const char*)sm + EEL_XR_OFF);

    #pragma unroll
    for (int mt = 0; mt < 2; mt++) {
        int el0 = mw * 32 + mt * 16 + gid;
        int el1 = el0 + 8;
        float p0 = 0.f, p1 = 0.f;
        #pragma unroll
        for (int nt = 0; nt < 8; nt++) {
            int coff = nw * 32 + nt * 4 + tig;
            int col = colBase + nw * 64 + nt * 8 + tig * 2;
            float2 at = *reinterpret_cast<const float2*>(att + h * CC + (col & (CC - 1)));
            float2 a0 = __half22float2(sXL[el0 * 68 + coff]);
            float2 b0 = __half22float2(sXR[el0 * 68 + coff]);
            float2 a1 = __half22float2(sXL[el1 * 68 + coff]);
            float2 b1 = __half22float2(sXR[el1 * 68 + coff]);
            float v0 = acc[mt][nt][0] + a0.x + b0.x;
            float v1 = acc[mt][nt][1] + a0.y + b0.y;
            float v2 = acc[mt][nt][2] + a1.x + b1.x;
            float v3 = acc[mt][nt][3] + a1.y + b1.y;
            v0 = (v0 > 0.f) ? v0 : NEG_SLOPE * v0;
            v1 = (v1 > 0.f) ? v1 : NEG_SLOPE * v1;
            v2 = (v2 > 0.f) ? v2 : NEG_SLOPE * v2;
            v3 = (v3 > 0.f) ? v3 : NEG_SLOPE * v3;
            p0 += v0 * at.x + v1 * at.y;
            p1 += v2 * at.x + v3 * at.y;
        }
        p0 += __shfl_xor_sync(0xffffffffu, p0, 1);
        p0 += __shfl_xor_sync(0xffffffffu, p0, 2);
        p1 += __shfl_xor_sync(0xffffffffu, p1, 1);
        p1 += __shfl_xor_sync(0xffffffffu, p1, 2);
        if (tig == 0) {
            g_logits[((rowBase + el0) * H + h) * 4 + q] = p0;
            g_logits[((rowBase + el1) * H + h) * 4 + q] = p1;
        }
    }
}

// ---------------- weight / input conversion ----------------
__global__ void k_wconv(const float* __restrict__ Wl1, const float* __restrict__ Wr1,
                        const float* __restrict__ Wl2, const float* __restrict__ Wr2,
                        const float* __restrict__ We1, const float* __restrict__ We2,
                        const float* __restrict__ x)
{
    int t = blockIdx.x * blockDim.x + threadIdx.x;
    const int s1 = HC1 * DNODE;
    const int s2 = HC2 * HC1;
    const int s3 = HC1 * DEDGE;
    const int s4 = HC2 * DEDGE;
    if (t < s1) { g_w1h[t] = __float2half_rn(Wl1[t]); g_w1h[s1 + t] = __float2half_rn(Wr1[t]); }
    if (t < s2) { g_w2h[t] = __float2half_rn(Wl2[t]); g_w2h[s2 + t] = __float2half_rn(Wr2[t]); }
    if (t < s3) g_we1h[t] = __float2half_rn(We1[t]);
    if (t < s4) g_we2h[t] = __float2half_rn(We2[t]);
    if (t < NN * DNODE) g_xh[t] = __float2half_rn(x[t]);
}

// ---------------- graph prep ----------------
__global__ void k_detect(const int* __restrict__ ei) {
    int is64 = 1;
    for (int i = 0; i < 16; i++)
        if (ei[2 * i + 1] != 0) is64 = 0;
    g_is64 = is64;
}
__global__ void k_prep(const int* __restrict__ ei, const int* __restrict__ batch) {
    int t = blockIdx.x * blockDim.x + threadIdx.x;
    int is64 = g_is64;
    if (t < EE) {
        g_src[t] = is64 ? ei[2 * t]        : ei[t];
        g_dst[t] = is64 ? ei[2 * (EE + t)] : ei[EE + t];
    }
    if (t < NN) {
        g_batch[t] = is64 ? batch[2 * t] : batch[t];
        g_deg[t] = 0;
        g_cur[t] = 0;
    }
    if (t < GG) { g_gstart[t] = 0; g_gend[t] = 0; }
    if (t < GG * HC2) g_pool[t] = 0.f;
}
__global__ void k_deg() {
    int e = blockIdx.x * blockDim.x + threadIdx.x;
    if (e < EE) atomicAdd(&g_deg[g_dst[e]], 1);
}
// parallel exclusive scan of (deg+1) over NN elements, 256 threads x 32
__global__ void k_scan() {
    __shared__ int wsum[8];
    int t = threadIdx.x, lane = t & 31, wid = t >> 5;
    int base = t * 32;
    int loc[32];
    int s = 0;
    #pragma unroll
    for (int i = 0; i < 32; i++) { loc[i] = s; s += g_deg[base + i] + 1; }
    int v = s;
    #pragma unroll
    for (int o = 1; o < 32; o <<= 1) {
        int u = __shfl_up_sync(0xffffffffu, v, o);
        if (lane >= o) v += u;
    }
    if (lane == 31) wsum[wid] = v;
    __syncthreads();
    if (wid == 0) {
        int w = (lane < 8) ? wsum[lane] : 0;
        #pragma unroll
        for (int o = 1; o < 8; o <<= 1) {
            int u = __shfl_up_sync(0xffffffffu, w, o);
            if (lane >= o) w += u;
        }
        if (lane < 8) wsum[lane] = w;
    }
    __syncthreads();
    int p = v - s + (wid > 0 ? wsum[wid - 1] : 0);
    #pragma unroll
    for (int i = 0; i < 32; i++) g_off[base + i] = p + loc[i];
    if (t == 255) g_off[NN] = p + s;
}
__global__ void k_csr() {
    int e = blockIdx.x * blockDim.x + threadIdx.x;
    if (e >= ET) return;
    int s, node;
    if (e < EE) { s = g_src[e]; node = g_dst[e]; } else { s = node = e - EE; }
    int pos = g_off[node] + atomicAdd(&g_cur[node], 1);
    g_pedge[pos] = e;
    g_psrc[pos]  = s;
    g_pdst[pos]  = node;
    if (e < NN) {
        int b = g_batch[e];
        if (e == 0 || g_batch[e - 1] != b) g_gstart[b] = e;
        if (e == NN - 1 || g_batch[e + 1] != b) g_gend[b] = e + 1;
    }
}
// ea2 in csr order; self-loop rows compute the in-edge mean directly
__global__ void k_ea2(const float* __restrict__ ea) {
    int t = blockIdx.x * blockDim.x + threadIdx.x;
    if (t >= ET * DEDGE) return;
    int pos = t >> 5, d = t & 31;
    int e = g_pedge[pos];
    float v;
    if (e < EE) {
        v = ea[e * DEDGE + d];
    } else {
        int n = e - EE;
        int s0 = g_off[n], s1 = g_off[n + 1];
        float sum = 0.f;
        for (int p = s0; p < s1; p++) {
            int ee = g_pedge[p];
            if (ee < EE) sum += ea[ee * DEDGE + d];
        }
        v = sum / fmaxf((float)(s1 - s0 - 1), 1.f);
    }
    g_ea2h[t] = __float2half_rn(v);
}

// ---------------- fp32 SGEMM for the tiny MLP ----------------
__global__ __launch_bounds__(256) void k_sgemm(
    const float* __restrict__ A, const float* __restrict__ Bm,
    const float* __restrict__ bias, float* __restrict__ Cm,
    int M, int Nc, int K, int act)
{
    constexpr int BM = 128, BN = 128, BK = 16, TM = 8, TN = 8;
    __shared__ float As[BK][BM];
    __shared__ float Bs[BK][BN];
    int tid = threadIdx.x;
    int tx = tid % 16, ty = tid / 16;
    int rowBase = blockIdx.y * BM;
    int colBase = blockIdx.x * BN;
    float acc[TM][TN];
    #pragma unroll
    for (int i = 0; i < TM; i++)
        #pragma unroll
        for (int j = 0; j < TN; j++) acc[i][j] = 0.f;
    for (int k0 = 0; k0 < K; k0 += BK) {
        #pragma unroll
        for (int i = 0; i < 2; i++) {
            int f4 = tid + i * 256;
            int r = f4 >> 2;
            int kk = (f4 & 3) * 4;
            int gr = rowBase + r;
            float4 v = make_float4(0.f, 0.f, 0.f, 0.f);
            if (gr < M) v = *reinterpret_cast<const float4*>(A + (size_t)gr * K + k0 + kk);
            As[kk + 0][r] = v.x; As[kk + 1][r] = v.y; As[kk + 2][r] = v.z; As[kk + 3][r] = v.w;
            int gc = colBase + r;
            float4 w = make_float4(0.f, 0.f, 0.f, 0.f);
            if (gc < Nc) w = *reinterpret_cast<const float4*>(Bm + (size_t)gc * K + k0 + kk);
            Bs[kk + 0][r] = w.x; Bs[kk + 1][r] = w.y; Bs[kk + 2][r] = w.z; Bs[kk + 3][r] = w.w;
        }
        __syncthreads();
        #pragma unroll
        for (int k = 0; k < BK; k++) {
            float a[TM], b[TN];
            #pragma unroll
            for (int i = 0; i < TM; i++) a[i] = As[k][ty * TM + i];
            #pragma unroll
            for (int j = 0; j < TN; j++) b[j] = Bs[k][tx * TN + j];
            #pragma unroll
            for (int i = 0; i < TM; i++)
                #pragma unroll
                for (int j = 0; j < TN; j++) acc[i][j] = fmaf(a[i], b[j], acc[i][j]);
        }
        __syncthreads();
    }
    #pragma unroll
    for (int i = 0; i < TM; i++) {
        int gr = rowBase + ty * TM + i;
        if (gr >= M) continue;
        #pragma unroll
        for (int j = 0; j < TN; j++) {
            int gc = colBase + tx * TN + j;
            if (gc >= Nc) continue;
            float v = acc[i][j];
            if (bias) v += bias[gc];
            if (act) v = fmaxf(v, 0.f);
            Cm[(size_t)gr * Nc + gc] = v;
        }
    }
}

// ---------------- segment softmax + weighted gather (csr order) ----------------
template <int H, int RELU, int OUTMODE>
__global__ void k_aggregate(const float* __restrict__ bias, void* __restrict__ out) {
    int n = blockIdx.x;
    int h = threadIdx.x >> 5, lane = threadIdx.x & 31;
    int s0 = g_off[n], s1 = g_off[n + 1];
    int cnt = s1 - s0;
    const int HCH = H * (CC / 2);
    const __half2* xl = reinterpret_cast<const __half2*>(g_xl);
    float2 acc[4];
    #pragma unroll
    for (int j = 0; j < 4; j++) acc[j] = make_float2(0.f, 0.f);

    if (cnt <= 64) {
        int cs0 = 0, cs1 = 0;
        float lv0 = -1e30f, lv1 = -1e30f;
        if (lane < cnt) {
            int p = s0 + lane;
            cs0 = g_psrc[p];
            float4 lg = *reinterpret_cast<const float4*>(&g_logits[(p * H + h) * 4]);
            lv0 = (lg.x + lg.y) + (lg.z + lg.w);
        }
        if (lane + 32 < cnt) {
            int p = s0 + lane + 32;
            cs1 = g_psrc[p];
            float4 lg = *reinterpret_cast<const float4*>(&g_logits[(p * H + h) * 4]);
            lv1 = (lg.x + lg.y) + (lg.z + lg.w);
        }
        float mx = warp_max(fmaxf(lv0, lv1));
        float ex0 = (lane < cnt)      ? __expf(lv0 - mx) : 0.f;
        float ex1 = (lane + 32 < cnt) ? __expf(lv1 - mx) : 0.f;
        float inv = 1.f / warp_sum(ex0 + ex1);
        for (int i = 0; i < cnt; i++) {
            int srcl = i & 31;
            float w = __shfl_sync(0xffffffffu, (i < 32) ? ex0 : ex1, srcl) * inv;
            int s = __shfl_sync(0xffffffffu, (i < 32) ? cs0 : cs1, srcl);
            const __half2* row = xl + (size_t)s * HCH + h * 128 + lane;
            #pragma unroll
            for (int j = 0; j < 4; j++) {
                float2 f = __half22float2(row[32 * j]);
                acc[j].x = fmaf(w, f.x, acc[j].x);
                acc[j].y = fmaf(w, f.y, acc[j].y);
            }
        }
    } else {
        float mx = -1e30f;
        for (int i = s0 + lane; i < s1; i += 32) {
            float4 lg = *reinterpret_cast<const float4*>(&g_logits[(i * H + h) * 4]);
            mx = fmaxf(mx, (lg.x + lg.y) + (lg.z + lg.w));
        }
        mx = warp_max(mx);
        float den = 0.f;
        for (int i = s0 + lane; i < s1; i += 32) {
            float4 lg = *reinterpret_cast<const float4*>(&g_logits[(i * H + h) * 4]);
            den += __expf((lg.x + lg.y) + (lg.z + lg.w) - mx);
        }
        den = warp_sum(den);
        float inv = 1.f / den;
        for (int i = s0; i < s1; i++) {
            float4 lg = *reinterpret_cast<const float4*>(&g_logits[(i * H + h) * 4]);
            float w = __expf((lg.x + lg.y) + (lg.z + lg.w) - mx) * inv;
            int s = g_psrc[i];
            const __half2* row = xl + (size_t)s * HCH + h * 128 + lane;
            #pragma unroll
            for (int j = 0; j < 4; j++) {
                float2 f = __half22float2(row[32 * j]);
                acc[j].x = fmaf(w, f.x, acc[j].x);
                acc[j].y = fmaf(w, f.y, acc[j].y);
            }
        }
    }

    int b = (OUTMODE == 2) ? g_batch[n] : 0;
    #pragma unroll
    for (int j = 0; j < 4; j++) {
        int col = h * CC + 2 * (lane + 32 * j);
        float2 bb = *reinterpret_cast<const float2*>(bias + col);
        float v0 = acc[j].x + bb.x, v1 = acc[j].y + bb.y;
        if (RELU) { v0 = fmaxf(v0, 0.f); v1 = fmaxf(v1, 0.f); }
        if (OUTMODE == 1) {
            __half* oh = (__half*)out;
            *reinterpret_cast<__half2*>(oh + (size_t)n * (H * CC) + col) = __floats2half2_rn(v0, v1);
        } else if (OUTMODE == 0) {
            float* of = (float*)out;
            *reinterpret_cast<float2*>(of + (size_t)n * (H * CC) + col) = make_float2(v0, v1);
        } else {
            atomicAdd(&g_pool[b * HC2 + col], v0);
            atomicAdd(&g_pool[b * HC2 + col + 1], v1);
        }
    }
}

// ---------------- pool divide + final ----------------
__global__ void k_pool_div() {
    int t = blockIdx.x * blockDim.x + threadIdx.x;
    if (t >= GG * HC2) return;
    int g = t >> 10;
    float cnt = (float)(g_gend[g] - g_gstart[g]);
    g_pool[t] /= fmaxf(cnt, 1.f);
}
__global__ void k_final(const float* __restrict__ W3, const float* __restrict__ b3,
                        float* __restrict__ out) {
    int g = blockIdx.x, lane = threadIdx.x;
    float acc = 0.f;
    #pragma unroll
    for (int j = 0; j < 8; j++) acc += g_m2[g * 256 + lane + 32 * j] * W3[lane + 32 * j];
    acc = warp_sum(acc);
    if (lane == 0) out[g] = 1.f / (1.f + expf(-(acc + b3[0])));
}

// ---------------- host launch ----------------
static inline void launch_sgemm(const float* A, const float* B, const float* bias,
                                float* C, int M, int Nc, int K, int act) {
    dim3 grid((Nc + 127) / 128, (M + 127) / 128);
    k_sgemm<<<grid, 256>>>(A, B, bias, C, M, Nc, K, act);
}

extern "C" void kernel_launch(void* const* d_in, const int* in_sizes, int n_in,
                              void* d_out, int out_size) {
    const float* x     = (const float*)d_in[0];
    const int*   ei    = (const int*)  d_in[1];
    const float* ea    = (const float*)d_in[2];
    const int*   batch = (const int*)  d_in[3];
    const float* Wl1 = (const float*)d_in[4],  *bl1 = (const float*)d_in[5];
    const float* Wr1 = (const float*)d_in[6],  *br1 = (const float*)d_in[7];
    const float* We1 = (const float*)d_in[8],  *att1 = (const float*)d_in[9];
    const float* bias1 = (const float*)d_in[10];
    const float* Wl2 = (const float*)d_in[11], *bl2 = (const float*)d_in[12];
    const float* Wr2 = (const float*)d_in[13], *br2 = (const float*)d_in[14];
    const float* We2 = (const float*)d_in[15], *att2 = (const float*)d_in[16];
    const float* bias2 = (const float*)d_in[17];
    const float* W1 = (const float*)d_in[18], *b1 = (const float*)d_in[19];
    const float* W2 = (const float*)d_in[20], *b2 = (const float*)d_in[21];
    const float* W3 = (const float*)d_in[22], *b3 = (const float*)d_in[23];
    float* out = (float*)d_out;

    static int s_init = 0;
    static cudaStream_t s1;
    static cudaEvent_t eFork, eJoin;
    if (!s_init) {
        cudaFuncSetAttribute(k_mma_dual, cudaFuncAttributeMaxDynamicSharedMemorySize, GEMM_SMEM_BYTES);
        cudaFuncSetAttribute(k_ee_logits<H1C>, cudaFuncAttributeMaxDynamicSharedMemorySize, EEL_SMEM_BYTES);
        cudaFuncSetAttribute(k_ee_logits<H2C>, cudaFuncAttributeMaxDynamicSharedMemorySize, EEL_SMEM_BYTES);
        cudaStreamCreateWithFlags(&s1, cudaStreamNonBlocking);
        cudaEventCreateWithFlags(&eFork, cudaEventDisableTiming);
        cudaEventCreateWithFlags(&eJoin, cudaEventDisableTiming);
        s_init = 1;
    }

    float *p_pool, *p_m1, *p_m2;
    __half *p_xl, *p_xr, *p_h1h, *p_ea2h, *p_w1h, *p_w2h, *p_we1h, *p_we2h, *p_xh;
    cudaGetSymbolAddress((void**)&p_xl,    g_xl);
    cudaGetSymbolAddress((void**)&p_xr,    g_xr);
    cudaGetSymbolAddress((void**)&p_h1h,   g_h1h);
    cudaGetSymbolAddress((void**)&p_ea2h,  g_ea2h);
    cudaGetSymbolAddress((void**)&p_w1h,   g_w1h);
    cudaGetSymbolAddress((void**)&p_w2h,   g_w2h);
    cudaGetSymbolAddress((void**)&p_we1h,  g_we1h);
    cudaGetSymbolAddress((void**)&p_we2h,  g_we2h);
    cudaGetSymbolAddress((void**)&p_xh,    g_xh);
    cudaGetSymbolAddress((void**)&p_pool,  g_pool);
    cudaGetSymbolAddress((void**)&p_m1,    g_m1);
    cudaGetSymbolAddress((void**)&p_m2,    g_m2);

    // --- fork: graph-prep chain on s1, GEMM path on default stream ---
    cudaEventRecord(eFork, 0);
    cudaStreamWaitEvent(s1, eFork, 0);

    // side stream: detect -> prep -> deg -> scan -> csr -> ea2
    k_detect<<<1, 1, 0, s1>>>(ei);
    k_prep<<<(EE + 255) / 256, 256, 0, s1>>>(ei, batch);
    k_deg<<<(EE + 255) / 256, 256, 0, s1>>>();
    k_scan<<<1, 256, 0, s1>>>();
    k_csr<<<(ET + 255) / 256, 256, 0, s1>>>();
    k_ea2<<<(ET * DEDGE + 255) / 256, 256, 0, s1>>>(ea);
    cudaEventRecord(eJoin, s1);

    // default stream: wconv -> layer-1 GEMM (independent of prep chain)
    k_wconv<<<(HC2 * HC1 + 255) / 256, 256>>>(Wl1, Wr1, Wl2, Wr2, We1, We2, x);
    k_mma_dual<<<dim3(2 * HC1 / 128, NN / 128), 256, GEMM_SMEM_BYTES>>>(
        p_xh, p_w1h, bl1, br1, p_xl, p_xr, NN, 2 * HC1, DNODE);

    // join: ee_logits needs csr/ea2 + xl/xr
    cudaStreamWaitEvent(0, eJoin, 0);

    // --- GATv2 layer 1 ---
    k_ee_logits<H1C><<<dim3(HC1 / 128, ET / 128), 256, EEL_SMEM_BYTES>>>(p_ea2h, p_we1h, att1);
    k_aggregate<H1C, 1, 1><<<NN, H1C * 32>>>(bias1, p_h1h);

    // --- GATv2 layer 2 (aggregate pools directly) ---
    k_mma_dual<<<dim3(2 * HC2 / 128, NN / 128), 256, GEMM_SMEM_BYTES>>>(
        p_h1h, p_w2h, bl2, br2, p_xl, p_xr, NN, 2 * HC2, HC1);
    k_ee_logits<H2C><<<dim3(HC2 / 128, ET / 128), 256, EEL_SMEM_BYTES>>>(p_ea2h, p_we2h, att2);
    k_aggregate<H2C, 0, 2><<<NN, H2C * 32>>>(bias2, nullptr);

    // --- pool + MLP ---
    k_pool_div<<<(GG * HC2 + 255) / 256, 256>>>();
    launch_sgemm(p_pool, W1, b1, p_m1, GG, 512, HC2, 1);
    launch_sgemm(p_m1,  W2, b2, p_m2, GG, 256, 512, 1);
    k_final<<<GG, 32>>>(W3, b3, out);
}